// round 1
// baseline (speedup 1.0000x reference)
#include <cuda_runtime.h>
#include <cstdint>

#define S_LEN 512
#define B_DIM 64
#define I_DIM 512
#define H_DIM 1024
#define EPS_C 1e-10f
#define NB    128   // persistent scan blocks
#define NCOL  16    // hidden columns per scan block

// ---------------- device scratch (static: no allocations allowed) ----------------
__device__ float g_mu_in[I_DIM * H_DIM];
__device__ float g_d_in [I_DIM * H_DIM];
__device__ float g_mu_h [H_DIM * H_DIM];
__device__ float g_d_h  [H_DIM * H_DIM];

// h double buffers, stored transposed: g_h[k][b] (k = hidden idx, b contiguous)
__device__ float g_hA [H_DIM * B_DIM];
__device__ float g_hA2[H_DIM * B_DIM];
__device__ float g_hB [H_DIM * B_DIM];
__device__ float g_hB2[H_DIM * B_DIM];

__device__ unsigned g_bar_arrive;
__device__ unsigned g_bar_gen;

// ---------------- prep: weight transforms + h0 = 0 + barrier reset ----------------
__global__ void prep_kernel(const float* __restrict__ m_in, const float* __restrict__ pi_in,
                            const float* __restrict__ chi_in,
                            const float* __restrict__ m_h, const float* __restrict__ pi_h,
                            const float* __restrict__ chi_h)
{
    int idx = blockIdx.x * blockDim.x + threadIdx.x;
    int stride = gridDim.x * blockDim.x;

    for (int i = idx; i < H_DIM * H_DIM; i += stride) {
        if (i < I_DIM * H_DIM) {
            float m = m_in[i], pi = pi_in[i], chi = chi_in[i];
            float mu = (1.0f - pi) * m;
            float rho = (1.0f - pi) * (chi + m * m);
            g_mu_in[i] = mu;
            g_d_in[i]  = rho - mu * mu;
        }
        float m = m_h[i], pi = pi_h[i], chi = chi_h[i];
        float mu = (1.0f - pi) * m;
        float rho = (1.0f - pi) * (chi + m * m);
        g_mu_h[i] = mu;
        g_d_h[i]  = rho - mu * mu;
    }
    for (int i = idx; i < H_DIM * B_DIM; i += stride) {
        g_hA[i]  = 0.0f;
        g_hA2[i] = 0.0f;
    }
    if (idx == 0) {
        g_bar_arrive = 0u;
        g_bar_gen    = 0u;
    }
}

// ---------------- phase B: xproj = x@mu_in + eps_in*sqrt((x*x)@d_in + EPS) --------
// M = S*B = 32768, K = 512, N = 1024. Tile 64x64x16, 256 thr, 4x4 micro, dual accum.
__global__ void __launch_bounds__(256) xproj_kernel(const float* __restrict__ x,
                                                    const float* __restrict__ eps_in,
                                                    float* __restrict__ out)
{
    __shared__ float xs[64 * 16];   // [m][k]
    __shared__ float wm[16 * 64];   // [k][n]
    __shared__ float wd[16 * 64];

    const int tid = threadIdx.x;
    const int tx = tid & 15;        // n-group
    const int ty = tid >> 4;        // m-group
    const int n_base = blockIdx.x * 64;
    const int m_base = blockIdx.y * 64;

    float accG[4][4], accD[4][4];
#pragma unroll
    for (int i = 0; i < 4; i++)
#pragma unroll
        for (int j = 0; j < 4; j++) { accG[i][j] = 0.0f; accD[i][j] = 0.0f; }

    const float* xg = x + (size_t)m_base * I_DIM;

    for (int k0 = 0; k0 < I_DIM; k0 += 16) {
#pragma unroll
        for (int i = 0; i < 4; i++) {
            int idx = tid + i * 256;
            int m = idx >> 4, k = idx & 15;
            xs[idx] = xg[m * I_DIM + k0 + k];
        }
#pragma unroll
        for (int i = 0; i < 4; i++) {
            int idx = tid + i * 256;
            int k = idx >> 6, n = idx & 63;
            wm[idx] = g_mu_in[(k0 + k) * H_DIM + n_base + n];
            wd[idx] = g_d_in [(k0 + k) * H_DIM + n_base + n];
        }
        __syncthreads();

#pragma unroll
        for (int k = 0; k < 16; k++) {
            float a[4], a2[4];
#pragma unroll
            for (int i = 0; i < 4; i++) {
                a[i]  = xs[(ty * 4 + i) * 16 + k];
                a2[i] = a[i] * a[i];
            }
            float4 m4 = *(const float4*)(wm + k * 64 + tx * 4);
            float4 d4 = *(const float4*)(wd + k * 64 + tx * 4);
            float mm[4] = {m4.x, m4.y, m4.z, m4.w};
            float dd[4] = {d4.x, d4.y, d4.z, d4.w};
#pragma unroll
            for (int i = 0; i < 4; i++)
#pragma unroll
                for (int j = 0; j < 4; j++) {
                    accG[i][j] += a[i]  * mm[j];
                    accD[i][j] += a2[i] * dd[j];
                }
        }
        __syncthreads();
    }

#pragma unroll
    for (int i = 0; i < 4; i++) {
        int m = m_base + ty * 4 + i;
#pragma unroll
        for (int j = 0; j < 4; j++) {
            int n = n_base + tx * 4 + j;
            int off = m * H_DIM + n;
            float e = eps_in[off];
            out[off] = accG[i][j] + e * sqrtf(accD[i][j] + EPS_C);
        }
    }
}

// ---------------- grid-wide barrier (persistent scan) ----------------
__device__ __forceinline__ void grid_barrier(unsigned target)
{
    __syncthreads();
    __threadfence();
    if (threadIdx.x == 0) {
        unsigned a = atomicAdd(&g_bar_arrive, 1u);
        if (a == NB - 1u) {
            g_bar_arrive = 0u;
            __threadfence();
            atomicExch(&g_bar_gen, target);
        } else {
            while (atomicAdd(&g_bar_gen, 0u) < target) { __nanosleep(64); }
        }
    }
    __syncthreads();
}

// ---------------- phase C: persistent recurrent scan ----------------
// 128 blocks: blockIdx -> (n_tile of 16 cols) x (b_tile of 32 rows).
// Weights for the block's 16 columns live in SMEM for all 512 steps.
// Each of 8 warps owns a K-slice of 128; lane = (bg 8) x (ng 4); 4b x 4n micro-tile.
__global__ void __launch_bounds__(256, 1) scan_kernel(const float* __restrict__ eps_h,
                                                      float* __restrict__ out,
                                                      int write_last)
{
    extern __shared__ float smem[];
    float* ws_mu = smem;                        // H_DIM * NCOL
    float* ws_d  = smem + H_DIM * NCOL;         // H_DIM * NCOL
    float* psum  = smem + 2 * H_DIM * NCOL;     // 8 warps * 1024 (512 G + 512 D)

    const int tid  = threadIdx.x;
    const int warp = tid >> 5;
    const int lane = tid & 31;
    const int b0 = (lane >> 2) * 4;             // 0..28
    const int n0 = (lane & 3) * 4;              // 0..12
    const int n_base = (blockIdx.x >> 1) * NCOL;
    const int b_base = (blockIdx.x & 1) * 32;

    // stage this block's weight slice into SMEM (reused for all 512 steps)
    for (int idx = tid; idx < H_DIM * NCOL; idx += 256) {
        int k = idx >> 4, j = idx & 15;
        ws_mu[idx] = g_mu_h[k * H_DIM + n_base + j];
        ws_d [idx] = g_d_h [k * H_DIM + n_base + j];
    }
    __syncthreads();

    const int kbeg = warp * 128;

    for (int t = 0; t < S_LEN; t++) {
        const float* hk  = (t & 1) ? g_hB  : g_hA;
        const float* hk2 = (t & 1) ? g_hB2 : g_hA2;
        float* hn  = (t & 1) ? g_hA  : g_hB;
        float* hn2 = (t & 1) ? g_hA2 : g_hB2;

        float accG[4][4], accD[4][4];
#pragma unroll
        for (int i = 0; i < 4; i++)
#pragma unroll
            for (int j = 0; j < 4; j++) { accG[i][j] = 0.0f; accD[i][j] = 0.0f; }

        const float* hp  = hk  + b_base + b0;
        const float* hp2 = hk2 + b_base + b0;

#pragma unroll 4
        for (int k = kbeg; k < kbeg + 128; k++) {
            float4 h4  = __ldcg((const float4*)(hp  + k * B_DIM));
            float4 h24 = __ldcg((const float4*)(hp2 + k * B_DIM));
            float4 m4 = *(const float4*)(ws_mu + k * NCOL + n0);
            float4 d4 = *(const float4*)(ws_d  + k * NCOL + n0);
            float ha[4]  = {h4.x,  h4.y,  h4.z,  h4.w};
            float h2a[4] = {h24.x, h24.y, h24.z, h24.w};
            float ma[4]  = {m4.x,  m4.y,  m4.z,  m4.w};
            float da[4]  = {d4.x,  d4.y,  d4.z,  d4.w};
#pragma unroll
            for (int i = 0; i < 4; i++)
#pragma unroll
                for (int j = 0; j < 4; j++) {
                    accG[i][j] += ha[i]  * ma[j];
                    accD[i][j] += h2a[i] * da[j];
                }
        }

        // per-warp partials -> SMEM
        float* myp = psum + warp * 1024;
#pragma unroll
        for (int i = 0; i < 4; i++)
#pragma unroll
            for (int j = 0; j < 4; j++) {
                int o = (b0 + i) * NCOL + n0 + j;
                myp[o]       = accG[i][j];
                myp[512 + o] = accD[i][j];
            }
        __syncthreads();

        // reduce across 8 warps + pointwise epilogue; 2 outputs per thread
#pragma unroll
        for (int r = 0; r < 2; r++) {
            int o = tid * 2 + r;                 // 0..511
            float G = 0.0f, D = 0.0f;
#pragma unroll
            for (int w = 0; w < 8; w++) {
                G += psum[w * 1024 + o];
                D += psum[w * 1024 + 512 + o];
            }
            int b = b_base + (o >> 4);           // global batch row
            int n = n_base + (o & 15);           // global hidden col
            int off = (t * B_DIM + b) * H_DIM + n;
            float e  = __ldg(eps_h + off);
            float xp = out[off];                 // xproj_t (written by phase B)
            float z  = G + e * sqrtf(D + EPS_C);
            float h  = tanhf(z + xp);
            out[off] = h;                        // outputs[t]
            hn [n * B_DIM + b] = h;
            hn2[n * B_DIM + b] = h * h;
            if (write_last && t == S_LEN - 1)
                out[S_LEN * B_DIM * H_DIM + b * H_DIM + n] = h;  // h_last
        }

        if (t < S_LEN - 1) grid_barrier((unsigned)(t + 1));
    }
}

// ---------------- launch ----------------
extern "C" void kernel_launch(void* const* d_in, const int* in_sizes, int n_in,
                              void* d_out, int out_size)
{
    (void)in_sizes; (void)n_in;
    const float* x      = (const float*)d_in[0];
    const float* eps_in = (const float*)d_in[1];
    const float* eps_h  = (const float*)d_in[2];
    const float* m_in   = (const float*)d_in[3];
    const float* pi_in  = (const float*)d_in[4];
    const float* chi_in = (const float*)d_in[5];
    const float* m_h    = (const float*)d_in[6];
    const float* pi_h   = (const float*)d_in[7];
    const float* chi_h  = (const float*)d_in[8];
    float* out = (float*)d_out;

    prep_kernel<<<512, 256>>>(m_in, pi_in, chi_in, m_h, pi_h, chi_h);

    dim3 gB(H_DIM / 64, (S_LEN * B_DIM) / 64);
    xproj_kernel<<<gB, 256>>>(x, eps_in, out);

    size_t smem = (size_t)(2 * H_DIM * NCOL + 8 * 1024) * sizeof(float);  // 160 KB
    cudaFuncSetAttribute(scan_kernel, cudaFuncAttributeMaxDynamicSharedMemorySize, (int)smem);
    int write_last = (out_size >= S_LEN * B_DIM * H_DIM + B_DIM * H_DIM) ? 1 : 0;
    scan_kernel<<<NB, 256, smem>>>(eps_h, out, write_last);
}

// round 2
// speedup vs baseline: 1.0784x; 1.0784x over previous
#include <cuda_runtime.h>
#include <cstdint>

#define S_LEN 512
#define B_DIM 64
#define I_DIM 512
#define H_DIM 1024
#define EPS_C 1e-10f
#define NB    128   // persistent scan blocks
#define NCOL  16    // hidden columns per scan block

typedef unsigned long long u64;

// ---------------- f32x2 packed-math helpers (sm_103a) ----------------
__device__ __forceinline__ u64 fma2(u64 a, u64 b, u64 c) {
    u64 d;
    asm("fma.rn.f32x2 %0, %1, %2, %3;" : "=l"(d) : "l"(a), "l"(b), "l"(c));
    return d;
}
__device__ __forceinline__ u64 pack2(float x) {
    u64 d;
    asm("mov.b64 %0, {%1, %1};" : "=l"(d) : "f"(x));
    return d;
}
__device__ __forceinline__ float2 unpk2(u64 v) {
    float2 r;
    asm("mov.b64 {%0, %1}, %2;" : "=f"(r.x), "=f"(r.y) : "l"(v));
    return r;
}

// ---------------- device scratch (static: no allocations allowed) ----------------
__device__ float g_mu_in[I_DIM * H_DIM];
__device__ float g_d_in [I_DIM * H_DIM];
__device__ float g_mu_h [H_DIM * H_DIM];
__device__ float g_d_h  [H_DIM * H_DIM];

// h double buffers, stored transposed: g_h[k][b]
__device__ float g_hA [H_DIM * B_DIM];
__device__ float g_hA2[H_DIM * B_DIM];
__device__ float g_hB [H_DIM * B_DIM];
__device__ float g_hB2[H_DIM * B_DIM];

__device__ unsigned g_bar_arrive;
__device__ volatile unsigned g_bar_gen;

// ---------------- prep: weight transforms + h0 = 0 + barrier reset ----------------
__global__ void prep_kernel(const float* __restrict__ m_in, const float* __restrict__ pi_in,
                            const float* __restrict__ chi_in,
                            const float* __restrict__ m_h, const float* __restrict__ pi_h,
                            const float* __restrict__ chi_h)
{
    int idx = blockIdx.x * blockDim.x + threadIdx.x;
    int stride = gridDim.x * blockDim.x;

    for (int i = idx; i < H_DIM * H_DIM; i += stride) {
        if (i < I_DIM * H_DIM) {
            float m = m_in[i], pi = pi_in[i], chi = chi_in[i];
            float mu = (1.0f - pi) * m;
            float rho = (1.0f - pi) * (chi + m * m);
            g_mu_in[i] = mu;
            g_d_in[i]  = rho - mu * mu;
        }
        float m = m_h[i], pi = pi_h[i], chi = chi_h[i];
        float mu = (1.0f - pi) * m;
        float rho = (1.0f - pi) * (chi + m * m);
        g_mu_h[i] = mu;
        g_d_h[i]  = rho - mu * mu;
    }
    for (int i = idx; i < H_DIM * B_DIM; i += stride) {
        g_hA[i]  = 0.0f;
        g_hA2[i] = 0.0f;
    }
    if (idx == 0) {
        g_bar_arrive = 0u;
        g_bar_gen    = 0u;
    }
}

// ---------------- phase B: xproj = x@mu_in + eps_in*sqrt((x*x)@d_in + EPS) --------
// M = S*B = 32768, K = 512, N = 1024. Tile 64x64x16, 256 thr, 4x4 micro, dual accum.
// f32x2: n-dim packed from weight float4s; a-operands broadcast LDS + pack.
__global__ void __launch_bounds__(256) xproj_kernel(const float* __restrict__ x,
                                                    const float* __restrict__ eps_in,
                                                    float* __restrict__ out)
{
    __shared__ float xs [64 * 16];   // [m][k]
    __shared__ float xs2[64 * 16];   // [m][k], squared
    __shared__ float wm [16 * 64];   // [k][n]
    __shared__ float wd [16 * 64];

    const int tid = threadIdx.x;
    const int tx = tid & 15;        // n-group
    const int ty = tid >> 4;        // m-group
    const int n_base = blockIdx.x * 64;
    const int m_base = blockIdx.y * 64;

    u64 accG[4][2], accD[4][2];     // [i(m)][jp(n-pair)]
    const u64 Z = pack2(0.0f);
#pragma unroll
    for (int i = 0; i < 4; i++) { accG[i][0]=Z; accG[i][1]=Z; accD[i][0]=Z; accD[i][1]=Z; }

    const float* xg = x + (size_t)m_base * I_DIM;

    for (int k0 = 0; k0 < I_DIM; k0 += 16) {
#pragma unroll
        for (int i = 0; i < 4; i++) {
            int idx = tid + i * 256;
            int m = idx >> 4, k = idx & 15;
            float v = xg[m * I_DIM + k0 + k];
            xs [idx] = v;
            xs2[idx] = v * v;
        }
#pragma unroll
        for (int i = 0; i < 4; i++) {
            int idx = tid + i * 256;
            int k = idx >> 6, n = idx & 63;
            wm[idx] = g_mu_in[(k0 + k) * H_DIM + n_base + n];
            wd[idx] = g_d_in [(k0 + k) * H_DIM + n_base + n];
        }
        __syncthreads();

#pragma unroll
        for (int k = 0; k < 16; k++) {
            u64 pa[4], pa2[4];
#pragma unroll
            for (int i = 0; i < 4; i++) {
                pa [i] = pack2(xs [(ty * 4 + i) * 16 + k]);
                pa2[i] = pack2(xs2[(ty * 4 + i) * 16 + k]);
            }
            // weight float4 = 2 natural n-pairs
            ulonglong2 mm = *(const ulonglong2*)(wm + k * 64 + tx * 4);
            ulonglong2 dd = *(const ulonglong2*)(wd + k * 64 + tx * 4);
#pragma unroll
            for (int i = 0; i < 4; i++) {
                accG[i][0] = fma2(pa [i], mm.x, accG[i][0]);
                accG[i][1] = fma2(pa [i], mm.y, accG[i][1]);
                accD[i][0] = fma2(pa2[i], dd.x, accD[i][0]);
                accD[i][1] = fma2(pa2[i], dd.y, accD[i][1]);
            }
        }
        __syncthreads();
    }

#pragma unroll
    for (int i = 0; i < 4; i++) {
        int m = m_base + ty * 4 + i;
#pragma unroll
        for (int jp = 0; jp < 2; jp++) {
            float2 G = unpk2(accG[i][jp]);
            float2 D = unpk2(accD[i][jp]);
            int n = n_base + tx * 4 + jp * 2;
            int off = m * H_DIM + n;
            float e0 = eps_in[off], e1 = eps_in[off + 1];
            out[off]     = G.x + e0 * sqrtf(D.x + EPS_C);
            out[off + 1] = G.y + e1 * sqrtf(D.y + EPS_C);
        }
    }
}

// ---------------- grid-wide barrier (volatile-load poll, no atomic spin) ----------
__device__ __forceinline__ void grid_barrier(unsigned target)
{
    __syncthreads();
    if (threadIdx.x == 0) {
        __threadfence();
        unsigned a = atomicAdd(&g_bar_arrive, 1u);
        if (a == NB - 1u) {
            g_bar_arrive = 0u;
            __threadfence();
            g_bar_gen = target;
        } else {
            while (g_bar_gen < target) { __nanosleep(16); }
            __threadfence();
        }
    }
    __syncthreads();
}

// ---------------- phase C: persistent recurrent scan ----------------
// 128 blocks: (n_tile of 16 cols) x (b_tile of 32 rows). Weights in SMEM all 512 steps.
// 8 warps each own a 128-K slice; lane micro-tile 4b x 4n; b packed as f32x2 pairs.
__global__ void __launch_bounds__(256, 1) scan_kernel(const float* __restrict__ eps_h,
                                                      float* __restrict__ out,
                                                      int write_last)
{
    extern __shared__ float smem[];
    float* ws_mu = smem;                        // H_DIM * NCOL
    float* ws_d  = smem + H_DIM * NCOL;         // H_DIM * NCOL
    float* psum  = smem + 2 * H_DIM * NCOL;     // 8 warps * 1024 (512 G + 512 D)

    const int tid  = threadIdx.x;
    const int warp = tid >> 5;
    const int lane = tid & 31;
    const int b0 = (lane >> 2) * 4;             // 0..28
    const int n0 = (lane & 3) * 4;              // 0..12
    const int n_base = (blockIdx.x >> 1) * NCOL;
    const int b_base = (blockIdx.x & 1) * 32;

    // stage this block's weight slice into SMEM (reused for all 512 steps)
    for (int idx = tid; idx < H_DIM * NCOL; idx += 256) {
        int k = idx >> 4, j = idx & 15;
        ws_mu[idx] = g_mu_h[k * H_DIM + n_base + j];
        ws_d [idx] = g_d_h [k * H_DIM + n_base + j];
    }
    __syncthreads();

    const int kbeg = warp * 128;

    for (int t = 0; t < S_LEN; t++) {
        const float* hk  = (t & 1) ? g_hB  : g_hA;
        const float* hk2 = (t & 1) ? g_hB2 : g_hA2;
        float* hn  = (t & 1) ? g_hA  : g_hB;
        float* hn2 = (t & 1) ? g_hA2 : g_hB2;

        // prefetch epilogue operands (independent of h) off the critical path
        float epre[2], xpre[2];
        int offv[2];
#pragma unroll
        for (int r = 0; r < 2; r++) {
            int o = tid * 2 + r;
            int b = b_base + (o >> 4);
            int n = n_base + (o & 15);
            int off = (t * B_DIM + b) * H_DIM + n;
            offv[r] = off;
            epre[r] = __ldg(eps_h + off);
            xpre[r] = __ldcg(out + off);
        }

        u64 accG[2][4], accD[2][4];             // [p(b-pair)][j(n)]
        const u64 Z = pack2(0.0f);
#pragma unroll
        for (int j = 0; j < 4; j++) { accG[0][j]=Z; accG[1][j]=Z; accD[0][j]=Z; accD[1][j]=Z; }

        const float* hp  = hk  + kbeg * B_DIM + b_base + b0;
        const float* hp2 = hk2 + kbeg * B_DIM + b_base + b0;
        const float* wmp = ws_mu + kbeg * NCOL + n0;
        const float* wdp = ws_d  + kbeg * NCOL + n0;

#pragma unroll 4
        for (int k = 0; k < 128; k++) {
            ulonglong2 ha  = __ldcg((const ulonglong2*)hp);   // (h[b0],h[b0+1]),(h[b0+2],h[b0+3])
            ulonglong2 h2a = __ldcg((const ulonglong2*)hp2);
            float4 m4 = *(const float4*)wmp;
            float4 d4 = *(const float4*)wdp;
            u64 mj[4] = {pack2(m4.x), pack2(m4.y), pack2(m4.z), pack2(m4.w)};
            u64 dj[4] = {pack2(d4.x), pack2(d4.y), pack2(d4.z), pack2(d4.w)};
#pragma unroll
            for (int j = 0; j < 4; j++) {
                accG[0][j] = fma2(ha.x,  mj[j], accG[0][j]);
                accG[1][j] = fma2(ha.y,  mj[j], accG[1][j]);
                accD[0][j] = fma2(h2a.x, dj[j], accD[0][j]);
                accD[1][j] = fma2(h2a.y, dj[j], accD[1][j]);
            }
            hp += B_DIM; hp2 += B_DIM; wmp += NCOL; wdp += NCOL;
        }

        // per-warp partials -> SMEM  (i = 2p + half within the f32x2)
        float* myp = psum + warp * 1024;
#pragma unroll
        for (int p = 0; p < 2; p++)
#pragma unroll
            for (int j = 0; j < 4; j++) {
                float2 G = unpk2(accG[p][j]);
                float2 D = unpk2(accD[p][j]);
                int o0 = (b0 + 2 * p)     * NCOL + n0 + j;
                int o1 = (b0 + 2 * p + 1) * NCOL + n0 + j;
                myp[o0]       = G.x;
                myp[o1]       = G.y;
                myp[512 + o0] = D.x;
                myp[512 + o1] = D.y;
            }
        __syncthreads();

        // reduce across 8 warps + pointwise epilogue; 2 outputs per thread
#pragma unroll
        for (int r = 0; r < 2; r++) {
            int o = tid * 2 + r;                 // 0..511
            float G = 0.0f, D = 0.0f;
#pragma unroll
            for (int w = 0; w < 8; w++) {
                G += psum[w * 1024 + o];
                D += psum[w * 1024 + 512 + o];
            }
            int b = b_base + (o >> 4);
            int n = n_base + (o & 15);
            int off = offv[r];
            float z  = G + epre[r] * sqrtf(D + EPS_C);
            float h  = tanhf(z + xpre[r]);
            out[off] = h;                        // outputs[t]
            hn [n * B_DIM + b] = h;
            hn2[n * B_DIM + b] = h * h;
            if (write_last && t == S_LEN - 1)
                out[S_LEN * B_DIM * H_DIM + b * H_DIM + n] = h;  // h_last
        }

        if (t < S_LEN - 1) grid_barrier((unsigned)(t + 1));
    }
}

// ---------------- launch ----------------
extern "C" void kernel_launch(void* const* d_in, const int* in_sizes, int n_in,
                              void* d_out, int out_size)
{
    (void)in_sizes; (void)n_in;
    const float* x      = (const float*)d_in[0];
    const float* eps_in = (const float*)d_in[1];
    const float* eps_h  = (const float*)d_in[2];
    const float* m_in   = (const float*)d_in[3];
    const float* pi_in  = (const float*)d_in[4];
    const float* chi_in = (const float*)d_in[5];
    const float* m_h    = (const float*)d_in[6];
    const float* pi_h   = (const float*)d_in[7];
    const float* chi_h  = (const float*)d_in[8];
    float* out = (float*)d_out;

    prep_kernel<<<512, 256>>>(m_in, pi_in, chi_in, m_h, pi_h, chi_h);

    dim3 gB(H_DIM / 64, (S_LEN * B_DIM) / 64);
    xproj_kernel<<<gB, 256>>>(x, eps_in, out);

    size_t smem = (size_t)(2 * H_DIM * NCOL + 8 * 1024) * sizeof(float);  // 160 KB
    cudaFuncSetAttribute(scan_kernel, cudaFuncAttributeMaxDynamicSharedMemorySize, (int)smem);
    int write_last = (out_size >= S_LEN * B_DIM * H_DIM + B_DIM * H_DIM) ? 1 : 0;
    scan_kernel<<<NB, 256, smem>>>(eps_h, out, write_last);
}

// round 3
// speedup vs baseline: 1.2420x; 1.1517x over previous
#include <cuda_runtime.h>
#include <cstdint>

#define S_LEN 512
#define B_DIM 64
#define I_DIM 512
#define H_DIM 1024
#define EPS_C 1e-10f
#define NB    128   // persistent scan blocks
#define NCOL  16    // hidden columns per scan block
#define PROW  18    // psum row stride (padded, bank-conflict-free-ish)
#define PWARP (32 * PROW * 2)   // floats per warp in psum (G block + D block)

typedef unsigned long long u64;

// ---------------- f32x2 packed-math helpers (sm_103a) ----------------
__device__ __forceinline__ u64 fma2(u64 a, u64 b, u64 c) {
    u64 d;
    asm("fma.rn.f32x2 %0, %1, %2, %3;" : "=l"(d) : "l"(a), "l"(b), "l"(c));
    return d;
}
__device__ __forceinline__ u64 pack2(float x) {
    u64 d;
    asm("mov.b64 %0, {%1, %1};" : "=l"(d) : "f"(x));
    return d;
}
__device__ __forceinline__ float2 unpk2(u64 v) {
    float2 r;
    asm("mov.b64 {%0, %1}, %2;" : "=f"(r.x), "=f"(r.y) : "l"(v));
    return r;
}

// ---------------- device scratch ----------------
__device__ float g_mu_in[I_DIM * H_DIM];
__device__ float g_d_in [I_DIM * H_DIM];
__device__ float g_mu_h [H_DIM * H_DIM];
__device__ float g_d_h  [H_DIM * H_DIM];

// h double buffers, stored transposed: g_h[k][b]
__device__ float g_hA [H_DIM * B_DIM];
__device__ float g_hA2[H_DIM * B_DIM];
__device__ float g_hB [H_DIM * B_DIM];
__device__ float g_hB2[H_DIM * B_DIM];

__device__ unsigned g_bar_arrive;
__device__ volatile unsigned g_bar_gen;

// ---------------- prep ----------------
__global__ void prep_kernel(const float* __restrict__ m_in, const float* __restrict__ pi_in,
                            const float* __restrict__ chi_in,
                            const float* __restrict__ m_h, const float* __restrict__ pi_h,
                            const float* __restrict__ chi_h)
{
    int idx = blockIdx.x * blockDim.x + threadIdx.x;
    int stride = gridDim.x * blockDim.x;

    for (int i = idx; i < H_DIM * H_DIM; i += stride) {
        if (i < I_DIM * H_DIM) {
            float m = m_in[i], pi = pi_in[i], chi = chi_in[i];
            float mu = (1.0f - pi) * m;
            float rho = (1.0f - pi) * (chi + m * m);
            g_mu_in[i] = mu;
            g_d_in[i]  = rho - mu * mu;
        }
        float m = m_h[i], pi = pi_h[i], chi = chi_h[i];
        float mu = (1.0f - pi) * m;
        float rho = (1.0f - pi) * (chi + m * m);
        g_mu_h[i] = mu;
        g_d_h[i]  = rho - mu * mu;
    }
    for (int i = idx; i < H_DIM * B_DIM; i += stride) {
        g_hA[i]  = 0.0f;
        g_hA2[i] = 0.0f;
    }
    if (idx == 0) {
        g_bar_arrive = 0u;
        g_bar_gen    = 0u;
    }
}

// ---------------- phase B: xproj ----------------
// M = 32768, K = 512, N = 1024. Tile 64x64x16, 256 thr, 4m x 4n micro, dual accum.
// x / x^2 pre-duplicated into u64 SMEM at staging (pack amortized over 16 consumers).
__global__ void __launch_bounds__(256) xproj_kernel(const float* __restrict__ x,
                                                    const float* __restrict__ eps_in,
                                                    float* __restrict__ out)
{
    __shared__ u64 xsp [64 * 16];   // [m][k] duplicated pair {v,v}
    __shared__ u64 xs2p[64 * 16];   // [m][k] duplicated pair {v*v,v*v}
    __shared__ float wm [16 * 64];  // [k][n]
    __shared__ float wd [16 * 64];

    const int tid = threadIdx.x;
    const int tx = tid & 15;        // n-group
    const int ty = tid >> 4;        // m-group
    const int n_base = blockIdx.x * 64;
    const int m_base = blockIdx.y * 64;

    u64 accG[4][2], accD[4][2];
    const u64 Z = pack2(0.0f);
#pragma unroll
    for (int i = 0; i < 4; i++) { accG[i][0]=Z; accG[i][1]=Z; accD[i][0]=Z; accD[i][1]=Z; }

    const float* xg = x + (size_t)m_base * I_DIM;

    for (int k0 = 0; k0 < I_DIM; k0 += 16) {
#pragma unroll
        for (int i = 0; i < 4; i++) {
            int idx = tid + i * 256;
            int m = idx >> 4, k = idx & 15;
            float v = xg[m * I_DIM + k0 + k];
            xsp [idx] = pack2(v);
            xs2p[idx] = pack2(v * v);
        }
#pragma unroll
        for (int i = 0; i < 4; i++) {
            int idx = tid + i * 256;
            int k = idx >> 6, n = idx & 63;
            wm[idx] = g_mu_in[(k0 + k) * H_DIM + n_base + n];
            wd[idx] = g_d_in [(k0 + k) * H_DIM + n_base + n];
        }
        __syncthreads();

#pragma unroll
        for (int k = 0; k < 16; k++) {
            u64 pa[4], pa2[4];
#pragma unroll
            for (int i = 0; i < 4; i++) {
                pa [i] = xsp [(ty * 4 + i) * 16 + k];
                pa2[i] = xs2p[(ty * 4 + i) * 16 + k];
            }
            ulonglong2 mm = *(const ulonglong2*)(wm + k * 64 + tx * 4);
            ulonglong2 dd = *(const ulonglong2*)(wd + k * 64 + tx * 4);
#pragma unroll
            for (int i = 0; i < 4; i++) {
                accG[i][0] = fma2(pa [i], mm.x, accG[i][0]);
                accG[i][1] = fma2(pa [i], mm.y, accG[i][1]);
                accD[i][0] = fma2(pa2[i], dd.x, accD[i][0]);
                accD[i][1] = fma2(pa2[i], dd.y, accD[i][1]);
            }
        }
        __syncthreads();
    }

#pragma unroll
    for (int i = 0; i < 4; i++) {
        int m = m_base + ty * 4 + i;
#pragma unroll
        for (int jp = 0; jp < 2; jp++) {
            float2 G = unpk2(accG[i][jp]);
            float2 D = unpk2(accD[i][jp]);
            int n = n_base + tx * 4 + jp * 2;
            int off = m * H_DIM + n;
            float2 e = *(const float2*)(eps_in + off);
            float2 o;
            o.x = G.x + e.x * sqrtf(D.x + EPS_C);
            o.y = G.y + e.y * sqrtf(D.y + EPS_C);
            *(float2*)(out + off) = o;
        }
    }
}

// ---------------- grid-wide barrier ----------------
__device__ __forceinline__ void grid_barrier(unsigned target)
{
    __syncthreads();
    if (threadIdx.x == 0) {
        __threadfence();
        unsigned a = atomicAdd(&g_bar_arrive, 1u);
        if (a == NB - 1u) {
            g_bar_arrive = 0u;
            __threadfence();
            g_bar_gen = target;
        } else {
            while (g_bar_gen < target) { __nanosleep(16); }
            __threadfence();
        }
    }
    __syncthreads();
}

// ---------------- phase C: persistent recurrent scan ----------------
// 128 blocks: (n_tile of 16 cols) x (b_tile of 32 rows).
// lane = b. 8 warps each own a 128-K slice. Weights pre-paired in SMEM:
// 16B unit per (k, n-pair) = {mu[n],mu[n+1],d[n],d[n+1]} -> broadcast LDS.128,
// zero per-iter packing. Inner loop: 1 LDG h + 1 LDG h2 + 8 LDS.128 + 2 packs + 16 fma2.
__global__ void __launch_bounds__(256, 1) scan_kernel(const float* __restrict__ eps_h,
                                                      float* __restrict__ out,
                                                      int write_last)
{
    extern __shared__ float smem[];
    // weights: H_DIM * 8 pairs * 16B = 128KB
    float4* wsf = (float4*)smem;
    const ulonglong2* wsu = (const ulonglong2*)smem;
    // psum: 8 warps * PWARP floats
    float* psum = smem + H_DIM * 8 * 4;

    const int tid  = threadIdx.x;
    const int warp = tid >> 5;
    const int lane = tid & 31;
    const int n_base = (blockIdx.x >> 1) * NCOL;
    const int b_base = (blockIdx.x & 1) * 32;

    // stage pre-paired weights: wsf[k*8 + p] = {mu[n],mu[n+1],d[n],d[n+1]}
    for (int idx = tid; idx < H_DIM * 8; idx += 256) {
        int k = idx >> 3, p = idx & 7;
        int n = n_base + 2 * p;
        float4 v;
        v.x = g_mu_h[k * H_DIM + n];
        v.y = g_mu_h[k * H_DIM + n + 1];
        v.z = g_d_h [k * H_DIM + n];
        v.w = g_d_h [k * H_DIM + n + 1];
        wsf[idx] = v;
    }
    __syncthreads();

    const int kbeg = warp * 128;
    // epilogue mapping: thread -> (b = tid>>3, n-pair n2 = (tid&7)*2)
    const int eb = tid >> 3;
    const int en = (tid & 7) * 2;
    const int gb = b_base + eb;
    const int gn = n_base + en;

    for (int t = 0; t < S_LEN; t++) {
        const float* hk  = (t & 1) ? g_hB  : g_hA;
        const float* hk2 = (t & 1) ? g_hB2 : g_hA2;
        float* hn  = (t & 1) ? g_hA  : g_hB;
        float* hn2 = (t & 1) ? g_hA2 : g_hB2;

        // prefetch epilogue operands (independent of h)
        const int off = (t * B_DIM + gb) * H_DIM + gn;
        const float2 epre = *(const float2*)(eps_h + off);
        const float2 xpre = __ldcg((const float2*)(out + off));

        u64 accG[8], accD[8];
        const u64 Z = pack2(0.0f);
#pragma unroll
        for (int p = 0; p < 8; p++) { accG[p] = Z; accD[p] = Z; }

        const float* hp  = hk  + kbeg * B_DIM + b_base + lane;
        const float* hp2 = hk2 + kbeg * B_DIM + b_base + lane;
        const ulonglong2* wp = wsu + kbeg * 8;

#pragma unroll 8
        for (int k = 0; k < 128; k++) {
            float hv  = __ldcg(hp);
            float h2v = __ldcg(hp2);
            u64 ph  = pack2(hv);
            u64 ph2 = pack2(h2v);
#pragma unroll
            for (int p = 0; p < 8; p++) {
                ulonglong2 w = wp[p];
                accG[p] = fma2(ph,  w.x, accG[p]);
                accD[p] = fma2(ph2, w.y, accD[p]);
            }
            hp += B_DIM; hp2 += B_DIM; wp += 8;
        }

        // per-warp partials: psum[warp][b=lane][n], padded rows
        float* myp = psum + warp * PWARP;
#pragma unroll
        for (int p = 0; p < 8; p++) {
            *(float2*)&myp[lane * PROW + 2 * p]                 = unpk2(accG[p]);
            *(float2*)&myp[32 * PROW + lane * PROW + 2 * p]     = unpk2(accD[p]);
        }
        __syncthreads();

        // reduce across 8 warps + epilogue; 2 adjacent-n outputs per thread
        float2 G = make_float2(0.0f, 0.0f);
        float2 D = make_float2(0.0f, 0.0f);
#pragma unroll
        for (int w = 0; w < 8; w++) {
            float2 g = *(const float2*)&psum[w * PWARP + eb * PROW + en];
            float2 d = *(const float2*)&psum[w * PWARP + 32 * PROW + eb * PROW + en];
            G.x += g.x; G.y += g.y; D.x += d.x; D.y += d.y;
        }
        float h0 = tanhf(G.x + epre.x * sqrtf(D.x + EPS_C) + xpre.x);
        float h1 = tanhf(G.y + epre.y * sqrtf(D.y + EPS_C) + xpre.y);
        float2 ho = make_float2(h0, h1);
        *(float2*)(out + off) = ho;             // outputs[t]
        hn [gn * B_DIM + gb]       = h0;
        hn [(gn + 1) * B_DIM + gb] = h1;
        hn2[gn * B_DIM + gb]       = h0 * h0;
        hn2[(gn + 1) * B_DIM + gb] = h1 * h1;
        if (write_last && t == S_LEN - 1) {
            out[S_LEN * B_DIM * H_DIM + gb * H_DIM + gn]     = h0;
            out[S_LEN * B_DIM * H_DIM + gb * H_DIM + gn + 1] = h1;
        }

        if (t < S_LEN - 1) grid_barrier((unsigned)(t + 1));
    }
}

// ---------------- launch ----------------
extern "C" void kernel_launch(void* const* d_in, const int* in_sizes, int n_in,
                              void* d_out, int out_size)
{
    (void)in_sizes; (void)n_in;
    const float* x      = (const float*)d_in[0];
    const float* eps_in = (const float*)d_in[1];
    const float* eps_h  = (const float*)d_in[2];
    const float* m_in   = (const float*)d_in[3];
    const float* pi_in  = (const float*)d_in[4];
    const float* chi_in = (const float*)d_in[5];
    const float* m_h    = (const float*)d_in[6];
    const float* pi_h   = (const float*)d_in[7];
    const float* chi_h  = (const float*)d_in[8];
    float* out = (float*)d_out;

    prep_kernel<<<512, 256>>>(m_in, pi_in, chi_in, m_h, pi_h, chi_h);

    dim3 gB(H_DIM / 64, (S_LEN * B_DIM) / 64);
    xproj_kernel<<<gB, 256>>>(x, eps_in, out);

    size_t smem = (size_t)(H_DIM * 8 * 16) + (size_t)(8 * PWARP * 4);  // 128KB + 36KB
    cudaFuncSetAttribute(scan_kernel, cudaFuncAttributeMaxDynamicSharedMemorySize, (int)smem);
    int write_last = (out_size >= S_LEN * B_DIM * H_DIM + B_DIM * H_DIM) ? 1 : 0;
    scan_kernel<<<NB, 256, smem>>>(eps_h, out, write_last);
}

// round 5
// speedup vs baseline: 2.5052x; 2.0171x over previous
#include <cuda_runtime.h>
#include <cstdint>

#define S_LEN 512
#define B_DIM 64
#define I_DIM 512
#define H_DIM 1024
#define EPS_C 1e-10f
#define NB    128

typedef unsigned long long u64;

// ---------------- tf32 helpers ----------------
__device__ __forceinline__ uint32_t rna(float f) {
    uint32_t r; asm("cvt.rna.tf32.f32 %0, %1;" : "=r"(r) : "f"(f)); return r;
}
__device__ __forceinline__ float rnaf(float f) { return __uint_as_float(rna(f)); }

__device__ __forceinline__ void mma8(float* c, uint32_t a0, uint32_t a1, uint32_t a2, uint32_t a3,
                                     uint32_t b0, uint32_t b1) {
    asm volatile("mma.sync.aligned.m16n8k8.row.col.f32.tf32.tf32.f32 "
        "{%0,%1,%2,%3}, {%4,%5,%6,%7}, {%8,%9}, {%0,%1,%2,%3};"
        : "+f"(c[0]), "+f"(c[1]), "+f"(c[2]), "+f"(c[3])
        : "r"(a0), "r"(a1), "r"(a2), "r"(a3), "r"(b0), "r"(b1));
}

// permute within each 8-group: original j -> (j&3)*2 + (j>>2), so a k8-chunk's
// (tig, tig+4) elements sit adjacent -> one 8B load yields (a0,a2) / (a1,a3).
__device__ __forceinline__ int kperm(int j) { return ((j & 3) << 1) | (j >> 2); }

// ---------------- device scratch ----------------
__device__ float g_mu_in[I_DIM * H_DIM];   // tf32-rounded, [k][n]
__device__ float g_d_in [I_DIM * H_DIM];
__device__ float g_mu_h [H_DIM * H_DIM];   // tf32-rounded, [k][n]
__device__ float g_d_h  [H_DIM * H_DIM];
__device__ __align__(16) float g_xb[S_LEN * B_DIM * I_DIM];  // tf32(x), k-permuted
__device__ __align__(16) float g_xq[S_LEN * B_DIM * I_DIM];  // tf32(x*x), k-permuted
__device__ float g_hA[B_DIM * H_DIM];      // tf32(h) transport, [b][k permuted]
__device__ float g_hB[B_DIM * H_DIM];
__device__ unsigned g_bar_arrive;
__device__ volatile unsigned g_bar_gen;

// ---------------- prep: weight transforms + h0 + barrier reset ----------------
__global__ void prep_kernel(const float* __restrict__ m_in, const float* __restrict__ pi_in,
                            const float* __restrict__ chi_in,
                            const float* __restrict__ m_h, const float* __restrict__ pi_h,
                            const float* __restrict__ chi_h)
{
    int idx = blockIdx.x * blockDim.x + threadIdx.x;
    int stride = gridDim.x * blockDim.x;

    for (int i = idx; i < H_DIM * H_DIM; i += stride) {
        if (i < I_DIM * H_DIM) {
            float m = m_in[i], pi = pi_in[i], chi = chi_in[i];
            float mu = (1.0f - pi) * m;
            float rho = (1.0f - pi) * (chi + m * m);
            g_mu_in[i] = rnaf(mu);
            g_d_in[i]  = rnaf(rho - mu * mu);
        }
        float m = m_h[i], pi = pi_h[i], chi = chi_h[i];
        float mu = (1.0f - pi) * m;
        float rho = (1.0f - pi) * (chi + m * m);
        g_mu_h[i] = rnaf(mu);
        g_d_h[i]  = rnaf(rho - mu * mu);
    }
    for (int i = idx; i < B_DIM * H_DIM; i += stride)
        g_hA[i] = 0.0f;
    if (idx == 0) { g_bar_arrive = 0u; g_bar_gen = 0u; }
}

// ---------------- prep_x: tf32-round x and x^2, k-permuted layout ----------------
__global__ void prep_x_kernel(const float* __restrict__ x)
{
    int idx = blockIdx.x * blockDim.x + threadIdx.x;
    int stride = gridDim.x * blockDim.x;
    const int N = S_LEN * B_DIM * I_DIM;
    for (int i = idx; i < N; i += stride) {
        int k = i & (I_DIM - 1);
        int m = i >> 9;
        float v = x[i];
        int p = (k & ~7) | kperm(k & 7);
        int o = (m << 9) | p;
        g_xb[o] = rnaf(v);
        g_xq[o] = rnaf(v * v);
    }
}

// ---------------- phase B: xproj via tf32 mma.sync ----------------
// Block = 128m x 64n, 256 thr. Warp tile 32m x 32n (2 m-tiles x 4 n-tiles).
// K staged in chunks of 64 through smem. Weights in pair-interleaved
// XOR-swizzled smem; x/x^2 in row-XOR-swizzled smem (all LDS.64, conflict-free).
#define XP_SMEM (96 * 1024)

__global__ void __launch_bounds__(256, 2) xproj_kernel(const float* __restrict__ eps_in,
                                                       float* __restrict__ out)
{
    extern __shared__ float sm[];
    float* xs  = sm;            // [128][64], row-swizzled
    float* xq  = sm + 8192;
    float* wmu = sm + 16384;    // [8 chunk][4 tig][64 n][2 pair], n XOR-swizzled
    float* wd  = sm + 20480;

    const int tid  = threadIdx.x;
    const int warp = tid >> 5, lane = tid & 31;
    const int gid = lane >> 2, tig = lane & 3;
    const int n_base = blockIdx.x * 64;
    const int m_base = blockIdx.y * 128;
    const int mg = (warp & 3) * 32;
    const int nh = (warp >> 2) * 32;

    float cG[2][4][4] = {}, cD[2][4][4] = {};

    for (int ks = 0; ks < 8; ks++) {
        const int k0s = ks * 64;
        // stage x / x^2 (already permuted+rounded in global); float4 with row swizzle
        for (int i = tid; i < 2048; i += 256) {
            int r = i >> 4, c4 = i & 15;
            int d4 = c4 ^ ((r & 3) << 1);
            *(float4*)&xs[r * 64 + d4 * 4] =
                *(const float4*)&g_xb[(size_t)(m_base + r) * I_DIM + k0s + c4 * 4];
            *(float4*)&xq[r * 64 + d4 * 4] =
                *(const float4*)&g_xq[(size_t)(m_base + r) * I_DIM + k0s + c4 * 4];
        }
        // stage weights pair-interleaved + XOR swizzle
        for (int i = tid; i < 4096; i += 256) {
            int k = i >> 6, n = i & 63;
            int ck = k >> 3, j = k & 7, tk = j & 3, pr = j >> 2;
            int pos = ((ck * 4 + tk) * 64 + (n ^ (tk << 2))) * 2 + pr;
            wmu[pos] = g_mu_in[(size_t)(k0s + k) * H_DIM + n_base + n];
            wd [pos] = g_d_in [(size_t)(k0s + k) * H_DIM + n_base + n];
        }
        __syncthreads();

#pragma unroll
        for (int c = 0; c < 8; c++) {
            uint32_t ax[2][4], aq[2][4];
#pragma unroll
            for (int t = 0; t < 2; t++) {
                int r0 = mg + t * 16 + gid;
                int r1 = r0 + 8;
                float2 f0 = *(float2*)&xs[r0 * 64 + ((c * 4 + tig) ^ ((r0 & 3) << 2)) * 2];
                float2 f1 = *(float2*)&xs[r1 * 64 + ((c * 4 + tig) ^ ((r1 & 3) << 2)) * 2];
                ax[t][0] = __float_as_uint(f0.x); ax[t][2] = __float_as_uint(f0.y);
                ax[t][1] = __float_as_uint(f1.x); ax[t][3] = __float_as_uint(f1.y);
                float2 q0 = *(float2*)&xq[r0 * 64 + ((c * 4 + tig) ^ ((r0 & 3) << 2)) * 2];
                float2 q1 = *(float2*)&xq[r1 * 64 + ((c * 4 + tig) ^ ((r1 & 3) << 2)) * 2];
                aq[t][0] = __float_as_uint(q0.x); aq[t][2] = __float_as_uint(q0.y);
                aq[t][1] = __float_as_uint(q1.x); aq[t][3] = __float_as_uint(q1.y);
            }
#pragma unroll
            for (int nt = 0; nt < 4; nt++) {
                int nl = nh + nt * 8 + gid;
                float2 bm = *(float2*)&wmu[((c * 4 + tig) * 64 + (nl ^ (tig << 2))) * 2];
                float2 bdv = *(float2*)&wd [((c * 4 + tig) * 64 + (nl ^ (tig << 2))) * 2];
                uint32_t bm0 = __float_as_uint(bm.x),  bm1 = __float_as_uint(bm.y);
                uint32_t bd0 = __float_as_uint(bdv.x), bd1 = __float_as_uint(bdv.y);
#pragma unroll
                for (int t = 0; t < 2; t++) {
                    mma8(cG[t][nt], ax[t][0], ax[t][1], ax[t][2], ax[t][3], bm0, bm1);
                    mma8(cD[t][nt], aq[t][0], aq[t][1], aq[t][2], aq[t][3], bd0, bd1);
                }
            }
        }
        __syncthreads();
    }

    // epilogue: out = G + eps * sqrt(D2 + EPS)
#pragma unroll
    for (int t = 0; t < 2; t++)
#pragma unroll
    for (int nt = 0; nt < 4; nt++) {
        int n = n_base + nh + nt * 8 + tig * 2;
#pragma unroll
        for (int half = 0; half < 2; half++) {
            int m = m_base + mg + t * 16 + gid + half * 8;
            size_t off = (size_t)m * H_DIM + n;
            float2 e = *(const float2*)(eps_in + off);
            float2 o;
            o.x = cG[t][nt][half * 2]     + e.x * sqrtf(cD[t][nt][half * 2]     + EPS_C);
            o.y = cG[t][nt][half * 2 + 1] + e.y * sqrtf(cD[t][nt][half * 2 + 1] + EPS_C);
            *(float2*)(out + off) = o;
        }
    }
}

// ---------------- grid-wide barrier ----------------
__device__ __forceinline__ void grid_barrier(unsigned target)
{
    __syncthreads();
    if (threadIdx.x == 0) {
        __threadfence();
        unsigned a = atomicAdd(&g_bar_arrive, 1u);
        if (a == NB - 1u) {
            g_bar_arrive = 0u;
            __threadfence();
            g_bar_gen = target;
        } else {
            while (g_bar_gen < target) { __nanosleep(16); }
            __threadfence();
        }
    }
    __syncthreads();
}

// ---------------- phase C: persistent scan via tf32 mma.sync ----------------
// 128 blocks = 64 n-groups (16 cols) x 2 batch-halves (32 rows). Weights for the
// block's 16 cols resident in smem all 512 steps (pair-interleaved, XOR-swizzled).
// 8 warps = 2 m-tiles x 4 k-quarters; per chunk: 2x LDG.64 h (k-permuted transport),
// squares in-register, 4x LDS.64 B-frags, 4 HMMA. Partials reduced through smem.
#define SC_SMEM (147456)

__global__ void __launch_bounds__(256, 1) scan_kernel(const float* __restrict__ eps_h,
                                                      float* __restrict__ out,
                                                      int write_last)
{
    extern __shared__ float sm[];
    float* wmu = sm;            // [128 chunk][4 tig][16 n][2 pair] = 16384 floats
    float* wd  = sm + 16384;
    float* pG  = sm + 32768;    // [4 kq][32 b][16 n]
    float* pD  = sm + 34816;

    const int tid  = threadIdx.x;
    const int warp = tid >> 5, lane = tid & 31;
    const int gid = lane >> 2, tig = lane & 3;
    const int n_base = (blockIdx.x >> 1) * 16;
    const int b_base = (blockIdx.x & 1) * 32;
    const int mt = warp & 1, kq = warp >> 1;

    // stage the block's weight slice once
    for (int i = tid; i < H_DIM * 16; i += 256) {
        int k = i >> 4, n = i & 15;
        int ck = k >> 3, j = k & 7, tk = j & 3, pr = j >> 2;
        int pos = ((ck * 4 + tk) * 16 + (n ^ (tk << 2))) * 2 + pr;
        wmu[pos] = g_mu_h[(size_t)k * H_DIM + n_base + n];
        wd [pos] = g_d_h [(size_t)k * H_DIM + n_base + n];
    }
    __syncthreads();

    const int r0 = b_base + mt * 16 + gid;
    const int bloc = tid >> 3;
    const int nloc = (tid & 7) * 2;
    const int gbrow = b_base + bloc;
    const int ncol = n_base + nloc;
    const int p0 = (ncol & ~7) | kperm(ncol & 7);
    const int p1 = (ncol & ~7) | kperm((ncol & 7) + 1);

    for (int t = 0; t < S_LEN; t++) {
        const float* hsrc = (t & 1) ? g_hB : g_hA;
        float* hdst = (t & 1) ? g_hA : g_hB;

        const size_t toff = (size_t)(t * B_DIM + gbrow) * H_DIM + ncol;
        const float2 epre = *(const float2*)(eps_h + toff);
        const float2 xpre = __ldcg((const float2*)(out + toff));

        float cG[2][4] = {}, cD[2][4] = {};
        const float* hr0 = hsrc + (size_t)r0 * H_DIM + 2 * tig;
        const float* hr1 = hsrc + (size_t)(r0 + 8) * H_DIM + 2 * tig;
        const int cg0 = kq * 32;

#pragma unroll 4
        for (int c = 0; c < 32; c++) {
            const int cg = cg0 + c;
            const int k0 = cg * 8;
            float2 f0 = __ldcg((const float2*)(hr0 + k0));
            float2 f1 = __ldcg((const float2*)(hr1 + k0));
            uint32_t a0 = __float_as_uint(f0.x), a2 = __float_as_uint(f0.y);
            uint32_t a1 = __float_as_uint(f1.x), a3 = __float_as_uint(f1.y);
            uint32_t q0 = rna(f0.x * f0.x), q2 = rna(f0.y * f0.y);
            uint32_t q1 = rna(f1.x * f1.x), q3 = rna(f1.y * f1.y);
#pragma unroll
            for (int nt = 0; nt < 2; nt++) {
                int nl = nt * 8 + gid;
                float2 bm = *(float2*)&wmu[((cg * 4 + tig) * 16 + (nl ^ (tig << 2))) * 2];
                float2 bdv = *(float2*)&wd [((cg * 4 + tig) * 16 + (nl ^ (tig << 2))) * 2];
                mma8(cG[nt], a0, a1, a2, a3, __float_as_uint(bm.x),  __float_as_uint(bm.y));
                mma8(cD[nt], q0, q1, q2, q3, __float_as_uint(bdv.x), __float_as_uint(bdv.y));
            }
        }

        // partials -> smem
#pragma unroll
        for (int nt = 0; nt < 2; nt++) {
            int colb = nt * 8 + tig * 2;
            int rowa = kq * 32 + mt * 16 + gid;
            *(float2*)&pG[rowa * 16 + colb]       = make_float2(cG[nt][0], cG[nt][1]);
            *(float2*)&pG[(rowa + 8) * 16 + colb] = make_float2(cG[nt][2], cG[nt][3]);
            *(float2*)&pD[rowa * 16 + colb]       = make_float2(cD[nt][0], cD[nt][1]);
            *(float2*)&pD[(rowa + 8) * 16 + colb] = make_float2(cD[nt][2], cD[nt][3]);
        }
        __syncthreads();

        // reduce 4 k-quarters + epilogue (2 adjacent-n outputs per thread)
        float2 G = make_float2(0.0f, 0.0f), D = make_float2(0.0f, 0.0f);
#pragma unroll
        for (int q = 0; q < 4; q++) {
            float2 g = *(float2*)&pG[(q * 32 + bloc) * 16 + nloc];
            float2 d = *(float2*)&pD[(q * 32 + bloc) * 16 + nloc];
            G.x += g.x; G.y += g.y; D.x += d.x; D.y += d.y;
        }
        float h0 = tanhf(G.x + epre.x * sqrtf(D.x + EPS_C) + xpre.x);
        float h1 = tanhf(G.y + epre.y * sqrtf(D.y + EPS_C) + xpre.y);
        hdst[gbrow * H_DIM + p0] = rnaf(h0);   // critical path: h transport first
        hdst[gbrow * H_DIM + p1] = rnaf(h1);
        *(float2*)(out + toff) = make_float2(h0, h1);
        if (write_last && t == S_LEN - 1) {
            out[(size_t)S_LEN * B_DIM * H_DIM + gbrow * H_DIM + ncol]     = h0;
            out[(size_t)S_LEN * B_DIM * H_DIM + gbrow * H_DIM + ncol + 1] = h1;
        }

        if (t < S_LEN - 1) grid_barrier((unsigned)(t + 1));
    }
}

// ---------------- launch ----------------
extern "C" void kernel_launch(void* const* d_in, const int* in_sizes, int n_in,
                              void* d_out, int out_size)
{
    (void)in_sizes; (void)n_in;
    const float* x      = (const float*)d_in[0];
    const float* eps_in = (const float*)d_in[1];
    const float* eps_h  = (const float*)d_in[2];
    const float* m_in   = (const float*)d_in[3];
    const float* pi_in  = (const float*)d_in[4];
    const float* chi_in = (const float*)d_in[5];
    const float* m_h    = (const float*)d_in[6];
    const float* pi_h   = (const float*)d_in[7];
    const float* chi_h  = (const float*)d_in[8];
    float* out = (float*)d_out;

    prep_kernel<<<512, 256>>>(m_in, pi_in, chi_in, m_h, pi_h, chi_h);
    prep_x_kernel<<<8192, 256>>>(x);

    cudaFuncSetAttribute(xproj_kernel, cudaFuncAttributeMaxDynamicSharedMemorySize, XP_SMEM);
    dim3 gB(H_DIM / 64, (S_LEN * B_DIM) / 128);   // n fast -> x-tile L2 reuse
    xproj_kernel<<<gB, 256, XP_SMEM>>>(eps_in, out);

    cudaFuncSetAttribute(scan_kernel, cudaFuncAttributeMaxDynamicSharedMemorySize, SC_SMEM);
    int write_last = (out_size >= S_LEN * B_DIM * H_DIM + B_DIM * H_DIM) ? 1 : 0;
    scan_kernel<<<NB, 256, SC_SMEM>>>(eps_h, out, write_last);
}

// round 6
// speedup vs baseline: 2.9720x; 1.1863x over previous
#include <cuda_runtime.h>
#include <cstdint>

#define S_LEN 512
#define B_DIM 64
#define I_DIM 512
#define H_DIM 1024
#define EPS_C 1e-10f
#define NB    128

typedef unsigned long long u64;

// ---------------- tf32 helpers ----------------
__device__ __forceinline__ uint32_t rna(float f) {
    uint32_t r; asm("cvt.rna.tf32.f32 %0, %1;" : "=r"(r) : "f"(f)); return r;
}
__device__ __forceinline__ float rnaf(float f) { return __uint_as_float(rna(f)); }

__device__ __forceinline__ void mma8(float* c, uint32_t a0, uint32_t a1, uint32_t a2, uint32_t a3,
                                     uint32_t b0, uint32_t b1) {
    asm volatile("mma.sync.aligned.m16n8k8.row.col.f32.tf32.tf32.f32 "
        "{%0,%1,%2,%3}, {%4,%5,%6,%7}, {%8,%9}, {%0,%1,%2,%3};"
        : "+f"(c[0]), "+f"(c[1]), "+f"(c[2]), "+f"(c[3])
        : "r"(a0), "r"(a1), "r"(a2), "r"(a3), "r"(b0), "r"(b1));
}

// permute within each 8-group: original j -> (j&3)*2 + (j>>2)
__device__ __forceinline__ int kperm(int j) { return ((j & 3) << 1) | (j >> 2); }

// ---------------- scoped atomics for the grid barrier ----------------
__device__ __forceinline__ unsigned atom_add_release(unsigned* p, unsigned v) {
    unsigned old;
    asm volatile("atom.add.release.gpu.u32 %0, [%1], %2;" : "=r"(old) : "l"(p), "r"(v) : "memory");
    return old;
}
__device__ __forceinline__ unsigned ld_acquire(const unsigned* p) {
    unsigned v;
    asm volatile("ld.acquire.gpu.u32 %0, [%1];" : "=r"(v) : "l"(p) : "memory");
    return v;
}
__device__ __forceinline__ void st_release(unsigned* p, unsigned v) {
    asm volatile("st.release.gpu.u32 [%0], %1;" :: "l"(p), "r"(v) : "memory");
}

// ---------------- device scratch ----------------
__device__ float g_mu_in[I_DIM * H_DIM];   // tf32-rounded, [k][n]
__device__ float g_d_in [I_DIM * H_DIM];
__device__ float g_mu_h [H_DIM * H_DIM];   // tf32-rounded, [k][n]
__device__ float g_d_h  [H_DIM * H_DIM];
__device__ __align__(16) float g_xb[S_LEN * B_DIM * I_DIM];  // tf32(x), k-permuted
__device__ __align__(16) float g_xq[S_LEN * B_DIM * I_DIM];  // tf32(x*x), k-permuted
__device__ float g_hA[B_DIM * H_DIM];      // tf32(h) transport, [b][k permuted]
__device__ float g_hB[B_DIM * H_DIM];
__device__ unsigned g_bar_arrive;
__device__ unsigned g_bar_gen;

// ---------------- prep ----------------
__global__ void prep_kernel(const float* __restrict__ m_in, const float* __restrict__ pi_in,
                            const float* __restrict__ chi_in,
                            const float* __restrict__ m_h, const float* __restrict__ pi_h,
                            const float* __restrict__ chi_h)
{
    int idx = blockIdx.x * blockDim.x + threadIdx.x;
    int stride = gridDim.x * blockDim.x;

    for (int i = idx; i < H_DIM * H_DIM; i += stride) {
        if (i < I_DIM * H_DIM) {
            float m = m_in[i], pi = pi_in[i], chi = chi_in[i];
            float mu = (1.0f - pi) * m;
            float rho = (1.0f - pi) * (chi + m * m);
            g_mu_in[i] = rnaf(mu);
            g_d_in[i]  = rnaf(rho - mu * mu);
        }
        float m = m_h[i], pi = pi_h[i], chi = chi_h[i];
        float mu = (1.0f - pi) * m;
        float rho = (1.0f - pi) * (chi + m * m);
        g_mu_h[i] = rnaf(mu);
        g_d_h[i]  = rnaf(rho - mu * mu);
    }
    for (int i = idx; i < B_DIM * H_DIM; i += stride)
        g_hA[i] = 0.0f;
    if (idx == 0) { g_bar_arrive = 0u; g_bar_gen = 0u; }
}

// ---------------- prep_x ----------------
__global__ void prep_x_kernel(const float* __restrict__ x)
{
    int idx = blockIdx.x * blockDim.x + threadIdx.x;
    int stride = gridDim.x * blockDim.x;
    const int N = S_LEN * B_DIM * I_DIM;
    for (int i = idx; i < N; i += stride) {
        int k = i & (I_DIM - 1);
        int m = i >> 9;
        float v = x[i];
        int p = (k & ~7) | kperm(k & 7);
        int o = (m << 9) | p;
        g_xb[o] = rnaf(v);
        g_xq[o] = rnaf(v * v);
    }
}

// ---------------- phase B: xproj via tf32 mma.sync ----------------
#define XP_SMEM (96 * 1024)

__global__ void __launch_bounds__(256, 2) xproj_kernel(const float* __restrict__ eps_in,
                                                       float* __restrict__ out)
{
    extern __shared__ float sm[];
    float* xs  = sm;            // [128][64], row-swizzled
    float* xq  = sm + 8192;
    float* wmu = sm + 16384;    // [8 chunk][4 tig][64 n][2 pair], n XOR-swizzled
    float* wd  = sm + 20480;

    const int tid  = threadIdx.x;
    const int warp = tid >> 5, lane = tid & 31;
    const int gid = lane >> 2, tig = lane & 3;
    const int n_base = blockIdx.x * 64;
    const int m_base = blockIdx.y * 128;
    const int mg = (warp & 3) * 32;
    const int nh = (warp >> 2) * 32;

    float cG[2][4][4] = {}, cD[2][4][4] = {};

    for (int ks = 0; ks < 8; ks++) {
        const int k0s = ks * 64;
        for (int i = tid; i < 2048; i += 256) {
            int r = i >> 4, c4 = i & 15;
            int d4 = c4 ^ ((r & 3) << 1);
            *(float4*)&xs[r * 64 + d4 * 4] =
                *(const float4*)&g_xb[(size_t)(m_base + r) * I_DIM + k0s + c4 * 4];
            *(float4*)&xq[r * 64 + d4 * 4] =
                *(const float4*)&g_xq[(size_t)(m_base + r) * I_DIM + k0s + c4 * 4];
        }
        for (int i = tid; i < 4096; i += 256) {
            int k = i >> 6, n = i & 63;
            int ck = k >> 3, j = k & 7, tk = j & 3, pr = j >> 2;
            int pos = ((ck * 4 + tk) * 64 + (n ^ (tk << 2))) * 2 + pr;
            wmu[pos] = g_mu_in[(size_t)(k0s + k) * H_DIM + n_base + n];
            wd [pos] = g_d_in [(size_t)(k0s + k) * H_DIM + n_base + n];
        }
        __syncthreads();

#pragma unroll
        for (int c = 0; c < 8; c++) {
            uint32_t ax[2][4], aq[2][4];
#pragma unroll
            for (int t = 0; t < 2; t++) {
                int r0 = mg + t * 16 + gid;
                int r1 = r0 + 8;
                float2 f0 = *(float2*)&xs[r0 * 64 + ((c * 4 + tig) ^ ((r0 & 3) << 2)) * 2];
                float2 f1 = *(float2*)&xs[r1 * 64 + ((c * 4 + tig) ^ ((r1 & 3) << 2)) * 2];
                ax[t][0] = __float_as_uint(f0.x); ax[t][2] = __float_as_uint(f0.y);
                ax[t][1] = __float_as_uint(f1.x); ax[t][3] = __float_as_uint(f1.y);
                float2 q0 = *(float2*)&xq[r0 * 64 + ((c * 4 + tig) ^ ((r0 & 3) << 2)) * 2];
                float2 q1 = *(float2*)&xq[r1 * 64 + ((c * 4 + tig) ^ ((r1 & 3) << 2)) * 2];
                aq[t][0] = __float_as_uint(q0.x); aq[t][2] = __float_as_uint(q0.y);
                aq[t][1] = __float_as_uint(q1.x); aq[t][3] = __float_as_uint(q1.y);
            }
#pragma unroll
            for (int nt = 0; nt < 4; nt++) {
                int nl = nh + nt * 8 + gid;
                float2 bm = *(float2*)&wmu[((c * 4 + tig) * 64 + (nl ^ (tig << 2))) * 2];
                float2 bdv = *(float2*)&wd [((c * 4 + tig) * 64 + (nl ^ (tig << 2))) * 2];
                uint32_t bm0 = __float_as_uint(bm.x),  bm1 = __float_as_uint(bm.y);
                uint32_t bd0 = __float_as_uint(bdv.x), bd1 = __float_as_uint(bdv.y);
#pragma unroll
                for (int t = 0; t < 2; t++) {
                    mma8(cG[t][nt], ax[t][0], ax[t][1], ax[t][2], ax[t][3], bm0, bm1);
                    mma8(cD[t][nt], aq[t][0], aq[t][1], aq[t][2], aq[t][3], bd0, bd1);
                }
            }
        }
        __syncthreads();
    }

#pragma unroll
    for (int t = 0; t < 2; t++)
#pragma unroll
    for (int nt = 0; nt < 4; nt++) {
        int n = n_base + nh + nt * 8 + tig * 2;
#pragma unroll
        for (int half = 0; half < 2; half++) {
            int m = m_base + mg + t * 16 + gid + half * 8;
            size_t off = (size_t)m * H_DIM + n;
            float2 e = *(const float2*)(eps_in + off);
            float2 o;
            o.x = cG[t][nt][half * 2]     + e.x * sqrtf(cD[t][nt][half * 2]     + EPS_C);
            o.y = cG[t][nt][half * 2 + 1] + e.y * sqrtf(cD[t][nt][half * 2 + 1] + EPS_C);
            *(float2*)(out + off) = o;
        }
    }
}

// ---------------- grid-wide barrier (release/acquire, no membar.gl) ----------------
__device__ __forceinline__ void grid_barrier(unsigned target)
{
    __syncthreads();
    if (threadIdx.x == 0) {
        unsigned a = atom_add_release(&g_bar_arrive, 1u);
        if (a == NB - 1u) {
            g_bar_arrive = 0u;
            st_release(&g_bar_gen, target);
        } else {
            while (ld_acquire(&g_bar_gen) < target) { __nanosleep(32); }
        }
    }
    __syncthreads();
}

// ---------------- phase C: persistent scan via tf32 mma.sync ----------------
// 128 blocks = 64 n-groups (16 cols) x 2 batch-halves (32 rows).
// 512 threads = 16 warps = 2 m-tiles x 8 k-eighths (128 k per warp, 16 chunks).
// Weights resident in smem all 512 steps; partials reduced across 8 k-slices.
#define SC_SMEM (40960 * 4)

__global__ void __launch_bounds__(512, 1) scan_kernel(const float* __restrict__ eps_h,
                                                      float* __restrict__ out,
                                                      int write_last)
{
    extern __shared__ float sm[];
    float* wmu = sm;            // [128 chunk][4 tig][16 n][2 pair] = 16384 floats
    float* wd  = sm + 16384;
    float* pG  = sm + 32768;    // [8 ke][32 b][16 n]
    float* pD  = sm + 36864;

    const int tid  = threadIdx.x;
    const int warp = tid >> 5, lane = tid & 31;
    const int gid = lane >> 2, tig = lane & 3;
    const int n_base = (blockIdx.x >> 1) * 16;
    const int b_base = (blockIdx.x & 1) * 32;
    const int mt = warp & 1, ke = warp >> 1;

    // stage the block's weight slice once
    for (int i = tid; i < H_DIM * 16; i += 512) {
        int k = i >> 4, n = i & 15;
        int ck = k >> 3, j = k & 7, tk = j & 3, pr = j >> 2;
        int pos = ((ck * 4 + tk) * 16 + (n ^ (tk << 2))) * 2 + pr;
        wmu[pos] = g_mu_h[(size_t)k * H_DIM + n_base + n];
        wd [pos] = g_d_h [(size_t)k * H_DIM + n_base + n];
    }
    __syncthreads();

    const int r0 = b_base + mt * 16 + gid;
    // epilogue: 1 output per thread
    const int eb = tid >> 4;                 // 0..31
    const int en = tid & 15;                 // 0..15
    const int gbrow = b_base + eb;
    const int ncol = n_base + en;
    const int pcol = (ncol & ~7) | kperm(ncol & 7);
    const int hoff = gbrow * H_DIM + pcol;

    for (int t = 0; t < S_LEN; t++) {
        const float* hsrc = (t & 1) ? g_hB : g_hA;
        float* hdst = (t & 1) ? g_hA : g_hB;

        const size_t toff = (size_t)(t * B_DIM + gbrow) * H_DIM + ncol;
        const float epre = __ldg(eps_h + toff);
        const float xpre = __ldcg(out + toff);

        float cG[2][4] = {}, cD[2][4] = {};
        const float* hr0 = hsrc + (size_t)r0 * H_DIM + ke * 128 + 2 * tig;
        const float* hr1 = hr0 + 8 * H_DIM;

#pragma unroll 4
        for (int c = 0; c < 16; c++) {
            const int cg = ke * 16 + c;
            float2 f0 = __ldcg((const float2*)(hr0 + c * 8));
            float2 f1 = __ldcg((const float2*)(hr1 + c * 8));
            uint32_t a0 = __float_as_uint(f0.x), a2 = __float_as_uint(f0.y);
            uint32_t a1 = __float_as_uint(f1.x), a3 = __float_as_uint(f1.y);
            uint32_t q0 = rna(f0.x * f0.x), q2 = rna(f0.y * f0.y);
            uint32_t q1 = rna(f1.x * f1.x), q3 = rna(f1.y * f1.y);
#pragma unroll
            for (int nt = 0; nt < 2; nt++) {
                int nl = nt * 8 + gid;
                float2 bm = *(float2*)&wmu[((cg * 4 + tig) * 16 + (nl ^ (tig << 2))) * 2];
                float2 bdv = *(float2*)&wd [((cg * 4 + tig) * 16 + (nl ^ (tig << 2))) * 2];
                mma8(cG[nt], a0, a1, a2, a3, __float_as_uint(bm.x),  __float_as_uint(bm.y));
                mma8(cD[nt], q0, q1, q2, q3, __float_as_uint(bdv.x), __float_as_uint(bdv.y));
            }
        }

        // partials -> smem
        const int rowa = ke * 32 + mt * 16 + gid;
#pragma unroll
        for (int nt = 0; nt < 2; nt++) {
            int colb = nt * 8 + tig * 2;
            *(float2*)&pG[rowa * 16 + colb]       = make_float2(cG[nt][0], cG[nt][1]);
            *(float2*)&pG[(rowa + 8) * 16 + colb] = make_float2(cG[nt][2], cG[nt][3]);
            *(float2*)&pD[rowa * 16 + colb]       = make_float2(cD[nt][0], cD[nt][1]);
            *(float2*)&pD[(rowa + 8) * 16 + colb] = make_float2(cD[nt][2], cD[nt][3]);
        }
        __syncthreads();

        // reduce 8 k-slices + epilogue (1 output per thread)
        float G = 0.0f, D = 0.0f;
#pragma unroll
        for (int q = 0; q < 8; q++) {
            G += pG[(q * 32 + eb) * 16 + en];
            D += pD[(q * 32 + eb) * 16 + en];
        }
        float h = tanhf(G + epre * sqrtf(D + EPS_C) + xpre);
        __stcg(hdst + hoff, rnaf(h));        // h transport first: on the critical path
        out[toff] = h;
        if (write_last && t == S_LEN - 1)
            out[(size_t)S_LEN * B_DIM * H_DIM + gbrow * H_DIM + ncol] = h;

        if (t < S_LEN - 1) grid_barrier((unsigned)(t + 1));
    }
}

// ---------------- launch ----------------
extern "C" void kernel_launch(void* const* d_in, const int* in_sizes, int n_in,
                              void* d_out, int out_size)
{
    (void)in_sizes; (void)n_in;
    const float* x      = (const float*)d_in[0];
    const float* eps_in = (const float*)d_in[1];
    const float* eps_h  = (const float*)d_in[2];
    const float* m_in   = (const float*)d_in[3];
    const float* pi_in  = (const float*)d_in[4];
    const float* chi_in = (const float*)d_in[5];
    const float* m_h    = (const float*)d_in[6];
    const float* pi_h   = (const float*)d_in[7];
    const float* chi_h  = (const float*)d_in[8];
    float* out = (float*)d_out;

    prep_kernel<<<512, 256>>>(m_in, pi_in, chi_in, m_h, pi_h, chi_h);
    prep_x_kernel<<<8192, 256>>>(x);

    cudaFuncSetAttribute(xproj_kernel, cudaFuncAttributeMaxDynamicSharedMemorySize, XP_SMEM);
    dim3 gB(H_DIM / 64, (S_LEN * B_DIM) / 128);
    xproj_kernel<<<gB, 256, XP_SMEM>>>(eps_in, out);

    cudaFuncSetAttribute(scan_kernel, cudaFuncAttributeMaxDynamicSharedMemorySize, SC_SMEM);
    int write_last = (out_size >= S_LEN * B_DIM * H_DIM + B_DIM * H_DIM) ? 1 : 0;
    scan_kernel<<<NB, 512, SC_SMEM>>>(eps_h, out, write_last);
}

// round 7
// speedup vs baseline: 3.0701x; 1.0330x over previous
#include <cuda_runtime.h>
#include <cstdint>

#define S_LEN 512
#define B_DIM 64
#define I_DIM 512
#define H_DIM 1024
#define EPS_C 1e-10f
#define NB    128

typedef unsigned long long u64;

// ---------------- tf32 helpers ----------------
__device__ __forceinline__ uint32_t rna(float f) {
    uint32_t r; asm("cvt.rna.tf32.f32 %0, %1;" : "=r"(r) : "f"(f)); return r;
}
__device__ __forceinline__ float rnaf(float f) { return __uint_as_float(rna(f)); }

__device__ __forceinline__ void mma8(float* c, uint32_t a0, uint32_t a1, uint32_t a2, uint32_t a3,
                                     uint32_t b0, uint32_t b1) {
    asm volatile("mma.sync.aligned.m16n8k8.row.col.f32.tf32.tf32.f32 "
        "{%0,%1,%2,%3}, {%4,%5,%6,%7}, {%8,%9}, {%0,%1,%2,%3};"
        : "+f"(c[0]), "+f"(c[1]), "+f"(c[2]), "+f"(c[3])
        : "r"(a0), "r"(a1), "r"(a2), "r"(a3), "r"(b0), "r"(b1));
}

// permute within each 8-group: original j -> (j&3)*2 + (j>>2)
__device__ __forceinline__ int kperm(int j) { return ((j & 3) << 1) | (j >> 2); }

// ---------------- scoped atomics for the grid barrier ----------------
__device__ __forceinline__ unsigned atom_add_release(unsigned* p, unsigned v) {
    unsigned old;
    asm volatile("atom.add.release.gpu.u32 %0, [%1], %2;" : "=r"(old) : "l"(p), "r"(v) : "memory");
    return old;
}
__device__ __forceinline__ unsigned ld_acquire(const unsigned* p) {
    unsigned v;
    asm volatile("ld.acquire.gpu.u32 %0, [%1];" : "=r"(v) : "l"(p) : "memory");
    return v;
}
__device__ __forceinline__ void st_release(unsigned* p, unsigned v) {
    asm volatile("st.release.gpu.u32 [%0], %1;" :: "l"(p), "r"(v) : "memory");
}

// ---------------- device scratch ----------------
__device__ float g_mu_in[I_DIM * H_DIM];   // tf32-rounded, [k][n]
__device__ float g_d_in [I_DIM * H_DIM];
__device__ float g_mu_h [H_DIM * H_DIM];   // tf32-rounded, [k][n]
__device__ float g_d_h  [H_DIM * H_DIM];
__device__ __align__(16) float g_xb[S_LEN * B_DIM * I_DIM];  // tf32(x), k-permuted
__device__ __align__(16) float g_xq[S_LEN * B_DIM * I_DIM];  // tf32(x*x), k-permuted
__device__ float g_hA[B_DIM * H_DIM];      // tf32(h) transport, [b][k permuted]
__device__ float g_hB[B_DIM * H_DIM];
__device__ unsigned g_bar_arrive;          // monotonic
__device__ unsigned g_bar_gen;

// ---------------- prep ----------------
__global__ void prep_kernel(const float* __restrict__ m_in, const float* __restrict__ pi_in,
                            const float* __restrict__ chi_in,
                            const float* __restrict__ m_h, const float* __restrict__ pi_h,
                            const float* __restrict__ chi_h)
{
    int idx = blockIdx.x * blockDim.x + threadIdx.x;
    int stride = gridDim.x * blockDim.x;

    for (int i = idx; i < H_DIM * H_DIM; i += stride) {
        if (i < I_DIM * H_DIM) {
            float m = m_in[i], pi = pi_in[i], chi = chi_in[i];
            float mu = (1.0f - pi) * m;
            float rho = (1.0f - pi) * (chi + m * m);
            g_mu_in[i] = rnaf(mu);
            g_d_in[i]  = rnaf(rho - mu * mu);
        }
        float m = m_h[i], pi = pi_h[i], chi = chi_h[i];
        float mu = (1.0f - pi) * m;
        float rho = (1.0f - pi) * (chi + m * m);
        g_mu_h[i] = rnaf(mu);
        g_d_h[i]  = rnaf(rho - mu * mu);
    }
    for (int i = idx; i < B_DIM * H_DIM; i += stride)
        g_hA[i] = 0.0f;
    if (idx == 0) { g_bar_arrive = 0u; g_bar_gen = 0u; }
}

// ---------------- prep_x ----------------
__global__ void prep_x_kernel(const float* __restrict__ x)
{
    int idx = blockIdx.x * blockDim.x + threadIdx.x;
    int stride = gridDim.x * blockDim.x;
    const int N = S_LEN * B_DIM * I_DIM;
    for (int i = idx; i < N; i += stride) {
        int k = i & (I_DIM - 1);
        int m = i >> 9;
        float v = x[i];
        int p = (k & ~7) | kperm(k & 7);
        int o = (m << 9) | p;
        g_xb[o] = rnaf(v);
        g_xq[o] = rnaf(v * v);
    }
}

// ---------------- phase B: xproj via tf32 mma.sync ----------------
#define XP_SMEM (96 * 1024)

__global__ void __launch_bounds__(256, 2) xproj_kernel(const float* __restrict__ eps_in,
                                                       float* __restrict__ out)
{
    extern __shared__ float sm[];
    float* xs  = sm;            // [128][64], row-swizzled
    float* xq  = sm + 8192;
    float* wmu = sm + 16384;    // [8 chunk][4 tig][64 n][2 pair], n XOR-swizzled
    float* wd  = sm + 20480;

    const int tid  = threadIdx.x;
    const int warp = tid >> 5, lane = tid & 31;
    const int gid = lane >> 2, tig = lane & 3;
    const int n_base = blockIdx.x * 64;
    const int m_base = blockIdx.y * 128;
    const int mg = (warp & 3) * 32;
    const int nh = (warp >> 2) * 32;

    float cG[2][4][4] = {}, cD[2][4][4] = {};

    for (int ks = 0; ks < 8; ks++) {
        const int k0s = ks * 64;
        for (int i = tid; i < 2048; i += 256) {
            int r = i >> 4, c4 = i & 15;
            int d4 = c4 ^ ((r & 3) << 1);
            *(float4*)&xs[r * 64 + d4 * 4] =
                *(const float4*)&g_xb[(size_t)(m_base + r) * I_DIM + k0s + c4 * 4];
            *(float4*)&xq[r * 64 + d4 * 4] =
                *(const float4*)&g_xq[(size_t)(m_base + r) * I_DIM + k0s + c4 * 4];
        }
        for (int i = tid; i < 4096; i += 256) {
            int k = i >> 6, n = i & 63;
            int ck = k >> 3, j = k & 7, tk = j & 3, pr = j >> 2;
            int pos = ((ck * 4 + tk) * 64 + (n ^ (tk << 2))) * 2 + pr;
            wmu[pos] = g_mu_in[(size_t)(k0s + k) * H_DIM + n_base + n];
            wd [pos] = g_d_in [(size_t)(k0s + k) * H_DIM + n_base + n];
        }
        __syncthreads();

#pragma unroll
        for (int c = 0; c < 8; c++) {
            uint32_t ax[2][4], aq[2][4];
#pragma unroll
            for (int t = 0; t < 2; t++) {
                int r0 = mg + t * 16 + gid;
                int r1 = r0 + 8;
                float2 f0 = *(float2*)&xs[r0 * 64 + ((c * 4 + tig) ^ ((r0 & 3) << 2)) * 2];
                float2 f1 = *(float2*)&xs[r1 * 64 + ((c * 4 + tig) ^ ((r1 & 3) << 2)) * 2];
                ax[t][0] = __float_as_uint(f0.x); ax[t][2] = __float_as_uint(f0.y);
                ax[t][1] = __float_as_uint(f1.x); ax[t][3] = __float_as_uint(f1.y);
                float2 q0 = *(float2*)&xq[r0 * 64 + ((c * 4 + tig) ^ ((r0 & 3) << 2)) * 2];
                float2 q1 = *(float2*)&xq[r1 * 64 + ((c * 4 + tig) ^ ((r1 & 3) << 2)) * 2];
                aq[t][0] = __float_as_uint(q0.x); aq[t][2] = __float_as_uint(q0.y);
                aq[t][1] = __float_as_uint(q1.x); aq[t][3] = __float_as_uint(q1.y);
            }
#pragma unroll
            for (int nt = 0; nt < 4; nt++) {
                int nl = nh + nt * 8 + gid;
                float2 bm = *(float2*)&wmu[((c * 4 + tig) * 64 + (nl ^ (tig << 2))) * 2];
                float2 bdv = *(float2*)&wd [((c * 4 + tig) * 64 + (nl ^ (tig << 2))) * 2];
                uint32_t bm0 = __float_as_uint(bm.x),  bm1 = __float_as_uint(bm.y);
                uint32_t bd0 = __float_as_uint(bdv.x), bd1 = __float_as_uint(bdv.y);
#pragma unroll
                for (int t = 0; t < 2; t++) {
                    mma8(cG[t][nt], ax[t][0], ax[t][1], ax[t][2], ax[t][3], bm0, bm1);
                    mma8(cD[t][nt], aq[t][0], aq[t][1], aq[t][2], aq[t][3], bd0, bd1);
                }
            }
        }
        __syncthreads();
    }

#pragma unroll
    for (int t = 0; t < 2; t++)
#pragma unroll
    for (int nt = 0; nt < 4; nt++) {
        int n = n_base + nh + nt * 8 + tig * 2;
#pragma unroll
        for (int half = 0; half < 2; half++) {
            int m = m_base + mg + t * 16 + gid + half * 8;
            size_t off = (size_t)m * H_DIM + n;
            float2 e = *(const float2*)(eps_in + off);
            float2 o;
            o.x = cG[t][nt][half * 2]     + e.x * sqrtf(cD[t][nt][half * 2]     + EPS_C);
            o.y = cG[t][nt][half * 2 + 1] + e.y * sqrtf(cD[t][nt][half * 2 + 1] + EPS_C);
            *(float2*)(out + off) = o;
        }
    }
}

// ---------------- phase C: persistent scan via tf32 mma.sync ----------------
// 128 blocks = 64 n-groups (16 cols) x 2 batch-halves (32 rows).
// 512 threads = 16 warps = 2 m-tiles x 8 k-eighths. Weights resident in smem.
// All 32 h-loads preloaded to registers (full MLP). Monotonic grid barrier with
// tight acquire-spin; out-store + next-step prefetch hidden between arrive & poll.
#define SC_SMEM (40960 * 4)

__global__ void __launch_bounds__(512, 1) scan_kernel(const float* __restrict__ eps_h,
                                                      float* __restrict__ out,
                                                      int write_last)
{
    extern __shared__ float sm[];
    float* wmu = sm;            // [128 chunk][4 tig][16 n][2 pair] = 16384 floats
    float* wd  = sm + 16384;
    float* pG  = sm + 32768;    // [8 ke][32 b][16 n]
    float* pD  = sm + 36864;

    const int tid  = threadIdx.x;
    const int warp = tid >> 5, lane = tid & 31;
    const int gid = lane >> 2, tig = lane & 3;
    const int n_base = (blockIdx.x >> 1) * 16;
    const int b_base = (blockIdx.x & 1) * 32;
    const int mt = warp & 1, ke = warp >> 1;

    // stage the block's weight slice once
    for (int i = tid; i < H_DIM * 16; i += 512) {
        int k = i >> 4, n = i & 15;
        int ck = k >> 3, j = k & 7, tk = j & 3, pr = j >> 2;
        int pos = ((ck * 4 + tk) * 16 + (n ^ (tk << 2))) * 2 + pr;
        wmu[pos] = g_mu_h[(size_t)k * H_DIM + n_base + n];
        wd [pos] = g_d_h [(size_t)k * H_DIM + n_base + n];
    }

    const int r0 = b_base + mt * 16 + gid;
    const int eb = tid >> 4;                 // 0..31
    const int en = tid & 15;                 // 0..15
    const int gbrow = b_base + eb;
    const int ncol = n_base + en;
    const int pcol = (ncol & ~7) | kperm(ncol & 7);
    const int hoff = gbrow * H_DIM + pcol;

    // prefetch step-0 epilogue operands
    size_t toff = (size_t)gbrow * H_DIM + ncol;
    float epre = __ldg(eps_h + toff);
    float xpre = __ldcg(out + toff);
    __syncthreads();

    for (int t = 0; t < S_LEN; t++) {
        const float* hsrc = (t & 1) ? g_hB : g_hA;
        float* hdst = (t & 1) ? g_hA : g_hB;

        // ---- preload all h fragments (32 independent LDGs, full MLP) ----
        const float* hr0 = hsrc + (size_t)r0 * H_DIM + ke * 128 + 2 * tig;
        const float* hr1 = hr0 + 8 * H_DIM;
        float2 f0v[16], f1v[16];
#pragma unroll
        for (int c = 0; c < 16; c++) {
            f0v[c] = __ldcg((const float2*)(hr0 + c * 8));
            f1v[c] = __ldcg((const float2*)(hr1 + c * 8));
        }

        float cG[2][4] = {}, cD[2][4] = {};
#pragma unroll
        for (int c = 0; c < 16; c++) {
            const int cg = ke * 16 + c;
            uint32_t a0 = __float_as_uint(f0v[c].x), a2 = __float_as_uint(f0v[c].y);
            uint32_t a1 = __float_as_uint(f1v[c].x), a3 = __float_as_uint(f1v[c].y);
            uint32_t q0 = rna(f0v[c].x * f0v[c].x), q2 = rna(f0v[c].y * f0v[c].y);
            uint32_t q1 = rna(f1v[c].x * f1v[c].x), q3 = rna(f1v[c].y * f1v[c].y);
#pragma unroll
            for (int nt = 0; nt < 2; nt++) {
                int nl = nt * 8 + gid;
                float2 bm = *(float2*)&wmu[((cg * 4 + tig) * 16 + (nl ^ (tig << 2))) * 2];
                float2 bdv = *(float2*)&wd [((cg * 4 + tig) * 16 + (nl ^ (tig << 2))) * 2];
                mma8(cG[nt], a0, a1, a2, a3, __float_as_uint(bm.x),  __float_as_uint(bm.y));
                mma8(cD[nt], q0, q1, q2, q3, __float_as_uint(bdv.x), __float_as_uint(bdv.y));
            }
        }

        // partials -> smem
        const int rowa = ke * 32 + mt * 16 + gid;
#pragma unroll
        for (int nt = 0; nt < 2; nt++) {
            int colb = nt * 8 + tig * 2;
            *(float2*)&pG[rowa * 16 + colb]       = make_float2(cG[nt][0], cG[nt][1]);
            *(float2*)&pG[(rowa + 8) * 16 + colb] = make_float2(cG[nt][2], cG[nt][3]);
            *(float2*)&pD[rowa * 16 + colb]       = make_float2(cD[nt][0], cD[nt][1]);
            *(float2*)&pD[(rowa + 8) * 16 + colb] = make_float2(cD[nt][2], cD[nt][3]);
        }
        __syncthreads();

        // reduce 8 k-slices + epilogue (1 output per thread)
        float G = 0.0f, D = 0.0f;
#pragma unroll
        for (int q = 0; q < 8; q++) {
            G += pG[(q * 32 + eb) * 16 + en];
            D += pD[(q * 32 + eb) * 16 + en];
        }
        float h = tanhf(G + epre * sqrtf(D + EPS_C) + xpre);
        __stcg(hdst + hoff, rnaf(h));        // h transport: the only critical store

        if (t == S_LEN - 1) {
            out[toff] = h;
            if (write_last)
                out[(size_t)S_LEN * B_DIM * H_DIM + gbrow * H_DIM + ncol] = h;
            break;
        }

        // ---- grid barrier: arrive, overlap non-critical work, then poll ----
        __syncthreads();                      // all h stores done (CTA edge)
        const unsigned target = (unsigned)(t + 1);
        if (tid == 0) {
            unsigned a = atom_add_release(&g_bar_arrive, 1u);
            if (a == target * NB - 1u)
                st_release(&g_bar_gen, target);
        }
        // hidden work: current out-store + next-step operand prefetch
        out[toff] = h;
        toff = (size_t)((t + 1) * B_DIM + gbrow) * H_DIM + ncol;
        epre = __ldg(eps_h + toff);
        xpre = __ldcg(out + toff);
        if (tid == 0) {
            while (ld_acquire(&g_bar_gen) < target) { }
        }
        __syncthreads();
    }
}

// ---------------- launch ----------------
extern "C" void kernel_launch(void* const* d_in, const int* in_sizes, int n_in,
                              void* d_out, int out_size)
{
    (void)in_sizes; (void)n_in;
    const float* x      = (const float*)d_in[0];
    const float* eps_in = (const float*)d_in[1];
    const float* eps_h  = (const float*)d_in[2];
    const float* m_in   = (const float*)d_in[3];
    const float* pi_in  = (const float*)d_in[4];
    const float* chi_in = (const float*)d_in[5];
    const float* m_h    = (const float*)d_in[6];
    const float* pi_h   = (const float*)d_in[7];
    const float* chi_h  = (const float*)d_in[8];
    float* out = (float*)d_out;

    prep_kernel<<<512, 256>>>(m_in, pi_in, chi_in, m_h, pi_h, chi_h);
    prep_x_kernel<<<8192, 256>>>(x);

    cudaFuncSetAttribute(xproj_kernel, cudaFuncAttributeMaxDynamicSharedMemorySize, XP_SMEM);
    dim3 gB(H_DIM / 64, (S_LEN * B_DIM) / 128);
    xproj_kernel<<<gB, 256, XP_SMEM>>>(eps_in, out);

    cudaFuncSetAttribute(scan_kernel, cudaFuncAttributeMaxDynamicSharedMemorySize, SC_SMEM);
    int write_last = (out_size >= S_LEN * B_DIM * H_DIM + B_DIM * H_DIM) ? 1 : 0;
    scan_kernel<<<NB, 512, SC_SMEM>>>(eps_h, out, write_last);
}

// round 8
// speedup vs baseline: 3.7895x; 1.2343x over previous
#include <cuda_runtime.h>
#include <cuda_bf16.h>
#include <cstdint>

#define S_LEN 512
#define B_DIM 64
#define I_DIM 512
#define H_DIM 1024
#define EPS_C 1e-10f
#define NB    128

typedef unsigned long long u64;

// ---------------- tf32 helpers (xproj) ----------------
__device__ __forceinline__ uint32_t rna(float f) {
    uint32_t r; asm("cvt.rna.tf32.f32 %0, %1;" : "=r"(r) : "f"(f)); return r;
}
__device__ __forceinline__ float rnaf(float f) { return __uint_as_float(rna(f)); }

__device__ __forceinline__ void mma8(float* c, uint32_t a0, uint32_t a1, uint32_t a2, uint32_t a3,
                                     uint32_t b0, uint32_t b1) {
    asm volatile("mma.sync.aligned.m16n8k8.row.col.f32.tf32.tf32.f32 "
        "{%0,%1,%2,%3}, {%4,%5,%6,%7}, {%8,%9}, {%0,%1,%2,%3};"
        : "+f"(c[0]), "+f"(c[1]), "+f"(c[2]), "+f"(c[3])
        : "r"(a0), "r"(a1), "r"(a2), "r"(a3), "r"(b0), "r"(b1));
}

// ---------------- bf16 helpers (scan) ----------------
__device__ __forceinline__ void mma16(float* c, uint32_t a0, uint32_t a1, uint32_t a2, uint32_t a3,
                                      uint32_t b0, uint32_t b1) {
    asm volatile("mma.sync.aligned.m16n8k16.row.col.f32.bf16.bf16.f32 "
        "{%0,%1,%2,%3}, {%4,%5,%6,%7}, {%8,%9}, {%0,%1,%2,%3};"
        : "+f"(c[0]), "+f"(c[1]), "+f"(c[2]), "+f"(c[3])
        : "r"(a0), "r"(a1), "r"(a2), "r"(a3), "r"(b0), "r"(b1));
}
__device__ __forceinline__ uint32_t mulbf2(uint32_t a, uint32_t b) {
    uint32_t d; asm("mul.rn.bf16x2 %0, %1, %2;" : "=r"(d) : "r"(a), "r"(b)); return d;
}
__device__ __forceinline__ uint32_t bpack(float lo, float hi) {
    __nv_bfloat162 t = __floats2bfloat162_rn(lo, hi);   // .x = low half
    return *reinterpret_cast<uint32_t*>(&t);
}

// k-permutations: tf32 k8 groups (xproj) and bf16 k16 groups (scan h transport)
__device__ __forceinline__ int kperm(int j)  { return ((j & 3) << 1) | (j >> 2); }
__device__ __forceinline__ int kperm16(int j) {   // order [0,1,8,9,2,3,10,11,...]
    return (((j & 7) >> 1) << 2) | (((j >> 3) & 1) << 1) | (j & 1);
}

// ---------------- scoped atomics for the grid barrier ----------------
__device__ __forceinline__ unsigned atom_add_release(unsigned* p, unsigned v) {
    unsigned old;
    asm volatile("atom.add.release.gpu.u32 %0, [%1], %2;" : "=r"(old) : "l"(p), "r"(v) : "memory");
    return old;
}
__device__ __forceinline__ unsigned ld_acquire(const unsigned* p) {
    unsigned v;
    asm volatile("ld.acquire.gpu.u32 %0, [%1];" : "=r"(v) : "l"(p) : "memory");
    return v;
}
__device__ __forceinline__ void st_release(unsigned* p, unsigned v) {
    asm volatile("st.release.gpu.u32 [%0], %1;" :: "l"(p), "r"(v) : "memory");
}

// ---------------- device scratch ----------------
__device__ float g_mu_in[I_DIM * H_DIM];   // tf32-rounded, [k][n]
__device__ float g_d_in [I_DIM * H_DIM];
__device__ float g_mu_h [H_DIM * H_DIM];   // fp32, [k][n] (bf16-split at staging)
__device__ float g_d_h  [H_DIM * H_DIM];
__device__ __align__(16) float g_xb[S_LEN * B_DIM * I_DIM];  // tf32(x), k-permuted
__device__ __align__(16) float g_xq[S_LEN * B_DIM * I_DIM];  // tf32(x*x), k-permuted
__device__ __align__(16) __nv_bfloat16 g_hA[B_DIM * H_DIM];  // bf16 h transport, k16-permuted
__device__ __align__(16) __nv_bfloat16 g_hB[B_DIM * H_DIM];
__device__ unsigned g_bar_arrive;          // monotonic
__device__ unsigned g_bar_gen;

// ---------------- prep ----------------
__global__ void prep_kernel(const float* __restrict__ m_in, const float* __restrict__ pi_in,
                            const float* __restrict__ chi_in,
                            const float* __restrict__ m_h, const float* __restrict__ pi_h,
                            const float* __restrict__ chi_h)
{
    int idx = blockIdx.x * blockDim.x + threadIdx.x;
    int stride = gridDim.x * blockDim.x;

    for (int i = idx; i < H_DIM * H_DIM; i += stride) {
        if (i < I_DIM * H_DIM) {
            float m = m_in[i], pi = pi_in[i], chi = chi_in[i];
            float mu = (1.0f - pi) * m;
            float rho = (1.0f - pi) * (chi + m * m);
            g_mu_in[i] = rnaf(mu);
            g_d_in[i]  = rnaf(rho - mu * mu);
        }
        float m = m_h[i], pi = pi_h[i], chi = chi_h[i];
        float mu = (1.0f - pi) * m;
        float rho = (1.0f - pi) * (chi + m * m);
        g_mu_h[i] = mu;
        g_d_h[i]  = rho - mu * mu;
    }
    // zero bf16 h buffer A (64K bf16 = 32768 u32)
    for (int i = idx; i < (B_DIM * H_DIM) / 2; i += stride)
        reinterpret_cast<uint32_t*>(g_hA)[i] = 0u;
    if (idx == 0) { g_bar_arrive = 0u; g_bar_gen = 0u; }
}

// ---------------- prep_x ----------------
__global__ void prep_x_kernel(const float* __restrict__ x)
{
    int idx = blockIdx.x * blockDim.x + threadIdx.x;
    int stride = gridDim.x * blockDim.x;
    const int N = S_LEN * B_DIM * I_DIM;
    for (int i = idx; i < N; i += stride) {
        int k = i & (I_DIM - 1);
        int m = i >> 9;
        float v = x[i];
        int p = (k & ~7) | kperm(k & 7);
        int o = (m << 9) | p;
        g_xb[o] = rnaf(v);
        g_xq[o] = rnaf(v * v);
    }
}

// ---------------- phase B: xproj via tf32 mma.sync (unchanged) ----------------
#define XP_SMEM (96 * 1024)

__global__ void __launch_bounds__(256, 2) xproj_kernel(const float* __restrict__ eps_in,
                                                       float* __restrict__ out)
{
    extern __shared__ float sm[];
    float* xs  = sm;
    float* xq  = sm + 8192;
    float* wmu = sm + 16384;
    float* wd  = sm + 20480;

    const int tid  = threadIdx.x;
    const int warp = tid >> 5, lane = tid & 31;
    const int gid = lane >> 2, tig = lane & 3;
    const int n_base = blockIdx.x * 64;
    const int m_base = blockIdx.y * 128;
    const int mg = (warp & 3) * 32;
    const int nh = (warp >> 2) * 32;

    float cG[2][4][4] = {}, cD[2][4][4] = {};

    for (int ks = 0; ks < 8; ks++) {
        const int k0s = ks * 64;
        for (int i = tid; i < 2048; i += 256) {
            int r = i >> 4, c4 = i & 15;
            int d4 = c4 ^ ((r & 3) << 1);
            *(float4*)&xs[r * 64 + d4 * 4] =
                *(const float4*)&g_xb[(size_t)(m_base + r) * I_DIM + k0s + c4 * 4];
            *(float4*)&xq[r * 64 + d4 * 4] =
                *(const float4*)&g_xq[(size_t)(m_base + r) * I_DIM + k0s + c4 * 4];
        }
        for (int i = tid; i < 4096; i += 256) {
            int k = i >> 6, n = i & 63;
            int ck = k >> 3, j = k & 7, tk = j & 3, pr = j >> 2;
            int pos = ((ck * 4 + tk) * 64 + (n ^ (tk << 2))) * 2 + pr;
            wmu[pos] = g_mu_in[(size_t)(k0s + k) * H_DIM + n_base + n];
            wd [pos] = g_d_in [(size_t)(k0s + k) * H_DIM + n_base + n];
        }
        __syncthreads();

#pragma unroll
        for (int c = 0; c < 8; c++) {
            uint32_t ax[2][4], aq[2][4];
#pragma unroll
            for (int t = 0; t < 2; t++) {
                int r0 = mg + t * 16 + gid;
                int r1 = r0 + 8;
                float2 f0 = *(float2*)&xs[r0 * 64 + ((c * 4 + tig) ^ ((r0 & 3) << 2)) * 2];
                float2 f1 = *(float2*)&xs[r1 * 64 + ((c * 4 + tig) ^ ((r1 & 3) << 2)) * 2];
                ax[t][0] = __float_as_uint(f0.x); ax[t][2] = __float_as_uint(f0.y);
                ax[t][1] = __float_as_uint(f1.x); ax[t][3] = __float_as_uint(f1.y);
                float2 q0 = *(float2*)&xq[r0 * 64 + ((c * 4 + tig) ^ ((r0 & 3) << 2)) * 2];
                float2 q1 = *(float2*)&xq[r1 * 64 + ((c * 4 + tig) ^ ((r1 & 3) << 2)) * 2];
                aq[t][0] = __float_as_uint(q0.x); aq[t][2] = __float_as_uint(q0.y);
                aq[t][1] = __float_as_uint(q1.x); aq[t][3] = __float_as_uint(q1.y);
            }
#pragma unroll
            for (int nt = 0; nt < 4; nt++) {
                int nl = nh + nt * 8 + gid;
                float2 bm = *(float2*)&wmu[((c * 4 + tig) * 64 + (nl ^ (tig << 2))) * 2];
                float2 bdv = *(float2*)&wd [((c * 4 + tig) * 64 + (nl ^ (tig << 2))) * 2];
                uint32_t bm0 = __float_as_uint(bm.x),  bm1 = __float_as_uint(bm.y);
                uint32_t bd0 = __float_as_uint(bdv.x), bd1 = __float_as_uint(bdv.y);
#pragma unroll
                for (int t = 0; t < 2; t++) {
                    mma8(cG[t][nt], ax[t][0], ax[t][1], ax[t][2], ax[t][3], bm0, bm1);
                    mma8(cD[t][nt], aq[t][0], aq[t][1], aq[t][2], aq[t][3], bd0, bd1);
                }
            }
        }
        __syncthreads();
    }

#pragma unroll
    for (int t = 0; t < 2; t++)
#pragma unroll
    for (int nt = 0; nt < 4; nt++) {
        int n = n_base + nh + nt * 8 + tig * 2;
#pragma unroll
        for (int half = 0; half < 2; half++) {
            int m = m_base + mg + t * 16 + gid + half * 8;
            size_t off = (size_t)m * H_DIM + n;
            float2 e = *(const float2*)(eps_in + off);
            float2 o;
            o.x = cG[t][nt][half * 2]     + e.x * sqrtf(cD[t][nt][half * 2]     + EPS_C);
            o.y = cG[t][nt][half * 2 + 1] + e.y * sqrtf(cD[t][nt][half * 2 + 1] + EPS_C);
            *(float2*)(out + off) = o;
        }
    }
}

// ---------------- phase C: persistent scan via bf16 mma.m16n8k16 ----------------
// 128 blocks = 64 n-groups (16 cols) x 2 batch-halves (32 rows). 512 threads =
// 16 warps = 2 m-tiles x 8 k-eighths (8 k16-chunks per warp). G weights hi+lo
// bf16 split; D weights single bf16; h transported single bf16 (k16-permuted).
// Weight smem pre-packed as 8B B-fragments with +4*tig bank rotation.
#define SC_SMEM (131072)

__global__ void __launch_bounds__(512, 1) scan_kernel(const float* __restrict__ eps_h,
                                                      float* __restrict__ out,
                                                      int write_last)
{
    extern __shared__ char smc[];
    u64* whi = (u64*)smc;                    // [64 cg][4 tig][16 n] u64 = 32KB
    u64* wlo = whi + 4096;
    u64* wdd = wlo + 4096;
    float* pG = (float*)(wdd + 4096);        // [8 ke][32 b][16 n] = 16KB
    float* pD = pG + 4096;

    const int tid  = threadIdx.x;
    const int warp = tid >> 5, lane = tid & 31;
    const int gid = lane >> 2, tig = lane & 3;
    const int n_base = (blockIdx.x >> 1) * 16;
    const int b_base = (blockIdx.x & 1) * 32;
    const int mt = warp & 1, ke = warp >> 1;

    // stage weights once: split mu into hi+lo bf16, d single bf16
    for (int i = tid; i < 4096; i += 512) {
        int cg = i >> 6, tg = (i >> 4) & 3, n = i & 15;
        int sidx = cg * 64 + tg * 16 + ((n + 4 * tg) & 15);
        int k0 = cg * 16 + 2 * tg;
        int gn = n_base + n;
        float m0 = g_mu_h[(size_t)k0 * H_DIM + gn];
        float m1 = g_mu_h[(size_t)(k0 + 1) * H_DIM + gn];
        float m8 = g_mu_h[(size_t)(k0 + 8) * H_DIM + gn];
        float m9 = g_mu_h[(size_t)(k0 + 9) * H_DIM + gn];
        float h0 = __bfloat162float(__float2bfloat16(m0));
        float h1 = __bfloat162float(__float2bfloat16(m1));
        float h8 = __bfloat162float(__float2bfloat16(m8));
        float h9 = __bfloat162float(__float2bfloat16(m9));
        whi[sidx] = (u64)bpack(h0, h1) | ((u64)bpack(h8, h9) << 32);
        wlo[sidx] = (u64)bpack(m0 - h0, m1 - h1) | ((u64)bpack(m8 - h8, m9 - h9) << 32);
        float d0 = g_d_h[(size_t)k0 * H_DIM + gn];
        float d1 = g_d_h[(size_t)(k0 + 1) * H_DIM + gn];
        float d8 = g_d_h[(size_t)(k0 + 8) * H_DIM + gn];
        float d9 = g_d_h[(size_t)(k0 + 9) * H_DIM + gn];
        wdd[sidx] = (u64)bpack(d0, d1) | ((u64)bpack(d8, d9) << 32);
    }

    const int r0 = b_base + mt * 16 + gid;
    const int eb = tid >> 4;                 // 0..31
    const int en = tid & 15;                 // 0..15
    const int gbrow = b_base + eb;
    const int ncol = n_base + en;
    const int hoff = gbrow * H_DIM + (ncol & ~15) + kperm16(ncol & 15);

    // prefetch step-0 epilogue operands
    size_t toff = (size_t)gbrow * H_DIM + ncol;
    float epre = __ldg(eps_h + toff);
    float xpre = __ldcg(out + toff);
    __syncthreads();

    for (int t = 0; t < S_LEN; t++) {
        const __nv_bfloat16* hsrc = (t & 1) ? g_hB : g_hA;
        __nv_bfloat16* hdst = (t & 1) ? g_hA : g_hB;

        // ---- preload all h fragments (16 independent LDG.64, full MLP) ----
        const __nv_bfloat16* hr0 = hsrc + (size_t)r0 * H_DIM + ke * 128 + tig * 4;
        const __nv_bfloat16* hr1 = hr0 + 8 * H_DIM;
        uint2 v0[8], v1[8];
#pragma unroll
        for (int c = 0; c < 8; c++) {
            v0[c] = __ldcg((const uint2*)(hr0 + c * 16));
            v1[c] = __ldcg((const uint2*)(hr1 + c * 16));
        }

        float cG[2][4] = {}, cD[2][4] = {};
#pragma unroll
        for (int c = 0; c < 8; c++) {
            const int cg = ke * 8 + c;
            uint32_t a0 = v0[c].x, a2 = v0[c].y;
            uint32_t a1 = v1[c].x, a3 = v1[c].y;
            uint32_t q0 = mulbf2(a0, a0), q2 = mulbf2(a2, a2);
            uint32_t q1 = mulbf2(a1, a1), q3 = mulbf2(a3, a3);
#pragma unroll
            for (int nt = 0; nt < 2; nt++) {
                int nl = nt * 8 + gid;
                int sidx = cg * 64 + tig * 16 + ((nl + 4 * tig) & 15);
                u64 wh = whi[sidx], wl = wlo[sidx], wv = wdd[sidx];
                mma16(cG[nt], a0, a1, a2, a3, (uint32_t)wh, (uint32_t)(wh >> 32));
                mma16(cG[nt], a0, a1, a2, a3, (uint32_t)wl, (uint32_t)(wl >> 32));
                mma16(cD[nt], q0, q1, q2, q3, (uint32_t)wv, (uint32_t)(wv >> 32));
            }
        }

        // partials -> smem
        const int rowa = ke * 32 + mt * 16 + gid;
#pragma unroll
        for (int nt = 0; nt < 2; nt++) {
            int colb = nt * 8 + tig * 2;
            *(float2*)&pG[rowa * 16 + colb]       = make_float2(cG[nt][0], cG[nt][1]);
            *(float2*)&pG[(rowa + 8) * 16 + colb] = make_float2(cG[nt][2], cG[nt][3]);
            *(float2*)&pD[rowa * 16 + colb]       = make_float2(cD[nt][0], cD[nt][1]);
            *(float2*)&pD[(rowa + 8) * 16 + colb] = make_float2(cD[nt][2], cD[nt][3]);
        }
        __syncthreads();

        // reduce 8 k-slices + epilogue (1 output per thread)
        float G = 0.0f, D = 0.0f;
#pragma unroll
        for (int q = 0; q < 8; q++) {
            G += pG[(q * 32 + eb) * 16 + en];
            D += pD[(q * 32 + eb) * 16 + en];
        }
        float h = tanhf(G + epre * sqrtf(D + EPS_C) + xpre);
        hdst[hoff] = __float2bfloat16(h);    // h transport: the only critical store

        if (t == S_LEN - 1) {
            out[toff] = h;
            if (write_last)
                out[(size_t)S_LEN * B_DIM * H_DIM + gbrow * H_DIM + ncol] = h;
            break;
        }

        // ---- grid barrier: arrive, overlap non-critical work, then poll ----
        __syncthreads();
        const unsigned target = (unsigned)(t + 1);
        if (tid == 0) {
            unsigned a = atom_add_release(&g_bar_arrive, 1u);
            if (a == target * NB - 1u)
                st_release(&g_bar_gen, target);
        }
        out[toff] = h;
        toff = (size_t)((t + 1) * B_DIM + gbrow) * H_DIM + ncol;
        epre = __ldg(eps_h + toff);
        xpre = __ldcg(out + toff);
        if (tid == 0) {
            while (ld_acquire(&g_bar_gen) < target) { }
        }
        __syncthreads();
    }
}

// ---------------- launch ----------------
extern "C" void kernel_launch(void* const* d_in, const int* in_sizes, int n_in,
                              void* d_out, int out_size)
{
    (void)in_sizes; (void)n_in;
    const float* x      = (const float*)d_in[0];
    const float* eps_in = (const float*)d_in[1];
    const float* eps_h  = (const float*)d_in[2];
    const float* m_in   = (const float*)d_in[3];
    const float* pi_in  = (const float*)d_in[4];
    const float* chi_in = (const float*)d_in[5];
    const float* m_h    = (const float*)d_in[6];
    const float* pi_h   = (const float*)d_in[7];
    const float* chi_h  = (const float*)d_in[8];
    float* out = (float*)d_out;

    prep_kernel<<<512, 256>>>(m_in, pi_in, chi_in, m_h, pi_h, chi_h);
    prep_x_kernel<<<8192, 256>>>(x);

    cudaFuncSetAttribute(xproj_kernel, cudaFuncAttributeMaxDynamicSharedMemorySize, XP_SMEM);
    dim3 gB(H_DIM / 64, (S_LEN * B_DIM) / 128);
    xproj_kernel<<<gB, 256, XP_SMEM>>>(eps_in, out);

    cudaFuncSetAttribute(scan_kernel, cudaFuncAttributeMaxDynamicSharedMemorySize, SC_SMEM);
    int write_last = (out_size >= S_LEN * B_DIM * H_DIM + B_DIM * H_DIM) ? 1 : 0;
    scan_kernel<<<NB, 512, SC_SMEM>>>(eps_h, out, write_last);
}

// round 9
// speedup vs baseline: 4.1292x; 1.0896x over previous
#include <cuda_runtime.h>
#include <cuda_bf16.h>
#include <cstdint>

#define S_LEN 512
#define B_DIM 64
#define I_DIM 512
#define H_DIM 1024
#define EPS_C 1e-10f
#define NB    128

typedef unsigned long long u64;

// ---------------- tf32 helpers (xproj) ----------------
__device__ __forceinline__ uint32_t rna(float f) {
    uint32_t r; asm("cvt.rna.tf32.f32 %0, %1;" : "=r"(r) : "f"(f)); return r;
}
__device__ __forceinline__ float rnaf(float f) { return __uint_as_float(rna(f)); }

__device__ __forceinline__ void mma8(float* c, uint32_t a0, uint32_t a1, uint32_t a2, uint32_t a3,
                                     uint32_t b0, uint32_t b1) {
    asm volatile("mma.sync.aligned.m16n8k8.row.col.f32.tf32.tf32.f32 "
        "{%0,%1,%2,%3}, {%4,%5,%6,%7}, {%8,%9}, {%0,%1,%2,%3};"
        : "+f"(c[0]), "+f"(c[1]), "+f"(c[2]), "+f"(c[3])
        : "r"(a0), "r"(a1), "r"(a2), "r"(a3), "r"(b0), "r"(b1));
}

// ---------------- bf16 helpers (scan) ----------------
__device__ __forceinline__ void mma16(float* c, uint32_t a0, uint32_t a1, uint32_t a2, uint32_t a3,
                                      uint32_t b0, uint32_t b1) {
    asm volatile("mma.sync.aligned.m16n8k16.row.col.f32.bf16.bf16.f32 "
        "{%0,%1,%2,%3}, {%4,%5,%6,%7}, {%8,%9}, {%0,%1,%2,%3};"
        : "+f"(c[0]), "+f"(c[1]), "+f"(c[2]), "+f"(c[3])
        : "r"(a0), "r"(a1), "r"(a2), "r"(a3), "r"(b0), "r"(b1));
}
__device__ __forceinline__ uint32_t mulbf2(uint32_t a, uint32_t b) {
    uint32_t d; asm("mul.rn.bf16x2 %0, %1, %2;" : "=r"(d) : "r"(a), "r"(b)); return d;
}
__device__ __forceinline__ uint32_t bpack(float lo, float hi) {
    __nv_bfloat162 t = __floats2bfloat162_rn(lo, hi);   // .x = low half
    return *reinterpret_cast<uint32_t*>(&t);
}
__device__ __forceinline__ float tanh_ap(float x) {
    float y; asm("tanh.approx.f32 %0, %1;" : "=f"(y) : "f"(x)); return y;
}

// k-permutations
__device__ __forceinline__ int kperm(int j)  { return ((j & 3) << 1) | (j >> 2); }
__device__ __forceinline__ int kperm16(int j) {   // order [0,1,8,9,2,3,10,11,...]
    return (((j & 7) >> 1) << 2) | (((j >> 3) & 1) << 1) | (j & 1);
}

// ---------------- scoped atomics for the grid barrier ----------------
__device__ __forceinline__ unsigned ld_acquire(const unsigned* p) {
    unsigned v;
    asm volatile("ld.acquire.gpu.u32 %0, [%1];" : "=r"(v) : "l"(p) : "memory");
    return v;
}
__device__ __forceinline__ void st_release(unsigned* p, unsigned v) {
    asm volatile("st.release.gpu.u32 [%0], %1;" :: "l"(p), "r"(v) : "memory");
}

// ---------------- device scratch ----------------
__device__ float g_mu_in[I_DIM * H_DIM];   // tf32-rounded, [k][n]
__device__ float g_d_in [I_DIM * H_DIM];
__device__ float g_mu_h [H_DIM * H_DIM];   // fp32, [k][n] (bf16-split at staging)
__device__ float g_d_h  [H_DIM * H_DIM];
__device__ __align__(16) float g_xb[S_LEN * B_DIM * I_DIM];  // tf32(x), k-permuted
__device__ __align__(16) float g_xq[S_LEN * B_DIM * I_DIM];  // tf32(x*x), k-permuted
__device__ __align__(16) __nv_bfloat16 g_hA[B_DIM * H_DIM];  // bf16 h transport, k16-permuted
__device__ __align__(16) __nv_bfloat16 g_hB[B_DIM * H_DIM];
__device__ __align__(128) unsigned g_flags[NB * 32];  // 1 flag per 128B line, monotonic

// ---------------- prep ----------------
__global__ void prep_kernel(const float* __restrict__ m_in, const float* __restrict__ pi_in,
                            const float* __restrict__ chi_in,
                            const float* __restrict__ m_h, const float* __restrict__ pi_h,
                            const float* __restrict__ chi_h)
{
    int idx = blockIdx.x * blockDim.x + threadIdx.x;
    int stride = gridDim.x * blockDim.x;

    for (int i = idx; i < H_DIM * H_DIM; i += stride) {
        if (i < I_DIM * H_DIM) {
            float m = m_in[i], pi = pi_in[i], chi = chi_in[i];
            float mu = (1.0f - pi) * m;
            float rho = (1.0f - pi) * (chi + m * m);
            g_mu_in[i] = rnaf(mu);
            g_d_in[i]  = rnaf(rho - mu * mu);
        }
        float m = m_h[i], pi = pi_h[i], chi = chi_h[i];
        float mu = (1.0f - pi) * m;
        float rho = (1.0f - pi) * (chi + m * m);
        g_mu_h[i] = mu;
        g_d_h[i]  = rho - mu * mu;
    }
    for (int i = idx; i < (B_DIM * H_DIM) / 2; i += stride)
        reinterpret_cast<uint32_t*>(g_hA)[i] = 0u;
    for (int i = idx; i < NB * 32; i += stride)
        g_flags[i] = 0u;
}

// ---------------- prep_x ----------------
__global__ void prep_x_kernel(const float* __restrict__ x)
{
    int idx = blockIdx.x * blockDim.x + threadIdx.x;
    int stride = gridDim.x * blockDim.x;
    const int N = S_LEN * B_DIM * I_DIM;
    for (int i = idx; i < N; i += stride) {
        int k = i & (I_DIM - 1);
        int m = i >> 9;
        float v = x[i];
        int p = (k & ~7) | kperm(k & 7);
        int o = (m << 9) | p;
        g_xb[o] = rnaf(v);
        g_xq[o] = rnaf(v * v);
    }
}

// ---------------- phase B: xproj via tf32 mma.sync ----------------
#define XP_SMEM (96 * 1024)

__global__ void __launch_bounds__(256, 2) xproj_kernel(const float* __restrict__ eps_in,
                                                       float* __restrict__ out)
{
    extern __shared__ float sm[];
    float* xs  = sm;
    float* xq  = sm + 8192;
    float* wmu = sm + 16384;
    float* wd  = sm + 20480;

    const int tid  = threadIdx.x;
    const int warp = tid >> 5, lane = tid & 31;
    const int gid = lane >> 2, tig = lane & 3;
    const int n_base = blockIdx.x * 64;
    const int m_base = blockIdx.y * 128;
    const int mg = (warp & 3) * 32;
    const int nh = (warp >> 2) * 32;

    float cG[2][4][4] = {}, cD[2][4][4] = {};

    for (int ks = 0; ks < 8; ks++) {
        const int k0s = ks * 64;
        for (int i = tid; i < 2048; i += 256) {
            int r = i >> 4, c4 = i & 15;
            int d4 = c4 ^ ((r & 3) << 1);
            *(float4*)&xs[r * 64 + d4 * 4] =
                *(const float4*)&g_xb[(size_t)(m_base + r) * I_DIM + k0s + c4 * 4];
            *(float4*)&xq[r * 64 + d4 * 4] =
                *(const float4*)&g_xq[(size_t)(m_base + r) * I_DIM + k0s + c4 * 4];
        }
        for (int i = tid; i < 4096; i += 256) {
            int k = i >> 6, n = i & 63;
            int ck = k >> 3, j = k & 7, tk = j & 3, pr = j >> 2;
            int pos = ((ck * 4 + tk) * 64 + (n ^ (tk << 2))) * 2 + pr;
            wmu[pos] = g_mu_in[(size_t)(k0s + k) * H_DIM + n_base + n];
            wd [pos] = g_d_in [(size_t)(k0s + k) * H_DIM + n_base + n];
        }
        __syncthreads();

#pragma unroll
        for (int c = 0; c < 8; c++) {
            uint32_t ax[2][4], aq[2][4];
#pragma unroll
            for (int t = 0; t < 2; t++) {
                int r0 = mg + t * 16 + gid;
                int r1 = r0 + 8;
                float2 f0 = *(float2*)&xs[r0 * 64 + ((c * 4 + tig) ^ ((r0 & 3) << 2)) * 2];
                float2 f1 = *(float2*)&xs[r1 * 64 + ((c * 4 + tig) ^ ((r1 & 3) << 2)) * 2];
                ax[t][0] = __float_as_uint(f0.x); ax[t][2] = __float_as_uint(f0.y);
                ax[t][1] = __float_as_uint(f1.x); ax[t][3] = __float_as_uint(f1.y);
                float2 q0 = *(float2*)&xq[r0 * 64 + ((c * 4 + tig) ^ ((r0 & 3) << 2)) * 2];
                float2 q1 = *(float2*)&xq[r1 * 64 + ((c * 4 + tig) ^ ((r1 & 3) << 2)) * 2];
                aq[t][0] = __float_as_uint(q0.x); aq[t][2] = __float_as_uint(q0.y);
                aq[t][1] = __float_as_uint(q1.x); aq[t][3] = __float_as_uint(q1.y);
            }
#pragma unroll
            for (int nt = 0; nt < 4; nt++) {
                int nl = nh + nt * 8 + gid;
                float2 bm = *(float2*)&wmu[((c * 4 + tig) * 64 + (nl ^ (tig << 2))) * 2];
                float2 bdv = *(float2*)&wd [((c * 4 + tig) * 64 + (nl ^ (tig << 2))) * 2];
                uint32_t bm0 = __float_as_uint(bm.x),  bm1 = __float_as_uint(bm.y);
                uint32_t bd0 = __float_as_uint(bdv.x), bd1 = __float_as_uint(bdv.y);
#pragma unroll
                for (int t = 0; t < 2; t++) {
                    mma8(cG[t][nt], ax[t][0], ax[t][1], ax[t][2], ax[t][3], bm0, bm1);
                    mma8(cD[t][nt], aq[t][0], aq[t][1], aq[t][2], aq[t][3], bd0, bd1);
                }
            }
        }
        __syncthreads();
    }

#pragma unroll
    for (int t = 0; t < 2; t++)
#pragma unroll
    for (int nt = 0; nt < 4; nt++) {
        int n = n_base + nh + nt * 8 + tig * 2;
#pragma unroll
        for (int half = 0; half < 2; half++) {
            int m = m_base + mg + t * 16 + gid + half * 8;
            size_t off = (size_t)m * H_DIM + n;
            float2 e = *(const float2*)(eps_in + off);
            float2 o;
            o.x = cG[t][nt][half * 2]     + e.x * sqrtf(cD[t][nt][half * 2]     + EPS_C);
            o.y = cG[t][nt][half * 2 + 1] + e.y * sqrtf(cD[t][nt][half * 2 + 1] + EPS_C);
            *(float2*)(out + off) = o;
        }
    }
}

// ---------------- phase C: persistent scan via bf16 mma.m16n8k16 ----------------
// Distributed flag barrier: each block release-stores its own flag (own 128B
// line); 128 threads per block each acquire-poll one flag. No serialized atomics.
#define SC_SMEM (131072)

__global__ void __launch_bounds__(512, 1) scan_kernel(const float* __restrict__ eps_h,
                                                      float* __restrict__ out,
                                                      int write_last)
{
    extern __shared__ char smc[];
    u64* whi = (u64*)smc;                    // [64 cg][4 tig][16 n] u64 = 32KB
    u64* wlo = whi + 4096;
    u64* wdd = wlo + 4096;
    float* pG = (float*)(wdd + 4096);        // [8 ke][32 b][16 n] = 16KB
    float* pD = pG + 4096;

    const int tid  = threadIdx.x;
    const int warp = tid >> 5, lane = tid & 31;
    const int gid = lane >> 2, tig = lane & 3;
    const int n_base = (blockIdx.x >> 1) * 16;
    const int b_base = (blockIdx.x & 1) * 32;
    const int mt = warp & 1, ke = warp >> 1;
    const int bid = blockIdx.x;

    // stage weights once: split mu into hi+lo bf16, d single bf16
    for (int i = tid; i < 4096; i += 512) {
        int cg = i >> 6, tg = (i >> 4) & 3, n = i & 15;
        int sidx = cg * 64 + tg * 16 + ((n + 4 * tg) & 15);
        int k0 = cg * 16 + 2 * tg;
        int gn = n_base + n;
        float m0 = g_mu_h[(size_t)k0 * H_DIM + gn];
        float m1 = g_mu_h[(size_t)(k0 + 1) * H_DIM + gn];
        float m8 = g_mu_h[(size_t)(k0 + 8) * H_DIM + gn];
        float m9 = g_mu_h[(size_t)(k0 + 9) * H_DIM + gn];
        float h0 = __bfloat162float(__float2bfloat16(m0));
        float h1 = __bfloat162float(__float2bfloat16(m1));
        float h8 = __bfloat162float(__float2bfloat16(m8));
        float h9 = __bfloat162float(__float2bfloat16(m9));
        whi[sidx] = (u64)bpack(h0, h1) | ((u64)bpack(h8, h9) << 32);
        wlo[sidx] = (u64)bpack(m0 - h0, m1 - h1) | ((u64)bpack(m8 - h8, m9 - h9) << 32);
        float d0 = g_d_h[(size_t)k0 * H_DIM + gn];
        float d1 = g_d_h[(size_t)(k0 + 1) * H_DIM + gn];
        float d8 = g_d_h[(size_t)(k0 + 8) * H_DIM + gn];
        float d9 = g_d_h[(size_t)(k0 + 9) * H_DIM + gn];
        wdd[sidx] = (u64)bpack(d0, d1) | ((u64)bpack(d8, d9) << 32);
    }

    const int r0 = b_base + mt * 16 + gid;
    const int eb = tid >> 4;                 // 0..31
    const int en = tid & 15;                 // 0..15
    const int gbrow = b_base + eb;
    const int ncol = n_base + en;
    const int hoff = gbrow * H_DIM + (ncol & ~15) + kperm16(ncol & 15);

    // prefetch step-0 epilogue operands
    size_t toff = (size_t)gbrow * H_DIM + ncol;
    float epre = __ldg(eps_h + toff);
    float xpre = __ldcg(out + toff);
    __syncthreads();

    for (int t = 0; t < S_LEN; t++) {
        const __nv_bfloat16* hsrc = (t & 1) ? g_hB : g_hA;
        __nv_bfloat16* hdst = (t & 1) ? g_hA : g_hB;

        // ---- preload all h fragments (16 independent LDG.64, full MLP) ----
        const __nv_bfloat16* hr0 = hsrc + (size_t)r0 * H_DIM + ke * 128 + tig * 4;
        const __nv_bfloat16* hr1 = hr0 + 8 * H_DIM;
        uint2 v0[8], v1[8];
#pragma unroll
        for (int c = 0; c < 8; c++) {
            v0[c] = __ldcg((const uint2*)(hr0 + c * 16));
            v1[c] = __ldcg((const uint2*)(hr1 + c * 16));
        }

        float cG[2][4] = {}, cD[2][4] = {};
#pragma unroll
        for (int c = 0; c < 8; c++) {
            const int cg = ke * 8 + c;
            uint32_t a0 = v0[c].x, a2 = v0[c].y;
            uint32_t a1 = v1[c].x, a3 = v1[c].y;
            uint32_t q0 = mulbf2(a0, a0), q2 = mulbf2(a2, a2);
            uint32_t q1 = mulbf2(a1, a1), q3 = mulbf2(a3, a3);
#pragma unroll
            for (int nt = 0; nt < 2; nt++) {
                int nl = nt * 8 + gid;
                int sidx = cg * 64 + tig * 16 + ((nl + 4 * tig) & 15);
                u64 wh = whi[sidx], wl = wlo[sidx], wv = wdd[sidx];
                mma16(cG[nt], a0, a1, a2, a3, (uint32_t)wh, (uint32_t)(wh >> 32));
                mma16(cG[nt], a0, a1, a2, a3, (uint32_t)wl, (uint32_t)(wl >> 32));
                mma16(cD[nt], q0, q1, q2, q3, (uint32_t)wv, (uint32_t)(wv >> 32));
            }
        }

        // partials -> smem
        const int rowa = ke * 32 + mt * 16 + gid;
#pragma unroll
        for (int nt = 0; nt < 2; nt++) {
            int colb = nt * 8 + tig * 2;
            *(float2*)&pG[rowa * 16 + colb]       = make_float2(cG[nt][0], cG[nt][1]);
            *(float2*)&pG[(rowa + 8) * 16 + colb] = make_float2(cG[nt][2], cG[nt][3]);
            *(float2*)&pD[rowa * 16 + colb]       = make_float2(cD[nt][0], cD[nt][1]);
            *(float2*)&pD[(rowa + 8) * 16 + colb] = make_float2(cD[nt][2], cD[nt][3]);
        }
        __syncthreads();

        // reduce 8 k-slices + epilogue (1 output per thread)
        float G = 0.0f, D = 0.0f;
#pragma unroll
        for (int q = 0; q < 8; q++) {
            G += pG[(q * 32 + eb) * 16 + en];
            D += pD[(q * 32 + eb) * 16 + en];
        }
        float h = tanh_ap(G + epre * sqrtf(D + EPS_C) + xpre);
        hdst[hoff] = __float2bfloat16(h);    // h transport: the only critical store

        if (t == S_LEN - 1) {
            out[toff] = h;
            if (write_last)
                out[(size_t)S_LEN * B_DIM * H_DIM + gbrow * H_DIM + ncol] = h;
            break;
        }

        // ---- distributed flag barrier ----
        __syncthreads();                      // all h stores done (block edge)
        const unsigned target = (unsigned)(t + 1);
        if (tid == 0)
            st_release(&g_flags[bid * 32], target);
        // hidden work: current out-store + next-step operand prefetch
        out[toff] = h;
        toff = (size_t)((t + 1) * B_DIM + gbrow) * H_DIM + ncol;
        epre = __ldg(eps_h + toff);
        xpre = __ldcg(out + toff);
        if (tid < NB) {
            while (ld_acquire(&g_flags[tid * 32]) < target) { }
        }
        __syncthreads();
    }
}

// ---------------- launch ----------------
extern "C" void kernel_launch(void* const* d_in, const int* in_sizes, int n_in,
                              void* d_out, int out_size)
{
    (void)in_sizes; (void)n_in;
    const float* x      = (const float*)d_in[0];
    const float* eps_in = (const float*)d_in[1];
    const float* eps_h  = (const float*)d_in[2];
    const float* m_in   = (const float*)d_in[3];
    const float* pi_in  = (const float*)d_in[4];
    const float* chi_in = (const float*)d_in[5];
    const float* m_h    = (const float*)d_in[6];
    const float* pi_h   = (const float*)d_in[7];
    const float* chi_h  = (const float*)d_in[8];
    float* out = (float*)d_out;

    prep_kernel<<<512, 256>>>(m_in, pi_in, chi_in, m_h, pi_h, chi_h);
    prep_x_kernel<<<8192, 256>>>(x);

    cudaFuncSetAttribute(xproj_kernel, cudaFuncAttributeMaxDynamicSharedMemorySize, XP_SMEM);
    dim3 gB(H_DIM / 64, (S_LEN * B_DIM) / 128);
    xproj_kernel<<<gB, 256, XP_SMEM>>>(eps_in, out);

    cudaFuncSetAttribute(scan_kernel, cudaFuncAttributeMaxDynamicSharedMemorySize, SC_SMEM);
    int write_last = (out_size >= S_LEN * B_DIM * H_DIM + B_DIM * H_DIM) ? 1 : 0;
    scan_kernel<<<NB, 512, SC_SMEM>>>(eps_h, out, write_last);
}

// round 10
// speedup vs baseline: 4.1841x; 1.0133x over previous
#include <cuda_runtime.h>
#include <cuda_bf16.h>
#include <cstdint>

#define S_LEN 512
#define B_DIM 64
#define I_DIM 512
#define H_DIM 1024
#define EPS_C 1e-10f
#define NB    128

typedef unsigned long long u64;

// ---------------- tf32 helpers (xproj) ----------------
__device__ __forceinline__ uint32_t rna(float f) {
    uint32_t r; asm("cvt.rna.tf32.f32 %0, %1;" : "=r"(r) : "f"(f)); return r;
}
__device__ __forceinline__ float rnaf(float f) { return __uint_as_float(rna(f)); }

__device__ __forceinline__ void mma8(float* c, uint32_t a0, uint32_t a1, uint32_t a2, uint32_t a3,
                                     uint32_t b0, uint32_t b1) {
    asm volatile("mma.sync.aligned.m16n8k8.row.col.f32.tf32.tf32.f32 "
        "{%0,%1,%2,%3}, {%4,%5,%6,%7}, {%8,%9}, {%0,%1,%2,%3};"
        : "+f"(c[0]), "+f"(c[1]), "+f"(c[2]), "+f"(c[3])
        : "r"(a0), "r"(a1), "r"(a2), "r"(a3), "r"(b0), "r"(b1));
}

// ---------------- bf16 helpers (scan) ----------------
__device__ __forceinline__ void mma16(float* c, uint32_t a0, uint32_t a1, uint32_t a2, uint32_t a3,
                                      uint32_t b0, uint32_t b1) {
    asm volatile("mma.sync.aligned.m16n8k16.row.col.f32.bf16.bf16.f32 "
        "{%0,%1,%2,%3}, {%4,%5,%6,%7}, {%8,%9}, {%0,%1,%2,%3};"
        : "+f"(c[0]), "+f"(c[1]), "+f"(c[2]), "+f"(c[3])
        : "r"(a0), "r"(a1), "r"(a2), "r"(a3), "r"(b0), "r"(b1));
}
__device__ __forceinline__ uint32_t mulbf2(uint32_t a, uint32_t b) {
    uint32_t d; asm("mul.rn.bf16x2 %0, %1, %2;" : "=r"(d) : "r"(a), "r"(b)); return d;
}
__device__ __forceinline__ uint32_t bpack(float lo, float hi) {
    __nv_bfloat162 t = __floats2bfloat162_rn(lo, hi);   // .x = low half
    return *reinterpret_cast<uint32_t*>(&t);
}
__device__ __forceinline__ float tanh_ap(float x) {
    float y; asm("tanh.approx.f32 %0, %1;" : "=f"(y) : "f"(x)); return y;
}

// k-permutations
__device__ __forceinline__ int kperm(int j)  { return ((j & 3) << 1) | (j >> 2); }
__device__ __forceinline__ int kperm16(int j) {   // order [0,1,8,9,2,3,10,11,...]
    return (((j & 7) >> 1) << 2) | (((j >> 3) & 1) << 1) | (j & 1);
}

// ---------------- scoped atomics for the grid barrier ----------------
__device__ __forceinline__ unsigned ld_acquire(const unsigned* p) {
    unsigned v;
    asm volatile("ld.acquire.gpu.u32 %0, [%1];" : "=r"(v) : "l"(p) : "memory");
    return v;
}
__device__ __forceinline__ void st_release(unsigned* p, unsigned v) {
    asm volatile("st.release.gpu.u32 [%0], %1;" :: "l"(p), "r"(v) : "memory");
}

// ---------------- device scratch ----------------
__device__ float g_mu_in[I_DIM * H_DIM];   // tf32-rounded, [k][n]
__device__ float g_d_in [I_DIM * H_DIM];
__device__ float g_mu_h [H_DIM * H_DIM];   // fp32, [k][n] (bf16 at staging)
__device__ float g_d_h  [H_DIM * H_DIM];
__device__ __align__(16) float g_xb[S_LEN * B_DIM * I_DIM];  // tf32(x), k-permuted
__device__ __align__(16) float g_xq[S_LEN * B_DIM * I_DIM];  // tf32(x*x), k-permuted
__device__ __align__(16) __nv_bfloat16 g_hA[B_DIM * H_DIM];  // bf16 h transport, k16-permuted
__device__ __align__(16) __nv_bfloat16 g_hB[B_DIM * H_DIM];
__device__ __align__(128) unsigned g_flags[NB * 32];  // 1 flag per 128B line, monotonic

// ---------------- prep ----------------
__global__ void prep_kernel(const float* __restrict__ m_in, const float* __restrict__ pi_in,
                            const float* __restrict__ chi_in,
                            const float* __restrict__ m_h, const float* __restrict__ pi_h,
                            const float* __restrict__ chi_h)
{
    int idx = blockIdx.x * blockDim.x + threadIdx.x;
    int stride = gridDim.x * blockDim.x;

    for (int i = idx; i < H_DIM * H_DIM; i += stride) {
        if (i < I_DIM * H_DIM) {
            float m = m_in[i], pi = pi_in[i], chi = chi_in[i];
            float mu = (1.0f - pi) * m;
            float rho = (1.0f - pi) * (chi + m * m);
            g_mu_in[i] = rnaf(mu);
            g_d_in[i]  = rnaf(rho - mu * mu);
        }
        float m = m_h[i], pi = pi_h[i], chi = chi_h[i];
        float mu = (1.0f - pi) * m;
        float rho = (1.0f - pi) * (chi + m * m);
        g_mu_h[i] = mu;
        g_d_h[i]  = rho - mu * mu;
    }
    for (int i = idx; i < (B_DIM * H_DIM) / 2; i += stride)
        reinterpret_cast<uint32_t*>(g_hA)[i] = 0u;
    for (int i = idx; i < NB * 32; i += stride)
        g_flags[i] = 0u;
}

// ---------------- prep_x ----------------
__global__ void prep_x_kernel(const float* __restrict__ x)
{
    int idx = blockIdx.x * blockDim.x + threadIdx.x;
    int stride = gridDim.x * blockDim.x;
    const int N = S_LEN * B_DIM * I_DIM;
    for (int i = idx; i < N; i += stride) {
        int k = i & (I_DIM - 1);
        int m = i >> 9;
        float v = x[i];
        int p = (k & ~7) | kperm(k & 7);
        int o = (m << 9) | p;
        g_xb[o] = rnaf(v);
        g_xq[o] = rnaf(v * v);
    }
}

// ---------------- phase B: xproj via tf32 mma.sync ----------------
#define XP_SMEM (96 * 1024)

__global__ void __launch_bounds__(256, 2) xproj_kernel(const float* __restrict__ eps_in,
                                                       float* __restrict__ out)
{
    extern __shared__ float sm[];
    float* xs  = sm;
    float* xq  = sm + 8192;
    float* wmu = sm + 16384;
    float* wd  = sm + 20480;

    const int tid  = threadIdx.x;
    const int warp = tid >> 5, lane = tid & 31;
    const int gid = lane >> 2, tig = lane & 3;
    const int n_base = blockIdx.x * 64;
    const int m_base = blockIdx.y * 128;
    const int mg = (warp & 3) * 32;
    const int nh = (warp >> 2) * 32;

    float cG[2][4][4] = {}, cD[2][4][4] = {};

    for (int ks = 0; ks < 8; ks++) {
        const int k0s = ks * 64;
        for (int i = tid; i < 2048; i += 256) {
            int r = i >> 4, c4 = i & 15;
            int d4 = c4 ^ ((r & 3) << 1);
            *(float4*)&xs[r * 64 + d4 * 4] =
                *(const float4*)&g_xb[(size_t)(m_base + r) * I_DIM + k0s + c4 * 4];
            *(float4*)&xq[r * 64 + d4 * 4] =
                *(const float4*)&g_xq[(size_t)(m_base + r) * I_DIM + k0s + c4 * 4];
        }
        for (int i = tid; i < 4096; i += 256) {
            int k = i >> 6, n = i & 63;
            int ck = k >> 3, j = k & 7, tk = j & 3, pr = j >> 2;
            int pos = ((ck * 4 + tk) * 64 + (n ^ (tk << 2))) * 2 + pr;
            wmu[pos] = g_mu_in[(size_t)(k0s + k) * H_DIM + n_base + n];
            wd [pos] = g_d_in [(size_t)(k0s + k) * H_DIM + n_base + n];
        }
        __syncthreads();

#pragma unroll
        for (int c = 0; c < 8; c++) {
            uint32_t ax[2][4], aq[2][4];
#pragma unroll
            for (int t = 0; t < 2; t++) {
                int r0 = mg + t * 16 + gid;
                int r1 = r0 + 8;
                float2 f0 = *(float2*)&xs[r0 * 64 + ((c * 4 + tig) ^ ((r0 & 3) << 2)) * 2];
                float2 f1 = *(float2*)&xs[r1 * 64 + ((c * 4 + tig) ^ ((r1 & 3) << 2)) * 2];
                ax[t][0] = __float_as_uint(f0.x); ax[t][2] = __float_as_uint(f0.y);
                ax[t][1] = __float_as_uint(f1.x); ax[t][3] = __float_as_uint(f1.y);
                float2 q0 = *(float2*)&xq[r0 * 64 + ((c * 4 + tig) ^ ((r0 & 3) << 2)) * 2];
                float2 q1 = *(float2*)&xq[r1 * 64 + ((c * 4 + tig) ^ ((r1 & 3) << 2)) * 2];
                aq[t][0] = __float_as_uint(q0.x); aq[t][2] = __float_as_uint(q0.y);
                aq[t][1] = __float_as_uint(q1.x); aq[t][3] = __float_as_uint(q1.y);
            }
#pragma unroll
            for (int nt = 0; nt < 4; nt++) {
                int nl = nh + nt * 8 + gid;
                float2 bm = *(float2*)&wmu[((c * 4 + tig) * 64 + (nl ^ (tig << 2))) * 2];
                float2 bdv = *(float2*)&wd [((c * 4 + tig) * 64 + (nl ^ (tig << 2))) * 2];
                uint32_t bm0 = __float_as_uint(bm.x),  bm1 = __float_as_uint(bm.y);
                uint32_t bd0 = __float_as_uint(bdv.x), bd1 = __float_as_uint(bdv.y);
#pragma unroll
                for (int t = 0; t < 2; t++) {
                    mma8(cG[t][nt], ax[t][0], ax[t][1], ax[t][2], ax[t][3], bm0, bm1);
                    mma8(cD[t][nt], aq[t][0], aq[t][1], aq[t][2], aq[t][3], bd0, bd1);
                }
            }
        }
        __syncthreads();
    }

#pragma unroll
    for (int t = 0; t < 2; t++)
#pragma unroll
    for (int nt = 0; nt < 4; nt++) {
        int n = n_base + nh + nt * 8 + tig * 2;
#pragma unroll
        for (int half = 0; half < 2; half++) {
            int m = m_base + mg + t * 16 + gid + half * 8;
            size_t off = (size_t)m * H_DIM + n;
            float2 e = *(const float2*)(eps_in + off);
            float2 o;
            o.x = cG[t][nt][half * 2]     + e.x * sqrtf(cD[t][nt][half * 2]     + EPS_C);
            o.y = cG[t][nt][half * 2 + 1] + e.y * sqrtf(cD[t][nt][half * 2 + 1] + EPS_C);
            *(float2*)(out + off) = o;
        }
    }
}

// ---------------- phase C: persistent scan via bf16 mma.m16n8k16 ----------------
// Weights single bf16 (mu & d) packed per (cg,nt) into one uint4 -> one LDS.128
// feeds both MMAs. Two independent 64-block barriers (one per batch half).
#define SC_SMEM (98304)

__global__ void __launch_bounds__(512, 1) scan_kernel(const float* __restrict__ eps_h,
                                                      float* __restrict__ out,
                                                      int write_last)
{
    extern __shared__ char smc[];
    uint4* wpk = (uint4*)smc;                // [64 cg][4 tig][16 n] uint4 = 64KB
    float* pG = (float*)(smc + 65536);       // [8 ke][32 b][16 n] = 16KB
    float* pD = pG + 4096;

    const int tid  = threadIdx.x;
    const int warp = tid >> 5, lane = tid & 31;
    const int gid = lane >> 2, tig = lane & 3;
    const int n_base = (blockIdx.x >> 1) * 16;
    const int b_base = (blockIdx.x & 1) * 32;
    const int half = blockIdx.x & 1;
    const int mt = warp & 1, ke = warp >> 1;
    const int bid = blockIdx.x;

    // stage weights once: mu and d single bf16, packed {mu01, mu89, d01, d89}
    for (int i = tid; i < 4096; i += 512) {
        int cg = i >> 6, tg = (i >> 4) & 3, n = i & 15;
        int sidx = cg * 64 + tg * 16 + ((n + 2 * tg) & 15);
        int k0 = cg * 16 + 2 * tg;
        int gn = n_base + n;
        float m0 = g_mu_h[(size_t)k0 * H_DIM + gn];
        float m1 = g_mu_h[(size_t)(k0 + 1) * H_DIM + gn];
        float m8 = g_mu_h[(size_t)(k0 + 8) * H_DIM + gn];
        float m9 = g_mu_h[(size_t)(k0 + 9) * H_DIM + gn];
        float d0 = g_d_h[(size_t)k0 * H_DIM + gn];
        float d1 = g_d_h[(size_t)(k0 + 1) * H_DIM + gn];
        float d8 = g_d_h[(size_t)(k0 + 8) * H_DIM + gn];
        float d9 = g_d_h[(size_t)(k0 + 9) * H_DIM + gn];
        uint4 w;
        w.x = bpack(m0, m1);
        w.y = bpack(m8, m9);
        w.z = bpack(d0, d1);
        w.w = bpack(d8, d9);
        wpk[sidx] = w;
    }

    const int r0 = b_base + mt * 16 + gid;
    const int eb = tid >> 4;                 // 0..31
    const int en = tid & 15;                 // 0..15
    const int gbrow = b_base + eb;
    const int ncol = n_base + en;
    const int hoff = gbrow * H_DIM + (ncol & ~15) + kperm16(ncol & 15);

    // prefetch step-0 epilogue operands
    size_t toff = (size_t)gbrow * H_DIM + ncol;
    float epre = __ldg(eps_h + toff);
    float xpre = __ldcg(out + toff);
    __syncthreads();

    for (int t = 0; t < S_LEN; t++) {
        const __nv_bfloat16* hsrc = (t & 1) ? g_hB : g_hA;
        __nv_bfloat16* hdst = (t & 1) ? g_hA : g_hB;

        // ---- preload all h fragments (16 independent LDG.64, full MLP) ----
        const __nv_bfloat16* hr0 = hsrc + (size_t)r0 * H_DIM + ke * 128 + tig * 4;
        const __nv_bfloat16* hr1 = hr0 + 8 * H_DIM;
        uint2 v0[8], v1[8];
#pragma unroll
        for (int c = 0; c < 8; c++) {
            v0[c] = __ldcg((const uint2*)(hr0 + c * 16));
            v1[c] = __ldcg((const uint2*)(hr1 + c * 16));
        }

        float cG[2][4] = {}, cD[2][4] = {};
#pragma unroll
        for (int c = 0; c < 8; c++) {
            const int cg = ke * 8 + c;
            uint32_t a0 = v0[c].x, a2 = v0[c].y;
            uint32_t a1 = v1[c].x, a3 = v1[c].y;
            uint32_t q0 = mulbf2(a0, a0), q2 = mulbf2(a2, a2);
            uint32_t q1 = mulbf2(a1, a1), q3 = mulbf2(a3, a3);
#pragma unroll
            for (int nt = 0; nt < 2; nt++) {
                int nl = nt * 8 + gid;
                uint4 w = wpk[cg * 64 + tig * 16 + ((nl + 2 * tig) & 15)];
                mma16(cG[nt], a0, a1, a2, a3, w.x, w.y);
                mma16(cD[nt], q0, q1, q2, q3, w.z, w.w);
            }
        }

        // partials -> smem
        const int rowa = ke * 32 + mt * 16 + gid;
#pragma unroll
        for (int nt = 0; nt < 2; nt++) {
            int colb = nt * 8 + tig * 2;
            *(float2*)&pG[rowa * 16 + colb]       = make_float2(cG[nt][0], cG[nt][1]);
            *(float2*)&pG[(rowa + 8) * 16 + colb] = make_float2(cG[nt][2], cG[nt][3]);
            *(float2*)&pD[rowa * 16 + colb]       = make_float2(cD[nt][0], cD[nt][1]);
            *(float2*)&pD[(rowa + 8) * 16 + colb] = make_float2(cD[nt][2], cD[nt][3]);
        }
        __syncthreads();

        // reduce 8 k-slices + epilogue (1 output per thread)
        float G = 0.0f, D = 0.0f;
#pragma unroll
        for (int q = 0; q < 8; q++) {
            G += pG[(q * 32 + eb) * 16 + en];
            D += pD[(q * 32 + eb) * 16 + en];
        }
        float h = tanh_ap(G + epre * sqrtf(D + EPS_C) + xpre);
        hdst[hoff] = __float2bfloat16(h);    // h transport: the only critical store

        if (t == S_LEN - 1) {
            out[toff] = h;
            if (write_last)
                out[(size_t)S_LEN * B_DIM * H_DIM + gbrow * H_DIM + ncol] = h;
            break;
        }

        // ---- distributed flag barrier (per batch-half: 64 blocks) ----
        __syncthreads();                      // all h stores done (block edge)
        const unsigned target = (unsigned)(t + 1);
        if (tid == 0)
            st_release(&g_flags[bid * 32], target);
        // hidden work: current out-store + next-step operand prefetch
        out[toff] = h;
        toff = (size_t)((t + 1) * B_DIM + gbrow) * H_DIM + ncol;
        epre = __ldg(eps_h + toff);
        xpre = __ldcg(out + toff);
        if (tid < 64) {
            while (ld_acquire(&g_flags[(tid * 2 + half) * 32]) < target) { }
        }
        __syncthreads();
    }
}

// ---------------- launch ----------------
extern "C" void kernel_launch(void* const* d_in, const int* in_sizes, int n_in,
                              void* d_out, int out_size)
{
    (void)in_sizes; (void)n_in;
    const float* x      = (const float*)d_in[0];
    const float* eps_in = (const float*)d_in[1];
    const float* eps_h  = (const float*)d_in[2];
    const float* m_in   = (const float*)d_in[3];
    const float* pi_in  = (const float*)d_in[4];
    const float* chi_in = (const float*)d_in[5];
    const float* m_h    = (const float*)d_in[6];
    const float* pi_h   = (const float*)d_in[7];
    const float* chi_h  = (const float*)d_in[8];
    float* out = (float*)d_out;

    prep_kernel<<<512, 256>>>(m_in, pi_in, chi_in, m_h, pi_h, chi_h);
    prep_x_kernel<<<8192, 256>>>(x);

    cudaFuncSetAttribute(xproj_kernel, cudaFuncAttributeMaxDynamicSharedMemorySize, XP_SMEM);
    dim3 gB(H_DIM / 64, (S_LEN * B_DIM) / 128);
    xproj_kernel<<<gB, 256, XP_SMEM>>>(eps_in, out);

    cudaFuncSetAttribute(scan_kernel, cudaFuncAttributeMaxDynamicSharedMemorySize, SC_SMEM);
    int write_last = (out_size >= S_LEN * B_DIM * H_DIM + B_DIM * H_DIM) ? 1 : 0;
    scan_kernel<<<NB, 512, SC_SMEM>>>(eps_h, out, write_last);
}

// round 11
// speedup vs baseline: 4.3183x; 1.0321x over previous
#include <cuda_runtime.h>
#include <cuda_bf16.h>
#include <cstdint>

#define S_LEN 512
#define B_DIM 64
#define I_DIM 512
#define H_DIM 1024
#define EPS_C 1e-10f
#define NB    128

typedef unsigned long long u64;

// ---------------- bf16 helpers ----------------
__device__ __forceinline__ void mma16(float* c, uint32_t a0, uint32_t a1, uint32_t a2, uint32_t a3,
                                      uint32_t b0, uint32_t b1) {
    asm volatile("mma.sync.aligned.m16n8k16.row.col.f32.bf16.bf16.f32 "
        "{%0,%1,%2,%3}, {%4,%5,%6,%7}, {%8,%9}, {%0,%1,%2,%3};"
        : "+f"(c[0]), "+f"(c[1]), "+f"(c[2]), "+f"(c[3])
        : "r"(a0), "r"(a1), "r"(a2), "r"(a3), "r"(b0), "r"(b1));
}
__device__ __forceinline__ uint32_t mulbf2(uint32_t a, uint32_t b) {
    uint32_t d; asm("mul.rn.bf16x2 %0, %1, %2;" : "=r"(d) : "r"(a), "r"(b)); return d;
}
__device__ __forceinline__ uint32_t bpack(float lo, float hi) {
    __nv_bfloat162 t = __floats2bfloat162_rn(lo, hi);   // .x = low half
    return *reinterpret_cast<uint32_t*>(&t);
}
__device__ __forceinline__ float tanh_ap(float x) {
    float y; asm("tanh.approx.f32 %0, %1;" : "=f"(y) : "f"(x)); return y;
}

// bf16 k16-group permutation: original j -> position; order [0,1,8,9,2,3,10,11,...]
__device__ __forceinline__ int kperm16(int j) {
    return (((j & 7) >> 1) << 2) | (((j >> 3) & 1) << 1) | (j & 1);
}

// ---------------- scoped atomics for the grid barrier ----------------
__device__ __forceinline__ unsigned ld_acquire(const unsigned* p) {
    unsigned v;
    asm volatile("ld.acquire.gpu.u32 %0, [%1];" : "=r"(v) : "l"(p) : "memory");
    return v;
}
__device__ __forceinline__ void st_release(unsigned* p, unsigned v) {
    asm volatile("st.release.gpu.u32 [%0], %1;" :: "l"(p), "r"(v) : "memory");
}

// ---------------- device scratch ----------------
__device__ float g_mu_h[H_DIM * H_DIM];    // fp32, [k][n] (bf16 at scan staging)
__device__ float g_d_h [H_DIM * H_DIM];
// input-layer weights pair-packed bf16x2: index = kp * H_DIM + n, kp = k/2 (k, k+1)
__device__ uint32_t g_pmh[(I_DIM / 2) * H_DIM];   // mu_in hi split
__device__ uint32_t g_pml[(I_DIM / 2) * H_DIM];   // mu_in lo split
__device__ uint32_t g_pd [(I_DIM / 2) * H_DIM];   // d_in single bf16
__device__ __align__(16) __nv_bfloat16 g_xb16[S_LEN * B_DIM * I_DIM];  // bf16(x), k16-permuted
__device__ __align__(16) __nv_bfloat16 g_xq16[S_LEN * B_DIM * I_DIM];  // bf16(x*x), k16-permuted
__device__ __align__(16) __nv_bfloat16 g_hA[B_DIM * H_DIM];  // bf16 h transport, k16-permuted
__device__ __align__(16) __nv_bfloat16 g_hB[B_DIM * H_DIM];
__device__ __align__(128) unsigned g_flags[NB * 32];  // 1 flag per 128B line, monotonic

// ---------------- prep ----------------
__global__ void prep_kernel(const float* __restrict__ m_in, const float* __restrict__ pi_in,
                            const float* __restrict__ chi_in,
                            const float* __restrict__ m_h, const float* __restrict__ pi_h,
                            const float* __restrict__ chi_h)
{
    int idx = blockIdx.x * blockDim.x + threadIdx.x;
    int stride = gridDim.x * blockDim.x;

    // hidden weights: fp32 effective params
    for (int i = idx; i < H_DIM * H_DIM; i += stride) {
        float m = m_h[i], pi = pi_h[i], chi = chi_h[i];
        float mu = (1.0f - pi) * m;
        float rho = (1.0f - pi) * (chi + m * m);
        g_mu_h[i] = mu;
        g_d_h[i]  = rho - mu * mu;
    }
    // input weights: pair-packed bf16 (hi/lo split for mu, single for d)
    for (int i = idx; i < (I_DIM / 2) * H_DIM; i += stride) {
        int kp = i >> 10, n = i & (H_DIM - 1);
        int i0 = (2 * kp) * H_DIM + n;
        int i1 = i0 + H_DIM;
        float m0 = m_in[i0], p0 = pi_in[i0], c0 = chi_in[i0];
        float m1 = m_in[i1], p1 = pi_in[i1], c1 = chi_in[i1];
        float mu0 = (1.0f - p0) * m0, mu1 = (1.0f - p1) * m1;
        float d0 = (1.0f - p0) * (c0 + m0 * m0) - mu0 * mu0;
        float d1 = (1.0f - p1) * (c1 + m1 * m1) - mu1 * mu1;
        float h0 = __bfloat162float(__float2bfloat16(mu0));
        float h1 = __bfloat162float(__float2bfloat16(mu1));
        g_pmh[i] = bpack(h0, h1);
        g_pml[i] = bpack(mu0 - h0, mu1 - h1);
        g_pd [i] = bpack(d0, d1);
    }
    for (int i = idx; i < (B_DIM * H_DIM) / 2; i += stride)
        reinterpret_cast<uint32_t*>(g_hA)[i] = 0u;
    for (int i = idx; i < NB * 32; i += stride)
        g_flags[i] = 0u;
}

// ---------------- prep_x: bf16(x), bf16(x^2), k16-permuted ----------------
__global__ void prep_x_kernel(const float* __restrict__ x)
{
    int idx = blockIdx.x * blockDim.x + threadIdx.x;
    int stride = gridDim.x * blockDim.x;
    const int N = S_LEN * B_DIM * I_DIM;
    for (int i = idx; i < N; i += stride) {
        int k = i & (I_DIM - 1);
        int m = i >> 9;
        float v = x[i];
        int p = (k & ~15) | kperm16(k & 15);
        int o = (m << 9) | p;
        g_xb16[o] = __float2bfloat16(v);
        g_xq16[o] = __float2bfloat16(v * v);
    }
}

// ---------------- phase B: xproj via bf16 mma.m16n8k16 ----------------
// Block = 128m x 64n, 256 thr, 8 warps (4 m-groups x 2 n-halves), warp tile 32m x 32n.
// K staged in chunks of 64. G = x @ (mu_hi + mu_lo) (2 MMAs), D2 = x^2 @ d (1 MMA).
// smem: xs/xq bf16 [128 rows][128B] granule-swizzled; weights packed per (cg,tg,n).
#define XP_SMEM (57344)

__global__ void __launch_bounds__(256, 2) xproj_kernel(const float* __restrict__ eps_in,
                                                       float* __restrict__ out)
{
    extern __shared__ char smx[];
    char* xs = smx;                           // 16KB
    char* xq = smx + 16384;                   // 16KB
    uint4* w4x = (uint4*)(smx + 32768);       // [4 cg][4 tg][64 n] {mhi0,mhi1,mlo0,mlo1} 16KB
    uint2* wdx = (uint2*)(smx + 49152);       // [4 cg][4 tg][64 n] {d0,d1} 8KB

    const int tid  = threadIdx.x;
    const int warp = tid >> 5, lane = tid & 31;
    const int gid = lane >> 2, tig = lane & 3;
    const int n_base = blockIdx.x * 64;
    const int m_base = blockIdx.y * 128;
    const int mg = (warp & 3) * 32;
    const int nh = (warp >> 2) * 32;

    float cG[2][4][4] = {}, cD[2][4][4] = {};

    for (int ks = 0; ks < 8; ks++) {
        // stage x / x^2 chunk (raw 16B units with row swizzle)
        for (int i = tid; i < 1024; i += 256) {
            int r = i >> 3, u = i & 7;
            int up = u ^ ((r & 3) << 1);
            const char* src = (const char*)(g_xb16 + (size_t)(m_base + r) * I_DIM + ks * 64) + u * 16;
            const char* srq = (const char*)(g_xq16 + (size_t)(m_base + r) * I_DIM + ks * 64) + u * 16;
            *(uint4*)(xs + r * 128 + up * 16) = *(const uint4*)src;
            *(uint4*)(xq + r * 128 + up * 16) = *(const uint4*)srq;
        }
        // stage weights (pair-packed source, bank-rotated dest)
        for (int i = tid; i < 1024; i += 256) {
            int cg = i >> 8, tg = (i >> 6) & 3, n = i & 63;
            int sidx = (cg * 4 + tg) * 64 + ((n + 2 * tg) & 63);
            int kpA = (ks * 4 + cg) * 8 + tg;
            int kpB = kpA + 4;
            int gn = n_base + n;
            uint4 w;
            w.x = g_pmh[kpA * H_DIM + gn];
            w.y = g_pmh[kpB * H_DIM + gn];
            w.z = g_pml[kpA * H_DIM + gn];
            w.w = g_pml[kpB * H_DIM + gn];
            w4x[sidx] = w;
            wdx[sidx] = make_uint2(g_pd[kpA * H_DIM + gn], g_pd[kpB * H_DIM + gn]);
        }
        __syncthreads();

#pragma unroll
        for (int c = 0; c < 4; c++) {
            uint2 ax[2][2], aq[2][2];    // [mt][row-half: r0, r1]
#pragma unroll
            for (int mt = 0; mt < 2; mt++) {
                int r0 = mg + mt * 16 + gid;
                int r1 = r0 + 8;
                int g0 = (c * 4 + tig) ^ ((r0 & 3) << 2);
                int g1 = (c * 4 + tig) ^ ((r1 & 3) << 2);
                ax[mt][0] = *(const uint2*)(xs + r0 * 128 + g0 * 8);
                ax[mt][1] = *(const uint2*)(xs + r1 * 128 + g1 * 8);
                aq[mt][0] = *(const uint2*)(xq + r0 * 128 + g0 * 8);
                aq[mt][1] = *(const uint2*)(xq + r1 * 128 + g1 * 8);
            }
#pragma unroll
            for (int nt = 0; nt < 4; nt++) {
                int nl = nh + nt * 8 + gid;
                int widx = (c * 4 + tig) * 64 + ((nl + 2 * tig) & 63);
                uint4 w = w4x[widx];
                uint2 wd = wdx[widx];
#pragma unroll
                for (int mt = 0; mt < 2; mt++) {
                    mma16(cG[mt][nt], ax[mt][0].x, ax[mt][1].x, ax[mt][0].y, ax[mt][1].y, w.x, w.y);
                    mma16(cG[mt][nt], ax[mt][0].x, ax[mt][1].x, ax[mt][0].y, ax[mt][1].y, w.z, w.w);
                    mma16(cD[mt][nt], aq[mt][0].x, aq[mt][1].x, aq[mt][0].y, aq[mt][1].y, wd.x, wd.y);
                }
            }
        }
        __syncthreads();
    }

    // epilogue: out = G + eps * sqrt(D2 + EPS)
#pragma unroll
    for (int mt = 0; mt < 2; mt++)
#pragma unroll
    for (int nt = 0; nt < 4; nt++) {
        int n = n_base + nh + nt * 8 + tig * 2;
#pragma unroll
        for (int half = 0; half < 2; half++) {
            int m = m_base + mg + mt * 16 + gid + half * 8;
            size_t off = (size_t)m * H_DIM + n;
            float2 e = *(const float2*)(eps_in + off);
            float2 o;
            o.x = cG[mt][nt][half * 2]     + e.x * sqrtf(cD[mt][nt][half * 2]     + EPS_C);
            o.y = cG[mt][nt][half * 2 + 1] + e.y * sqrtf(cD[mt][nt][half * 2 + 1] + EPS_C);
            *(float2*)(out + off) = o;
        }
    }
}

// ---------------- phase C: persistent scan via bf16 mma.m16n8k16 (unchanged) ----------------
#define SC_SMEM (98304)

__global__ void __launch_bounds__(512, 1) scan_kernel(const float* __restrict__ eps_h,
                                                      float* __restrict__ out,
                                                      int write_last)
{
    extern __shared__ char smc[];
    uint4* wpk = (uint4*)smc;                // [64 cg][4 tig][16 n] uint4 = 64KB
    float* pG = (float*)(smc + 65536);       // [8 ke][32 b][16 n] = 16KB
    float* pD = pG + 4096;

    const int tid  = threadIdx.x;
    const int warp = tid >> 5, lane = tid & 31;
    const int gid = lane >> 2, tig = lane & 3;
    const int n_base = (blockIdx.x >> 1) * 16;
    const int b_base = (blockIdx.x & 1) * 32;
    const int half = blockIdx.x & 1;
    const int mt = warp & 1, ke = warp >> 1;
    const int bid = blockIdx.x;

    // stage weights once: mu and d single bf16, packed {mu01, mu89, d01, d89}
    for (int i = tid; i < 4096; i += 512) {
        int cg = i >> 6, tg = (i >> 4) & 3, n = i & 15;
        int sidx = cg * 64 + tg * 16 + ((n + 2 * tg) & 15);
        int k0 = cg * 16 + 2 * tg;
        int gn = n_base + n;
        float m0 = g_mu_h[(size_t)k0 * H_DIM + gn];
        float m1 = g_mu_h[(size_t)(k0 + 1) * H_DIM + gn];
        float m8 = g_mu_h[(size_t)(k0 + 8) * H_DIM + gn];
        float m9 = g_mu_h[(size_t)(k0 + 9) * H_DIM + gn];
        float d0 = g_d_h[(size_t)k0 * H_DIM + gn];
        float d1 = g_d_h[(size_t)(k0 + 1) * H_DIM + gn];
        float d8 = g_d_h[(size_t)(k0 + 8) * H_DIM + gn];
        float d9 = g_d_h[(size_t)(k0 + 9) * H_DIM + gn];
        uint4 w;
        w.x = bpack(m0, m1);
        w.y = bpack(m8, m9);
        w.z = bpack(d0, d1);
        w.w = bpack(d8, d9);
        wpk[sidx] = w;
    }

    const int r0 = b_base + mt * 16 + gid;
    const int eb = tid >> 4;                 // 0..31
    const int en = tid & 15;                 // 0..15
    const int gbrow = b_base + eb;
    const int ncol = n_base + en;
    const int hoff = gbrow * H_DIM + (ncol & ~15) + kperm16(ncol & 15);

    // prefetch step-0 epilogue operands
    size_t toff = (size_t)gbrow * H_DIM + ncol;
    float epre = __ldg(eps_h + toff);
    float xpre = __ldcg(out + toff);
    __syncthreads();

    for (int t = 0; t < S_LEN; t++) {
        const __nv_bfloat16* hsrc = (t & 1) ? g_hB : g_hA;
        __nv_bfloat16* hdst = (t & 1) ? g_hA : g_hB;

        // ---- preload all h fragments (16 independent LDG.64, full MLP) ----
        const __nv_bfloat16* hr0 = hsrc + (size_t)r0 * H_DIM + ke * 128 + tig * 4;
        const __nv_bfloat16* hr1 = hr0 + 8 * H_DIM;
        uint2 v0[8], v1[8];
#pragma unroll
        for (int c = 0; c < 8; c++) {
            v0[c] = __ldcg((const uint2*)(hr0 + c * 16));
            v1[c] = __ldcg((const uint2*)(hr1 + c * 16));
        }

        float cG[2][4] = {}, cD[2][4] = {};
#pragma unroll
        for (int c = 0; c < 8; c++) {
            const int cg = ke * 8 + c;
            uint32_t a0 = v0[c].x, a2 = v0[c].y;
            uint32_t a1 = v1[c].x, a3 = v1[c].y;
            uint32_t q0 = mulbf2(a0, a0), q2 = mulbf2(a2, a2);
            uint32_t q1 = mulbf2(a1, a1), q3 = mulbf2(a3, a3);
#pragma unroll
            for (int nt = 0; nt < 2; nt++) {
                int nl = nt * 8 + gid;
                uint4 w = wpk[cg * 64 + tig * 16 + ((nl + 2 * tig) & 15)];
                mma16(cG[nt], a0, a1, a2, a3, w.x, w.y);
                mma16(cD[nt], q0, q1, q2, q3, w.z, w.w);
            }
        }

        // partials -> smem
        const int rowa = ke * 32 + mt * 16 + gid;
#pragma unroll
        for (int nt = 0; nt < 2; nt++) {
            int colb = nt * 8 + tig * 2;
            *(float2*)&pG[rowa * 16 + colb]       = make_float2(cG[nt][0], cG[nt][1]);
            *(float2*)&pG[(rowa + 8) * 16 + colb] = make_float2(cG[nt][2], cG[nt][3]);
            *(float2*)&pD[rowa * 16 + colb]       = make_float2(cD[nt][0], cD[nt][1]);
            *(float2*)&pD[(rowa + 8) * 16 + colb] = make_float2(cD[nt][2], cD[nt][3]);
        }
        __syncthreads();

        // reduce 8 k-slices + epilogue (1 output per thread)
        float G = 0.0f, D = 0.0f;
#pragma unroll
        for (int q = 0; q < 8; q++) {
            G += pG[(q * 32 + eb) * 16 + en];
            D += pD[(q * 32 + eb) * 16 + en];
        }
        float h = tanh_ap(G + epre * sqrtf(D + EPS_C) + xpre);
        hdst[hoff] = __float2bfloat16(h);    // h transport: the only critical store

        if (t == S_LEN - 1) {
            out[toff] = h;
            if (write_last)
                out[(size_t)S_LEN * B_DIM * H_DIM + gbrow * H_DIM + ncol] = h;
            break;
        }

        // ---- distributed flag barrier (per batch-half: 64 blocks) ----
        __syncthreads();                      // all h stores done (block edge)
        const unsigned target = (unsigned)(t + 1);
        if (tid == 0)
            st_release(&g_flags[bid * 32], target);
        // hidden work: current out-store + next-step operand prefetch
        out[toff] = h;
        toff = (size_t)((t + 1) * B_DIM + gbrow) * H_DIM + ncol;
        epre = __ldg(eps_h + toff);
        xpre = __ldcg(out + toff);
        if (tid < 64) {
            while (ld_acquire(&g_flags[(tid * 2 + half) * 32]) < target) { }
        }
        __syncthreads();
    }
}

// ---------------- launch ----------------
extern "C" void kernel_launch(void* const* d_in, const int* in_sizes, int n_in,
                              void* d_out, int out_size)
{
    (void)in_sizes; (void)n_in;
    const float* x      = (const float*)d_in[0];
    const float* eps_in = (const float*)d_in[1];
    const float* eps_h  = (const float*)d_in[2];
    const float* m_in   = (const float*)d_in[3];
    const float* pi_in  = (const float*)d_in[4];
    const float* chi_in = (const float*)d_in[5];
    const float* m_h    = (const float*)d_in[6];
    const float* pi_h   = (const float*)d_in[7];
    const float* chi_h  = (const float*)d_in[8];
    float* out = (float*)d_out;

    prep_kernel<<<512, 256>>>(m_in, pi_in, chi_in, m_h, pi_h, chi_h);
    prep_x_kernel<<<8192, 256>>>(x);

    cudaFuncSetAttribute(xproj_kernel, cudaFuncAttributeMaxDynamicSharedMemorySize, XP_SMEM);
    dim3 gB(H_DIM / 64, (S_LEN * B_DIM) / 128);
    xproj_kernel<<<gB, 256, XP_SMEM>>>(eps_in, out);

    cudaFuncSetAttribute(scan_kernel, cudaFuncAttributeMaxDynamicSharedMemorySize, SC_SMEM);
    int write_last = (out_size >= S_LEN * B_DIM * H_DIM + B_DIM * H_DIM) ? 1 : 0;
    scan_kernel<<<NB, 512, SC_SMEM>>>(eps_h, out, write_last);
}

// round 12
// speedup vs baseline: 4.9928x; 1.1562x over previous
#include <cuda_runtime.h>
#include <cuda_bf16.h>
#include <cstdint>

#define S_LEN 512
#define B_DIM 64
#define I_DIM 512
#define H_DIM 1024
#define EPS_C 1e-10f
#define NB    128

typedef unsigned long long u64;

// ---------------- bf16 helpers ----------------
__device__ __forceinline__ void mma16(float* c, uint32_t a0, uint32_t a1, uint32_t a2, uint32_t a3,
                                      uint32_t b0, uint32_t b1) {
    asm volatile("mma.sync.aligned.m16n8k16.row.col.f32.bf16.bf16.f32 "
        "{%0,%1,%2,%3}, {%4,%5,%6,%7}, {%8,%9}, {%0,%1,%2,%3};"
        : "+f"(c[0]), "+f"(c[1]), "+f"(c[2]), "+f"(c[3])
        : "r"(a0), "r"(a1), "r"(a2), "r"(a3), "r"(b0), "r"(b1));
}
__device__ __forceinline__ uint32_t mulbf2(uint32_t a, uint32_t b) {
    uint32_t d; asm("mul.rn.bf16x2 %0, %1, %2;" : "=r"(d) : "r"(a), "r"(b)); return d;
}
__device__ __forceinline__ uint32_t bpack(float lo, float hi) {
    __nv_bfloat162 t = __floats2bfloat162_rn(lo, hi);   // .x = low half
    return *reinterpret_cast<uint32_t*>(&t);
}
__device__ __forceinline__ float tanh_ap(float x) {
    float y; asm("tanh.approx.f32 %0, %1;" : "=f"(y) : "f"(x)); return y;
}

// bf16 k16-group permutation: original j -> position; order [0,1,8,9,2,3,10,11,...]
__device__ __forceinline__ int kperm16(int j) {
    return (((j & 7) >> 1) << 2) | (((j >> 3) & 1) << 1) | (j & 1);
}

// ---------------- cp.async helpers ----------------
__device__ __forceinline__ uint32_t smem_u32(const void* p) {
    uint32_t a;
    asm("{ .reg .u64 t; cvta.to.shared.u64 t, %1; cvt.u32.u64 %0, t; }" : "=r"(a) : "l"(p));
    return a;
}
__device__ __forceinline__ void cp16(uint32_t dst, const void* src) {
    asm volatile("cp.async.cg.shared.global [%0], [%1], 16;" :: "r"(dst), "l"(src));
}
#define CP_COMMIT() asm volatile("cp.async.commit_group;" ::: "memory")
#define CP_WAIT1()  asm volatile("cp.async.wait_group 1;" ::: "memory")
#define CP_WAIT0()  asm volatile("cp.async.wait_group 0;" ::: "memory")

// ---------------- scoped atomics for the grid barrier ----------------
__device__ __forceinline__ unsigned ld_acquire(const unsigned* p) {
    unsigned v;
    asm volatile("ld.acquire.gpu.u32 %0, [%1];" : "=r"(v) : "l"(p) : "memory");
    return v;
}
__device__ __forceinline__ void st_release(unsigned* p, unsigned v) {
    asm volatile("st.release.gpu.u32 [%0], %1;" :: "l"(p), "r"(v) : "memory");
}

// ---------------- device scratch ----------------
__device__ float g_mu_h[H_DIM * H_DIM];    // fp32, [k][n] (bf16 at scan staging)
__device__ float g_d_h [H_DIM * H_DIM];
// xproj weights pre-merged in smem image: [8 ks][4 cg][4 tg][1024 n-slot] uint4
// entry = {mu(kA0,kA1), mu(kB0,kB1), d(kA0,kA1), d(kB0,kB1)}, bank rotation baked in
__device__ __align__(16) uint4 g_wx[8 * 16 * 1024];
__device__ __align__(16) __nv_bfloat16 g_xb16[S_LEN * B_DIM * I_DIM];  // bf16(x), k16-permuted
__device__ __align__(16) __nv_bfloat16 g_xq16[S_LEN * B_DIM * I_DIM];  // bf16(x*x), k16-permuted
__device__ __align__(16) __nv_bfloat16 g_hA[B_DIM * H_DIM];  // bf16 h transport, k16-permuted
__device__ __align__(16) __nv_bfloat16 g_hB[B_DIM * H_DIM];
__device__ __align__(128) unsigned g_flags[NB * 32];  // 1 flag per 128B line, monotonic

// ---------------- prep ----------------
__global__ void prep_kernel(const float* __restrict__ m_in, const float* __restrict__ pi_in,
                            const float* __restrict__ chi_in,
                            const float* __restrict__ m_h, const float* __restrict__ pi_h,
                            const float* __restrict__ chi_h)
{
    int idx = blockIdx.x * blockDim.x + threadIdx.x;
    int stride = gridDim.x * blockDim.x;

    // hidden weights: fp32 effective params
    for (int i = idx; i < H_DIM * H_DIM; i += stride) {
        float m = m_h[i], pi = pi_h[i], chi = chi_h[i];
        float mu = (1.0f - pi) * m;
        float rho = (1.0f - pi) * (chi + m * m);
        g_mu_h[i] = mu;
        g_d_h[i]  = rho - mu * mu;
    }
    // xproj weights, merged smem image. i = (((ks*4+cg)*4+tg)*1024 + n)
    for (int i = idx; i < 8 * 16 * 1024; i += stride) {
        int n  = i & 1023;
        int tg = (i >> 10) & 3;
        int cgks = i >> 12;                 // ks*4 + cg
        int kA = cgks * 16 + 2 * tg;        // k16-group base + pair offset
        int kB = kA + 8;

        float mv[4], dv[4];
        int kk[4] = {kA, kA + 1, kB, kB + 1};
#pragma unroll
        for (int j = 0; j < 4; j++) {
            int o = kk[j] * H_DIM + n;
            float m = m_in[o], pi = pi_in[o], chi = chi_in[o];
            float mu = (1.0f - pi) * m;
            mv[j] = mu;
            dv[j] = (1.0f - pi) * (chi + m * m) - mu * mu;
        }
        uint4 w;
        w.x = bpack(mv[0], mv[1]);
        w.y = bpack(mv[2], mv[3]);
        w.z = bpack(dv[0], dv[1]);
        w.w = bpack(dv[2], dv[3]);
        // bank rotation baked: slot within the 64-wide n-block
        int nb = n >> 6, nl = n & 63;
        int slot = nb * 64 + ((nl + 2 * tg) & 63);
        g_wx[(i & ~1023) + slot] = w;
    }
    for (int i = idx; i < (B_DIM * H_DIM) / 2; i += stride)
        reinterpret_cast<uint32_t*>(g_hA)[i] = 0u;
    for (int i = idx; i < NB * 32; i += stride)
        g_flags[i] = 0u;
}

// ---------------- prep_x: bf16(x), bf16(x^2), k16-permuted ----------------
__global__ void prep_x_kernel(const float* __restrict__ x)
{
    int idx = blockIdx.x * blockDim.x + threadIdx.x;
    int stride = gridDim.x * blockDim.x;
    const int N = S_LEN * B_DIM * I_DIM;
    for (int i = idx; i < N; i += stride) {
        int k = i & (I_DIM - 1);
        int m = i >> 9;
        float v = x[i];
        int p = (k & ~15) | kperm16(k & 15);
        int o = (m << 9) | p;
        g_xb16[o] = __float2bfloat16(v);
        g_xq16[o] = __float2bfloat16(v * v);
    }
}

// ---------------- phase B: xproj via bf16 mma.m16n8k16, cp.async pipelined ----------------
// Block = 128m x 64n, 256 thr, 8 warps (4 m-groups x 2 n-halves), warp tile 32m x 32n.
// 8 k-chunks of 64, double-buffered (48KB/buffer): chunk ks+1 streams via cp.async
// while chunk ks computes. G = x @ mu (1 MMA), D2 = x^2 @ d (1 MMA).
#define XP_SMEM (98304)
#define BUF_SZ  49152

__global__ void __launch_bounds__(256, 2) xproj_kernel(const float* __restrict__ eps_in,
                                                       float* __restrict__ out)
{
    extern __shared__ char smx[];
    const uint32_t sb = smem_u32(smx);

    const int tid  = threadIdx.x;
    const int warp = tid >> 5, lane = tid & 31;
    const int gid = lane >> 2, tig = lane & 3;
    const int n_base = blockIdx.x * 64;
    const int m_base = blockIdx.y * 128;
    const int mg = (warp & 3) * 32;
    const int nh = (warp >> 2) * 32;

    // issue cp.async for one chunk into buffer (ks & 1)
    auto issue = [&](int ks) {
        const uint32_t boff = sb + (ks & 1) * BUF_SZ;
        // x and x^2 tiles: 1024 16B units each, row-swizzled dest
        for (int i = tid; i < 1024; i += 256) {
            int r = i >> 3, u = i & 7;
            int up = u ^ ((r & 3) << 1);
            const char* src = (const char*)(g_xb16 + (size_t)(m_base + r) * I_DIM + ks * 64) + u * 16;
            const char* srq = (const char*)(g_xq16 + (size_t)(m_base + r) * I_DIM + ks * 64) + u * 16;
            cp16(boff + r * 128 + up * 16, src);
            cp16(boff + 16384 + r * 128 + up * 16, srq);
        }
        // weights: flat copy of the pre-merged image slice (rotation baked in prep)
        for (int i = tid; i < 1024; i += 256) {
            int cgtg = i >> 6, j = i & 63;
            cp16(boff + 32768 + i * 16,
                 (const char*)(g_wx + (((ks * 16 + cgtg) << 10) + n_base + j)));
        }
    };

    float cG[2][4][4] = {}, cD[2][4][4] = {};

    issue(0); CP_COMMIT();
    issue(1); CP_COMMIT();

    for (int ks = 0; ks < 8; ks++) {
        if (ks < 7) { CP_WAIT1(); } else { CP_WAIT0(); }
        __syncthreads();

        const char* xs = smx + (ks & 1) * BUF_SZ;
        const char* xq = xs + 16384;
        const uint4* w4 = (const uint4*)(xs + 32768);

#pragma unroll
        for (int c = 0; c < 4; c++) {
            uint2 ax[2][2], aq[2][2];    // [mt][row-half]
#pragma unroll
            for (int mt = 0; mt < 2; mt++) {
                int r0 = mg + mt * 16 + gid;
                int r1 = r0 + 8;
                int g0 = (c * 4 + tig) ^ ((r0 & 3) << 2);
                int g1 = (c * 4 + tig) ^ ((r1 & 3) << 2);
                ax[mt][0] = *(const uint2*)(xs + r0 * 128 + g0 * 8);
                ax[mt][1] = *(const uint2*)(xs + r1 * 128 + g1 * 8);
                aq[mt][0] = *(const uint2*)(xq + r0 * 128 + g0 * 8);
                aq[mt][1] = *(const uint2*)(xq + r1 * 128 + g1 * 8);
            }
#pragma unroll
            for (int nt = 0; nt < 4; nt++) {
                int nl = nh + nt * 8 + gid;
                uint4 w = w4[(c * 4 + tig) * 64 + ((nl + 2 * tig) & 63)];
#pragma unroll
                for (int mt = 0; mt < 2; mt++) {
                    mma16(cG[mt][nt], ax[mt][0].x, ax[mt][1].x, ax[mt][0].y, ax[mt][1].y, w.x, w.y);
                    mma16(cD[mt][nt], aq[mt][0].x, aq[mt][1].x, aq[mt][0].y, aq[mt][1].y, w.z, w.w);
                }
            }
        }
        __syncthreads();               // everyone done reading this buffer
        if (ks + 2 < 8) { issue(ks + 2); CP_COMMIT(); }
    }

    // epilogue: out = G + eps * sqrt(D2 + EPS)
#pragma unroll
    for (int mt = 0; mt < 2; mt++)
#pragma unroll
    for (int nt = 0; nt < 4; nt++) {
        int n = n_base + nh + nt * 8 + tig * 2;
#pragma unroll
        for (int half = 0; half < 2; half++) {
            int m = m_base + mg + mt * 16 + gid + half * 8;
            size_t off = (size_t)m * H_DIM + n;
            float2 e = *(const float2*)(eps_in + off);
            float2 o;
            o.x = cG[mt][nt][half * 2]     + e.x * sqrtf(cD[mt][nt][half * 2]     + EPS_C);
            o.y = cG[mt][nt][half * 2 + 1] + e.y * sqrtf(cD[mt][nt][half * 2 + 1] + EPS_C);
            *(float2*)(out + off) = o;
        }
    }
}

// ---------------- phase C: persistent scan via bf16 mma.m16n8k16 (unchanged) ----------------
#define SC_SMEM (98304)

__global__ void __launch_bounds__(512, 1) scan_kernel(const float* __restrict__ eps_h,
                                                      float* __restrict__ out,
                                                      int write_last)
{
    extern __shared__ char smc[];
    uint4* wpk = (uint4*)smc;                // [64 cg][4 tig][16 n] uint4 = 64KB
    float* pG = (float*)(smc + 65536);       // [8 ke][32 b][16 n] = 16KB
    float* pD = pG + 4096;

    const int tid  = threadIdx.x;
    const int warp = tid >> 5, lane = tid & 31;
    const int gid = lane >> 2, tig = lane & 3;
    const int n_base = (blockIdx.x >> 1) * 16;
    const int b_base = (blockIdx.x & 1) * 32;
    const int half = blockIdx.x & 1;
    const int mt = warp & 1, ke = warp >> 1;
    const int bid = blockIdx.x;

    // stage weights once: mu and d single bf16, packed {mu01, mu89, d01, d89}
    for (int i = tid; i < 4096; i += 512) {
        int cg = i >> 6, tg = (i >> 4) & 3, n = i & 15;
        int sidx = cg * 64 + tg * 16 + ((n + 2 * tg) & 15);
        int k0 = cg * 16 + 2 * tg;
        int gn = n_base + n;
        float m0 = g_mu_h[(size_t)k0 * H_DIM + gn];
        float m1 = g_mu_h[(size_t)(k0 + 1) * H_DIM + gn];
        float m8 = g_mu_h[(size_t)(k0 + 8) * H_DIM + gn];
        float m9 = g_mu_h[(size_t)(k0 + 9) * H_DIM + gn];
        float d0 = g_d_h[(size_t)k0 * H_DIM + gn];
        float d1 = g_d_h[(size_t)(k0 + 1) * H_DIM + gn];
        float d8 = g_d_h[(size_t)(k0 + 8) * H_DIM + gn];
        float d9 = g_d_h[(size_t)(k0 + 9) * H_DIM + gn];
        uint4 w;
        w.x = bpack(m0, m1);
        w.y = bpack(m8, m9);
        w.z = bpack(d0, d1);
        w.w = bpack(d8, d9);
        wpk[sidx] = w;
    }

    const int r0 = b_base + mt * 16 + gid;
    const int eb = tid >> 4;                 // 0..31
    const int en = tid & 15;                 // 0..15
    const int gbrow = b_base + eb;
    const int ncol = n_base + en;
    const int hoff = gbrow * H_DIM + (ncol & ~15) + kperm16(ncol & 15);

    // prefetch step-0 epilogue operands
    size_t toff = (size_t)gbrow * H_DIM + ncol;
    float epre = __ldg(eps_h + toff);
    float xpre = __ldcg(out + toff);
    __syncthreads();

    for (int t = 0; t < S_LEN; t++) {
        const __nv_bfloat16* hsrc = (t & 1) ? g_hB : g_hA;
        __nv_bfloat16* hdst = (t & 1) ? g_hA : g_hB;

        // ---- preload all h fragments (16 independent LDG.64, full MLP) ----
        const __nv_bfloat16* hr0 = hsrc + (size_t)r0 * H_DIM + ke * 128 + tig * 4;
        const __nv_bfloat16* hr1 = hr0 + 8 * H_DIM;
        uint2 v0[8], v1[8];
#pragma unroll
        for (int c = 0; c < 8; c++) {
            v0[c] = __ldcg((const uint2*)(hr0 + c * 16));
            v1[c] = __ldcg((const uint2*)(hr1 + c * 16));
        }

        float cG[2][4] = {}, cD[2][4] = {};
#pragma unroll
        for (int c = 0; c < 8; c++) {
            const int cg = ke * 8 + c;
            uint32_t a0 = v0[c].x, a2 = v0[c].y;
            uint32_t a1 = v1[c].x, a3 = v1[c].y;
            uint32_t q0 = mulbf2(a0, a0), q2 = mulbf2(a2, a2);
            uint32_t q1 = mulbf2(a1, a1), q3 = mulbf2(a3, a3);
#pragma unroll
            for (int nt = 0; nt < 2; nt++) {
                int nl = nt * 8 + gid;
                uint4 w = wpk[cg * 64 + tig * 16 + ((nl + 2 * tig) & 15)];
                mma16(cG[nt], a0, a1, a2, a3, w.x, w.y);
                mma16(cD[nt], q0, q1, q2, q3, w.z, w.w);
            }
        }

        // partials -> smem
        const int rowa = ke * 32 + mt * 16 + gid;
#pragma unroll
        for (int nt = 0; nt < 2; nt++) {
            int colb = nt * 8 + tig * 2;
            *(float2*)&pG[rowa * 16 + colb]       = make_float2(cG[nt][0], cG[nt][1]);
            *(float2*)&pG[(rowa + 8) * 16 + colb] = make_float2(cG[nt][2], cG[nt][3]);
            *(float2*)&pD[rowa * 16 + colb]       = make_float2(cD[nt][0], cD[nt][1]);
            *(float2*)&pD[(rowa + 8) * 16 + colb] = make_float2(cD[nt][2], cD[nt][3]);
        }
        __syncthreads();

        // reduce 8 k-slices + epilogue (1 output per thread)
        float G = 0.0f, D = 0.0f;
#pragma unroll
        for (int q = 0; q < 8; q++) {
            G += pG[(q * 32 + eb) * 16 + en];
            D += pD[(q * 32 + eb) * 16 + en];
        }
        float h = tanh_ap(G + epre * sqrtf(D + EPS_C) + xpre);
        hdst[hoff] = __float2bfloat16(h);    // h transport: the only critical store

        if (t == S_LEN - 1) {
            out[toff] = h;
            if (write_last)
                out[(size_t)S_LEN * B_DIM * H_DIM + gbrow * H_DIM + ncol] = h;
            break;
        }

        // ---- distributed flag barrier (per batch-half: 64 blocks) ----
        __syncthreads();                      // all h stores done (block edge)
        const unsigned target = (unsigned)(t + 1);
        if (tid == 0)
            st_release(&g_flags[bid * 32], target);
        // hidden work: current out-store + next-step operand prefetch
        out[toff] = h;
        toff = (size_t)((t + 1) * B_DIM + gbrow) * H_DIM + ncol;
        epre = __ldg(eps_h + toff);
        xpre = __ldcg(out + toff);
        if (tid < 64) {
            while (ld_acquire(&g_flags[(tid * 2 + half) * 32]) < target) { }
        }
        __syncthreads();
    }
}

// ---------------- launch ----------------
extern "C" void kernel_launch(void* const* d_in, const int* in_sizes, int n_in,
                              void* d_out, int out_size)
{
    (void)in_sizes; (void)n_in;
    const float* x      = (const float*)d_in[0];
    const float* eps_in = (const float*)d_in[1];
    const float* eps_h  = (const float*)d_in[2];
    const float* m_in   = (const float*)d_in[3];
    const float* pi_in  = (const float*)d_in[4];
    const float* chi_in = (const float*)d_in[5];
    const float* m_h    = (const float*)d_in[6];
    const float* pi_h   = (const float*)d_in[7];
    const float* chi_h  = (const float*)d_in[8];
    float* out = (float*)d_out;

    prep_kernel<<<1024, 256>>>(m_in, pi_in, chi_in, m_h, pi_h, chi_h);
    prep_x_kernel<<<8192, 256>>>(x);

    cudaFuncSetAttribute(xproj_kernel, cudaFuncAttributeMaxDynamicSharedMemorySize, XP_SMEM);
    dim3 gB(H_DIM / 64, (S_LEN * B_DIM) / 128);
    xproj_kernel<<<gB, 256, XP_SMEM>>>(eps_in, out);

    cudaFuncSetAttribute(scan_kernel, cudaFuncAttributeMaxDynamicSharedMemorySize, SC_SMEM);
    int write_last = (out_size >= S_LEN * B_DIM * H_DIM + B_DIM * H_DIM) ? 1 : 0;
    scan_kernel<<<NB, 512, SC_SMEM>>>(eps_h, out, write_last);
}

// round 13
// speedup vs baseline: 5.5000x; 1.1016x over previous
#include <cuda_runtime.h>
#include <cuda_bf16.h>
#include <cstdint>

#define S_LEN 512
#define B_DIM 64
#define I_DIM 512
#define H_DIM 1024
#define EPS_C 1e-10f
#define NB    128

typedef unsigned long long u64;

// ---------------- bf16 helpers ----------------
__device__ __forceinline__ void mma16(float* c, uint32_t a0, uint32_t a1, uint32_t a2, uint32_t a3,
                                      uint32_t b0, uint32_t b1) {
    asm volatile("mma.sync.aligned.m16n8k16.row.col.f32.bf16.bf16.f32 "
        "{%0,%1,%2,%3}, {%4,%5,%6,%7}, {%8,%9}, {%0,%1,%2,%3};"
        : "+f"(c[0]), "+f"(c[1]), "+f"(c[2]), "+f"(c[3])
        : "r"(a0), "r"(a1), "r"(a2), "r"(a3), "r"(b0), "r"(b1));
}
__device__ __forceinline__ uint32_t mulbf2(uint32_t a, uint32_t b) {
    uint32_t d; asm("mul.rn.bf16x2 %0, %1, %2;" : "=r"(d) : "r"(a), "r"(b)); return d;
}
__device__ __forceinline__ uint32_t bpack(float lo, float hi) {
    __nv_bfloat162 t = __floats2bfloat162_rn(lo, hi);   // .x = low half
    return *reinterpret_cast<uint32_t*>(&t);
}
__device__ __forceinline__ float tanh_ap(float x) {
    float y; asm("tanh.approx.f32 %0, %1;" : "=f"(y) : "f"(x)); return y;
}

// bf16 k16-group permutation: original j -> position; order [0,1,8,9,2,3,10,11,...]
__device__ __forceinline__ int kperm16(int j) {
    return (((j & 7) >> 1) << 2) | (((j >> 3) & 1) << 1) | (j & 1);
}

// ---------------- cp.async helpers ----------------
__device__ __forceinline__ uint32_t smem_u32(const void* p) {
    uint32_t a;
    asm("{ .reg .u64 t; cvta.to.shared.u64 t, %1; cvt.u32.u64 %0, t; }" : "=r"(a) : "l"(p));
    return a;
}
__device__ __forceinline__ void cp16(uint32_t dst, const void* src) {
    asm volatile("cp.async.cg.shared.global [%0], [%1], 16;" :: "r"(dst), "l"(src));
}
#define CP_COMMIT() asm volatile("cp.async.commit_group;" ::: "memory")
#define CP_WAIT1()  asm volatile("cp.async.wait_group 1;" ::: "memory")
#define CP_WAIT0()  asm volatile("cp.async.wait_group 0;" ::: "memory")

// ---------------- scoped atomics for the grid barrier ----------------
__device__ __forceinline__ unsigned ld_acquire(const unsigned* p) {
    unsigned v;
    asm volatile("ld.acquire.gpu.u32 %0, [%1];" : "=r"(v) : "l"(p) : "memory");
    return v;
}
__device__ __forceinline__ void st_release(unsigned* p, unsigned v) {
    asm volatile("st.release.gpu.u32 [%0], %1;" :: "l"(p), "r"(v) : "memory");
}

// ---------------- device scratch ----------------
__device__ float g_mu_h[H_DIM * H_DIM];    // fp32, [k][n] (bf16 at scan staging)
__device__ float g_d_h [H_DIM * H_DIM];
// xproj weights pre-merged in smem image: [8 ks][4 cg][4 tg][1024 n-slot] uint4
__device__ __align__(16) uint4 g_wx[8 * 16 * 1024];
__device__ __align__(16) __nv_bfloat16 g_xb16[S_LEN * B_DIM * I_DIM];  // bf16(x), k16-permuted
__device__ __align__(16) __nv_bfloat16 g_xq16[S_LEN * B_DIM * I_DIM];  // bf16(x*x), k16-permuted
__device__ __align__(16) __nv_bfloat16 g_hA[B_DIM * H_DIM];  // bf16 h transport, k16-permuted
__device__ __align__(16) __nv_bfloat16 g_hB[B_DIM * H_DIM];
__device__ __align__(128) unsigned g_flags[NB * 32];  // 1 flag per 128B line, monotonic

// ---------------- prep ----------------
__global__ void prep_kernel(const float* __restrict__ m_in, const float* __restrict__ pi_in,
                            const float* __restrict__ chi_in,
                            const float* __restrict__ m_h, const float* __restrict__ pi_h,
                            const float* __restrict__ chi_h)
{
    int idx = blockIdx.x * blockDim.x + threadIdx.x;
    int stride = gridDim.x * blockDim.x;

    // hidden weights: fp32 effective params
    for (int i = idx; i < H_DIM * H_DIM; i += stride) {
        float m = m_h[i], pi = pi_h[i], chi = chi_h[i];
        float mu = (1.0f - pi) * m;
        float rho = (1.0f - pi) * (chi + m * m);
        g_mu_h[i] = mu;
        g_d_h[i]  = rho - mu * mu;
    }
    // xproj weights, merged smem image. i = (((ks*4+cg)*4+tg)*1024 + n)
    for (int i = idx; i < 8 * 16 * 1024; i += stride) {
        int n  = i & 1023;
        int tg = (i >> 10) & 3;
        int cgks = i >> 12;                 // ks*4 + cg
        int kA = cgks * 16 + 2 * tg;
        int kB = kA + 8;

        float mv[4], dv[4];
        int kk[4] = {kA, kA + 1, kB, kB + 1};
#pragma unroll
        for (int j = 0; j < 4; j++) {
            int o = kk[j] * H_DIM + n;
            float m = m_in[o], pi = pi_in[o], chi = chi_in[o];
            float mu = (1.0f - pi) * m;
            mv[j] = mu;
            dv[j] = (1.0f - pi) * (chi + m * m) - mu * mu;
        }
        uint4 w;
        w.x = bpack(mv[0], mv[1]);
        w.y = bpack(mv[2], mv[3]);
        w.z = bpack(dv[0], dv[1]);
        w.w = bpack(dv[2], dv[3]);
        int nb = n >> 6, nl = n & 63;
        int slot = nb * 64 + ((nl + 2 * tg) & 63);
        g_wx[(i & ~1023) + slot] = w;
    }
    for (int i = idx; i < (B_DIM * H_DIM) / 2; i += stride)
        reinterpret_cast<uint32_t*>(g_hA)[i] = 0u;
    for (int i = idx; i < NB * 32; i += stride)
        g_flags[i] = 0u;
}

// ---------------- prep_x: bf16(x), bf16(x^2), k16-permuted ----------------
__global__ void prep_x_kernel(const float* __restrict__ x)
{
    int idx = blockIdx.x * blockDim.x + threadIdx.x;
    int stride = gridDim.x * blockDim.x;
    const int N = S_LEN * B_DIM * I_DIM;
    for (int i = idx; i < N; i += stride) {
        int k = i & (I_DIM - 1);
        int m = i >> 9;
        float v = x[i];
        int p = (k & ~15) | kperm16(k & 15);
        int o = (m << 9) | p;
        g_xb16[o] = __float2bfloat16(v);
        g_xq16[o] = __float2bfloat16(v * v);
    }
}

// ---------------- phase B: xproj via bf16 mma.m16n8k16, cp.async pipelined ----------------
#define XP_SMEM (98304)
#define BUF_SZ  49152

__global__ void __launch_bounds__(256, 2) xproj_kernel(const float* __restrict__ eps_in,
                                                       float* __restrict__ out)
{
    extern __shared__ char smx[];
    const uint32_t sb = smem_u32(smx);

    const int tid  = threadIdx.x;
    const int warp = tid >> 5, lane = tid & 31;
    const int gid = lane >> 2, tig = lane & 3;
    const int n_base = blockIdx.x * 64;
    const int m_base = blockIdx.y * 128;
    const int mg = (warp & 3) * 32;
    const int nh = (warp >> 2) * 32;

    auto issue = [&](int ks) {
        const uint32_t boff = sb + (ks & 1) * BUF_SZ;
        for (int i = tid; i < 1024; i += 256) {
            int r = i >> 3, u = i & 7;
            int up = u ^ ((r & 3) << 1);
            const char* src = (const char*)(g_xb16 + (size_t)(m_base + r) * I_DIM + ks * 64) + u * 16;
            const char* srq = (const char*)(g_xq16 + (size_t)(m_base + r) * I_DIM + ks * 64) + u * 16;
            cp16(boff + r * 128 + up * 16, src);
            cp16(boff + 16384 + r * 128 + up * 16, srq);
        }
        for (int i = tid; i < 1024; i += 256) {
            cp16(boff + 32768 + i * 16,
                 (const char*)(g_wx + (((ks * 16 + (i >> 6)) << 10) + n_base + (i & 63))));
        }
    };

    float cG[2][4][4] = {}, cD[2][4][4] = {};

    issue(0); CP_COMMIT();
    issue(1); CP_COMMIT();

    for (int ks = 0; ks < 8; ks++) {
        if (ks < 7) { CP_WAIT1(); } else { CP_WAIT0(); }
        __syncthreads();

        const char* xs = smx + (ks & 1) * BUF_SZ;
        const char* xq = xs + 16384;
        const uint4* w4 = (const uint4*)(xs + 32768);

#pragma unroll
        for (int c = 0; c < 4; c++) {
            uint2 ax[2][2], aq[2][2];
#pragma unroll
            for (int mt = 0; mt < 2; mt++) {
                int r0 = mg + mt * 16 + gid;
                int r1 = r0 + 8;
                int g0 = (c * 4 + tig) ^ ((r0 & 3) << 2);
                int g1 = (c * 4 + tig) ^ ((r1 & 3) << 2);
                ax[mt][0] = *(const uint2*)(xs + r0 * 128 + g0 * 8);
                ax[mt][1] = *(const uint2*)(xs + r1 * 128 + g1 * 8);
                aq[mt][0] = *(const uint2*)(xq + r0 * 128 + g0 * 8);
                aq[mt][1] = *(const uint2*)(xq + r1 * 128 + g1 * 8);
            }
#pragma unroll
            for (int nt = 0; nt < 4; nt++) {
                int nl = nh + nt * 8 + gid;
                uint4 w = w4[(c * 4 + tig) * 64 + ((nl + 2 * tig) & 63)];
#pragma unroll
                for (int mt = 0; mt < 2; mt++) {
                    mma16(cG[mt][nt], ax[mt][0].x, ax[mt][1].x, ax[mt][0].y, ax[mt][1].y, w.x, w.y);
                    mma16(cD[mt][nt], aq[mt][0].x, aq[mt][1].x, aq[mt][0].y, aq[mt][1].y, w.z, w.w);
                }
            }
        }
        __syncthreads();
        if (ks + 2 < 8) { issue(ks + 2); CP_COMMIT(); }
    }

#pragma unroll
    for (int mt = 0; mt < 2; mt++)
#pragma unroll
    for (int nt = 0; nt < 4; nt++) {
        int n = n_base + nh + nt * 8 + tig * 2;
#pragma unroll
        for (int half = 0; half < 2; half++) {
            int m = m_base + mg + mt * 16 + gid + half * 8;
            size_t off = (size_t)m * H_DIM + n;
            float2 e = *(const float2*)(eps_in + off);
            float2 o;
            o.x = cG[mt][nt][half * 2]     + e.x * sqrtf(cD[mt][nt][half * 2]     + EPS_C);
            o.y = cG[mt][nt][half * 2 + 1] + e.y * sqrtf(cD[mt][nt][half * 2 + 1] + EPS_C);
            *(float2*)(out + off) = o;
        }
    }
}

// ---------------- phase C: persistent scan via bf16 mma.m16n8k16 ----------------
// Per-warp producer gating: warp ke consumes h cols [ke*128, ke*128+128), produced
// by exactly the 8 same-half blocks ng = ke*8..ke*8+7. Each warp polls only those
// 8 flags (8 lanes, 1 flag each) and starts its loads/MMAs immediately — no
// block-wide poll, no post-poll __syncthreads on the critical path.
#define SC_SMEM (98304)

__global__ void __launch_bounds__(512, 1) scan_kernel(const float* __restrict__ eps_h,
                                                      float* __restrict__ out,
                                                      int write_last)
{
    extern __shared__ char smc[];
    uint4* wpk = (uint4*)smc;                // [64 cg][4 tig][16 n] uint4 = 64KB
    float* pG = (float*)(smc + 65536);       // [8 ke][32 b][16 n] = 16KB
    float* pD = pG + 4096;

    const int tid  = threadIdx.x;
    const int warp = tid >> 5, lane = tid & 31;
    const int gid = lane >> 2, tig = lane & 3;
    const int n_base = (blockIdx.x >> 1) * 16;
    const int b_base = (blockIdx.x & 1) * 32;
    const int half = blockIdx.x & 1;
    const int mt = warp & 1, ke = warp >> 1;
    const int bid = blockIdx.x;

    // this warp's producer flag (lanes 0..7 each own one)
    unsigned* my_flag = &g_flags[(((ke * 8 + lane) * 2) + half) * 32];

    // stage weights once: mu and d single bf16, packed {mu01, mu89, d01, d89}
    for (int i = tid; i < 4096; i += 512) {
        int cg = i >> 6, tg = (i >> 4) & 3, n = i & 15;
        int sidx = cg * 64 + tg * 16 + ((n + 2 * tg) & 15);
        int k0 = cg * 16 + 2 * tg;
        int gn = n_base + n;
        float m0 = g_mu_h[(size_t)k0 * H_DIM + gn];
        float m1 = g_mu_h[(size_t)(k0 + 1) * H_DIM + gn];
        float m8 = g_mu_h[(size_t)(k0 + 8) * H_DIM + gn];
        float m9 = g_mu_h[(size_t)(k0 + 9) * H_DIM + gn];
        float d0 = g_d_h[(size_t)k0 * H_DIM + gn];
        float d1 = g_d_h[(size_t)(k0 + 1) * H_DIM + gn];
        float d8 = g_d_h[(size_t)(k0 + 8) * H_DIM + gn];
        float d9 = g_d_h[(size_t)(k0 + 9) * H_DIM + gn];
        uint4 w;
        w.x = bpack(m0, m1);
        w.y = bpack(m8, m9);
        w.z = bpack(d0, d1);
        w.w = bpack(d8, d9);
        wpk[sidx] = w;
    }

    const int r0 = b_base + mt * 16 + gid;
    const int eb = tid >> 4;                 // 0..31
    const int en = tid & 15;                 // 0..15
    const int gbrow = b_base + eb;
    const int ncol = n_base + en;
    const int hoff = gbrow * H_DIM + (ncol & ~15) + kperm16(ncol & 15);

    // prefetch step-0 epilogue operands
    size_t toff = (size_t)gbrow * H_DIM + ncol;
    float epre = __ldg(eps_h + toff);
    float xpre = __ldcg(out + toff);
    __syncthreads();

    for (int t = 0; t < S_LEN; t++) {
        const __nv_bfloat16* hsrc = (t & 1) ? g_hB : g_hA;
        __nv_bfloat16* hdst = (t & 1) ? g_hA : g_hB;

        // ---- per-warp producer gate (skip t=0: h0 preset by prep) ----
        if (t > 0) {
            if (lane < 8) {
                const unsigned tgt = (unsigned)t;
                while (ld_acquire(my_flag) < tgt) { }
            }
            __syncwarp();
        }

        // ---- preload all h fragments (16 independent LDG.64, full MLP) ----
        const __nv_bfloat16* hr0 = hsrc + (size_t)r0 * H_DIM + ke * 128 + tig * 4;
        const __nv_bfloat16* hr1 = hr0 + 8 * H_DIM;
        uint2 v0[8], v1[8];
#pragma unroll
        for (int c = 0; c < 8; c++) {
            v0[c] = __ldcg((const uint2*)(hr0 + c * 16));
            v1[c] = __ldcg((const uint2*)(hr1 + c * 16));
        }

        float cG[2][4] = {}, cD[2][4] = {};
#pragma unroll
        for (int c = 0; c < 8; c++) {
            const int cg = ke * 8 + c;
            uint32_t a0 = v0[c].x, a2 = v0[c].y;
            uint32_t a1 = v1[c].x, a3 = v1[c].y;
            uint32_t q0 = mulbf2(a0, a0), q2 = mulbf2(a2, a2);
            uint32_t q1 = mulbf2(a1, a1), q3 = mulbf2(a3, a3);
#pragma unroll
            for (int nt = 0; nt < 2; nt++) {
                int nl = nt * 8 + gid;
                uint4 w = wpk[cg * 64 + tig * 16 + ((nl + 2 * tig) & 15)];
                mma16(cG[nt], a0, a1, a2, a3, w.x, w.y);
                mma16(cD[nt], q0, q1, q2, q3, w.z, w.w);
            }
        }

        // partials -> smem
        const int rowa = ke * 32 + mt * 16 + gid;
#pragma unroll
        for (int nt = 0; nt < 2; nt++) {
            int colb = nt * 8 + tig * 2;
            *(float2*)&pG[rowa * 16 + colb]       = make_float2(cG[nt][0], cG[nt][1]);
            *(float2*)&pG[(rowa + 8) * 16 + colb] = make_float2(cG[nt][2], cG[nt][3]);
            *(float2*)&pD[rowa * 16 + colb]       = make_float2(cD[nt][0], cD[nt][1]);
            *(float2*)&pD[(rowa + 8) * 16 + colb] = make_float2(cD[nt][2], cD[nt][3]);
        }
        __syncthreads();

        // reduce 8 k-slices + epilogue (1 output per thread)
        float G = 0.0f, D = 0.0f;
#pragma unroll
        for (int q = 0; q < 8; q++) {
            G += pG[(q * 32 + eb) * 16 + en];
            D += pD[(q * 32 + eb) * 16 + en];
        }
        float h = tanh_ap(G + epre * sqrtf(D + EPS_C) + xpre);
        hdst[hoff] = __float2bfloat16(h);    // h transport: the only critical store

        if (t == S_LEN - 1) {
            out[toff] = h;
            if (write_last)
                out[(size_t)S_LEN * B_DIM * H_DIM + gbrow * H_DIM + ncol] = h;
            break;
        }

        // ---- release: all block h stores done -> publish flag ----
        __syncthreads();                      // h stores + psum reads complete
        if (tid == 0)
            st_release(&g_flags[bid * 32], (unsigned)(t + 1));
        // hidden work: current out-store + next-step operand prefetch
        out[toff] = h;
        toff = (size_t)((t + 1) * B_DIM + gbrow) * H_DIM + ncol;
        epre = __ldg(eps_h + toff);
        xpre = __ldcg(out + toff);
    }
}

// ---------------- launch ----------------
extern "C" void kernel_launch(void* const* d_in, const int* in_sizes, int n_in,
                              void* d_out, int out_size)
{
    (void)in_sizes; (void)n_in;
    const float* x      = (const float*)d_in[0];
    const float* eps_in = (const float*)d_in[1];
    const float* eps_h  = (const float*)d_in[2];
    const float* m_in   = (const float*)d_in[3];
    const float* pi_in  = (const float*)d_in[4];
    const float* chi_in = (const float*)d_in[5];
    const float* m_h    = (const float*)d_in[6];
    const float* pi_h   = (const float*)d_in[7];
    const float* chi_h  = (const float*)d_in[8];
    float* out = (float*)d_out;

    prep_kernel<<<1024, 256>>>(m_in, pi_in, chi_in, m_h, pi_h, chi_h);
    prep_x_kernel<<<8192, 256>>>(x);

    cudaFuncSetAttribute(xproj_kernel, cudaFuncAttributeMaxDynamicSharedMemorySize, XP_SMEM);
    dim3 gB(H_DIM / 64, (S_LEN * B_DIM) / 128);
    xproj_kernel<<<gB, 256, XP_SMEM>>>(eps_in, out);

    cudaFuncSetAttribute(scan_kernel, cudaFuncAttributeMaxDynamicSharedMemorySize, SC_SMEM);
    int write_last = (out_size >= S_LEN * B_DIM * H_DIM + B_DIM * H_DIM) ? 1 : 0;
    scan_kernel<<<NB, 512, SC_SMEM>>>(eps_h, out, write_last);
}